// round 10
// baseline (speedup 1.0000x reference)
#include <cuda_runtime.h>
#include <cstdint>

#define Bz 4
#define Tz 1024
#define Dz 1024
#define Hz 16
#define DHz 64
#define Mz (Bz*Tz)        // 4096
#define Kz Dz
#define Nz Dz
#define MD (Mz*Dz)        // 4,194,304
#define NBH (Bz*Hz)       // 64
#define CL 64             // chunk length
#define NC (Tz/CL)        // 16 chunks

// 0..3 = xr,xk,xv,xw (tf32, k-permuted) ; 4=r ; 5=k ; 6=v ; 7=exp(w) (normal)
// 8=o (k-permuted tf32, written by fused scanC)
__device__ float g_buf[9][MD];
__device__ float g_wr[5 * Dz * Dz];               // tf32 k-permuted weights
__device__ float g_state[NBH * NC * DHz * DHz];   // chunk states
__device__ float g_wprod[NBH * NC * DHz];         // per-chunk decay products

__device__ __forceinline__ float to_tf32(float x)
{
    uint32_t d;
    asm("cvt.rna.tf32.f32 %0, %1;" : "=r"(d) : "f"(x));
    return __uint_as_float(d);
}
__device__ __forceinline__ uint32_t smem_to_u32(const void* p) {
    uint32_t a;
    asm("{ .reg .u64 t; cvta.to.shared.u64 t, %1; cvt.u32.u64 %0, t; }"
        : "=r"(a) : "l"(p));
    return a;
}
__device__ __forceinline__ void cp16(uint32_t dst, const void* src) {
    asm volatile("cp.async.cg.shared.global [%0], [%1], 16;"
                 :: "r"(dst), "l"(src));
}
__device__ __forceinline__ void cp_commit() {
    asm volatile("cp.async.commit_group;" ::: "memory");
}
__device__ __forceinline__ void mma_tf32(float c[4], const uint32_t a[4],
                                         const uint32_t b[2])
{
    asm volatile(
        "mma.sync.aligned.m16n8k8.row.col.f32.tf32.tf32.f32 "
        "{%0,%1,%2,%3}, {%4,%5,%6,%7}, {%8,%9}, {%0,%1,%2,%3};"
        : "+f"(c[0]), "+f"(c[1]), "+f"(c[2]), "+f"(c[3])
        : "r"(a[0]), "r"(a[1]), "r"(a[2]), "r"(a[3]),
          "r"(b[0]), "r"(b[1]));
}

// permute helper: 8 floats (a=k0..3, b=k4..7) -> [k0,k4,k1,k5] and [k2,k6,k3,k7]
__device__ __forceinline__ void perm_pair(const float4& a, const float4& b,
                                          float4& o0, float4& o1)
{
    o0 = make_float4(a.x, b.x, a.y, b.y);
    o1 = make_float4(a.z, b.z, a.w, b.w);
}

// ---------------------------------------------------------------------------
// round 5 weight matrices to tf32, k-permuted, into g_wr
// ---------------------------------------------------------------------------
__global__ void __launch_bounds__(256) roundw_kernel(
    const float4* __restrict__ a, const float4* __restrict__ b,
    const float4* __restrict__ c, const float4* __restrict__ d,
    const float4* __restrict__ e)
{
    int idx = blockIdx.x * 256 + threadIdx.x;      // 0..655359
    int which = idx >> 17;
    int off = idx & 131071;
    const float4* src = which == 0 ? a : which == 1 ? b : which == 2 ? c
                       : which == 3 ? d : e;
    float4 v0 = src[2 * off], v1 = src[2 * off + 1];
    v0.x = to_tf32(v0.x); v0.y = to_tf32(v0.y); v0.z = to_tf32(v0.z); v0.w = to_tf32(v0.w);
    v1.x = to_tf32(v1.x); v1.y = to_tf32(v1.y); v1.z = to_tf32(v1.z); v1.w = to_tf32(v1.w);
    float4 o0, o1;
    perm_pair(v0, v1, o0, o1);
    float4* dst = reinterpret_cast<float4*>(g_wr) + (size_t)which * 262144;
    dst[2 * off] = o0;
    dst[2 * off + 1] = o1;
}

// ---------------------------------------------------------------------------
// token-shift mix, tf32-rounded + k-permuted
// ---------------------------------------------------------------------------
__global__ void __launch_bounds__(256) mix_kernel(
    const float4* __restrict__ x,
    const float4* __restrict__ tmr, const float4* __restrict__ tmk,
    const float4* __restrict__ tmv, const float4* __restrict__ tmw)
{
    int idx = blockIdx.x * 256 + threadIdx.x;   // MD/8
    int m  = idx >> 7;
    int gg = idx & 127;
    int t  = m & (Tz - 1);

    float4 x0 = x[(m << 8) + 2 * gg];
    float4 x1 = x[(m << 8) + 2 * gg + 1];
    float4 p0 = make_float4(0.f, 0.f, 0.f, 0.f), p1 = p0;
    if (t != 0) {
        p0 = x[((m - 1) << 8) + 2 * gg];
        p1 = x[((m - 1) << 8) + 2 * gg + 1];
    }

    #define DO_MIX(TMV, DSTI)                                               \
    {                                                                       \
        float4 w0 = TMV[2 * gg], w1 = TMV[2 * gg + 1];                      \
        float4 a, b;                                                        \
        a.x = to_tf32(w0.x * x0.x + (1.f - w0.x) * p0.x);                   \
        a.y = to_tf32(w0.y * x0.y + (1.f - w0.y) * p0.y);                   \
        a.z = to_tf32(w0.z * x0.z + (1.f - w0.z) * p0.z);                   \
        a.w = to_tf32(w0.w * x0.w + (1.f - w0.w) * p0.w);                   \
        b.x = to_tf32(w1.x * x1.x + (1.f - w1.x) * p1.x);                   \
        b.y = to_tf32(w1.y * x1.y + (1.f - w1.y) * p1.y);                   \
        b.z = to_tf32(w1.z * x1.z + (1.f - w1.z) * p1.z);                   \
        b.w = to_tf32(w1.w * x1.w + (1.f - w1.w) * p1.w);                   \
        float4 o0, o1;                                                      \
        perm_pair(a, b, o0, o1);                                            \
        reinterpret_cast<float4*>(g_buf[DSTI])[2 * idx]     = o0;           \
        reinterpret_cast<float4*>(g_buf[DSTI])[2 * idx + 1] = o1;           \
    }
    DO_MIX(tmr, 0)
    DO_MIX(tmk, 1)
    DO_MIX(tmv, 2)
    DO_MIX(tmw, 3)
    #undef DO_MIX
}

// ---------------------------------------------------------------------------
// tf32 mma.sync GEMM on k-permuted operands (unchanged from round 9)
// ---------------------------------------------------------------------------
#define TB 4096
#define GSMB (3 * 2 * TB * 4)                 // 98304 bytes

__device__ __forceinline__ void gemm_body(
    const float* __restrict__ A,
    const float* __restrict__ W,
    float* __restrict__ C, int epi)
{
    extern __shared__ __align__(16) float sm[];
    float* As = sm;
    float* Bs = sm + 3 * TB;
    uint32_t a32 = smem_to_u32(As);
    uint32_t b32 = smem_to_u32(Bs);

    int tid  = threadIdx.x;
    int lane = tid & 31;
    int wid  = tid >> 5;
    int bm = blockIdx.y * 128;
    int bn = blockIdx.x * 128;

    int wm = (wid >> 1) * 64;
    int wn = (wid & 1) * 64;
    int frow = lane >> 2;
    int fk   = lane & 3;

    float acc[4][8][4];
    #pragma unroll
    for (int i = 0; i < 4; i++)
        #pragma unroll
        for (int j = 0; j < 8; j++)
            #pragma unroll
            for (int r = 0; r < 4; r++) acc[i][j][r] = 0.f;

    #define GSTAGE(CC, BUF)                                                  \
    {                                                                        \
        const char* ap = (const char*)(A + (size_t)bm * Kz + (CC) * 32);     \
        const char* bp = (const char*)(W + (size_t)bn * Kz + (CC) * 32);     \
        _Pragma("unroll")                                                    \
        for (int i = 0; i < 8; i++) {                                        \
            int lin = i * 128 + tid;                                         \
            int r = lin >> 3;                                                \
            int g = lin & 7;                                                 \
            int slot = (g + 2 * (r & 3)) & 7;                                \
            cp16(a32 + (BUF) * (TB * 4) + r * 128 + slot * 16,               \
                 ap + (size_t)r * (Kz * 4) + g * 16);                        \
            cp16(b32 + (BUF) * (TB * 4) + r * 128 + slot * 16,               \
                 bp + (size_t)r * (Kz * 4) + g * 16);                        \
        }                                                                    \
    }

    GSTAGE(0, 0) cp_commit();
    GSTAGE(1, 1) cp_commit();

    const int NIT = Kz >> 5;
    int buf = 0;
    for (int c = 0; c < NIT; c++) {
        asm volatile("cp.async.wait_group 1;" ::: "memory");
        __syncthreads();
        if (c + 2 < NIT) {
            int nb = (c + 2) % 3;
            if (nb == 0)      { GSTAGE(c + 2, 0) }
            else if (nb == 1) { GSTAGE(c + 2, 1) }
            else              { GSTAGE(c + 2, 2) }
        }
        cp_commit();

        const float* a_s = As + buf * TB;
        const float* b_s = Bs + buf * TB;
        #pragma unroll
        for (int ks = 0; ks < 4; ks++) {
            uint32_t afr[4][4], bfr[8][2];
            int slot = (2 * ks + (fk >> 1) + 2 * (frow & 3)) & 7;
            int fo = slot * 4 + (fk & 1) * 2;
            #pragma unroll
            for (int mt = 0; mt < 4; mt++) {
                int rr = wm + mt * 16 + frow;
                float2 u = *(const float2*)&a_s[rr * 32 + fo];
                float2 v = *(const float2*)&a_s[(rr + 8) * 32 + fo];
                afr[mt][0] = __float_as_uint(u.x);
                afr[mt][1] = __float_as_uint(v.x);
                afr[mt][2] = __float_as_uint(u.y);
                afr[mt][3] = __float_as_uint(v.y);
            }
            #pragma unroll
            for (int nt = 0; nt < 8; nt++) {
                int rn = wn + nt * 8 + frow;
                float2 w2 = *(const float2*)&b_s[rn * 32 + fo];
                bfr[nt][0] = __float_as_uint(w2.x);
                bfr[nt][1] = __float_as_uint(w2.y);
            }
            #pragma unroll
            for (int mt = 0; mt < 4; mt++)
                #pragma unroll
                for (int nt = 0; nt < 8; nt++)
                    mma_tf32(acc[mt][nt], afr[mt], bfr[nt]);
        }
        buf = (buf + 1) == 3 ? 0 : buf + 1;
    }
    #undef GSTAGE

    #pragma unroll
    for (int mt = 0; mt < 4; mt++) {
        int row = bm + wm + mt * 16 + frow;
        #pragma unroll
        for (int nt = 0; nt < 8; nt++) {
            int col = bn + wn + nt * 8 + fk * 2;
            float vv[4];
            #pragma unroll
            for (int r = 0; r < 4; r++) {
                float v = acc[mt][nt][r];
                if (epi == 1)      v = 1.f / (1.f + __expf(-v));
                else if (epi == 2) v = 0.999900004999833f / (1.f + __expf(-v));
                vv[r] = v;
            }
            *(float2*)&C[(size_t)row * Nz + col]       = make_float2(vv[0], vv[1]);
            *(float2*)&C[(size_t)(row + 8) * Nz + col] = make_float2(vv[2], vv[3]);
        }
    }
}

__global__ void __launch_bounds__(128, 2) proj_gemm()
{
    int which = blockIdx.z;
    int epi = (which == 0) ? 1 : (which == 3) ? 2 : 0;
    gemm_body(g_buf[which], g_wr + (size_t)which * (Dz * Dz),
              g_buf[4 + which], epi);
}

__global__ void __launch_bounds__(128, 2) out_gemm(float* __restrict__ out)
{
    gemm_body(g_buf[8], g_wr + (size_t)4 * (Dz * Dz), out, 0);
}

// ---------------------------------------------------------------------------
// Pass A: chunk-local scan, zero init. grid (NC-1, NBH), 128 threads.
// ---------------------------------------------------------------------------
__global__ void __launch_bounds__(128) scanA_kernel()
{
    extern __shared__ __align__(16) float sm[];
    float* k_s = sm;
    float* e_s = sm + 4096;
    float* v_s = sm + 8192;

    int tid  = threadIdx.x;
    int j    = tid & 63;
    int half = tid >> 6;
    int c  = blockIdx.x;
    int bh = blockIdx.y;
    int b = bh >> 4, h = bh & 15;

    int base0 = (b * Tz + c * CL) * Dz + h * 64;

    #pragma unroll
    for (int it = 0; it < 8; it++) {
        int f  = it * 128 + tid;
        int t  = f >> 4;
        int i4 = (f & 15) << 2;
        int ga = base0 + t * Dz + i4;
        int sa = t * 64 + i4;
        *(float4*)&k_s[sa] = *(const float4*)&g_buf[5][ga];
        *(float4*)&e_s[sa] = *(const float4*)&g_buf[7][ga];
        *(float4*)&v_s[sa] = *(const float4*)&g_buf[6][ga];
    }
    __syncthreads();

    float s[32];
    #pragma unroll
    for (int i = 0; i < 32; i++) s[i] = 0.f;

    for (int t = 0; t < CL; t++) {
        float vj = v_s[t * 64 + j];
        const float4* kp = (const float4*)&k_s[t * 64 + half * 32];
        const float4* ep = (const float4*)&e_s[t * 64 + half * 32];
        #pragma unroll
        for (int q = 0; q < 8; q++) {
            float4 kv = kp[q], ev = ep[q];
            s[q * 4 + 0] = ev.x * s[q * 4 + 0] + kv.x * vj;
            s[q * 4 + 1] = ev.y * s[q * 4 + 1] + kv.y * vj;
            s[q * 4 + 2] = ev.z * s[q * 4 + 2] + kv.z * vj;
            s[q * 4 + 3] = ev.w * s[q * 4 + 3] + kv.w * vj;
        }
    }

    int slot = (bh * NC + c) * DHz;
    #pragma unroll 8
    for (int ii = 0; ii < 32; ii++)
        g_state[(size_t)(slot + half * 32 + ii) * DHz + j] = s[ii];

    if (half == 0) {
        float w0 = 1.f, w1 = 1.f, w2 = 1.f, w3 = 1.f;
        #pragma unroll
        for (int t = 0; t < CL; t += 4) {
            w0 *= e_s[(t + 0) * 64 + j];
            w1 *= e_s[(t + 1) * 64 + j];
            w2 *= e_s[(t + 2) * 64 + j];
            w3 *= e_s[(t + 3) * 64 + j];
        }
        g_wprod[slot + j] = (w0 * w1) * (w2 * w3);
    }
}

// ---------------------------------------------------------------------------
// Pass B: sequential prefix over chunks. grid NBH, 256 threads.
// ---------------------------------------------------------------------------
__global__ void __launch_bounds__(256) scanB_kernel()
{
    __shared__ float s_w[64];
    int tid = threadIdx.x;
    int j   = tid & 63;
    int q   = tid >> 6;
    int bh = blockIdx.x;

    float R[16];
    #pragma unroll
    for (int i = 0; i < 16; i++) R[i] = 0.f;

    for (int c = 0; c < NC; c++) {
        int slot = (bh * NC + c) * DHz;
        if (c < NC - 1) {
            if (tid < 64) s_w[tid] = g_wprod[slot + tid];
            __syncthreads();
            #pragma unroll 8
            for (int ii = 0; ii < 16; ii++) {
                int i = q * 16 + ii;
                size_t a = (size_t)(slot + i) * DHz + j;
                float local = g_state[a];
                g_state[a] = R[ii];
                R[ii] = s_w[i] * R[ii] + local;
            }
            __syncthreads();
        } else {
            #pragma unroll 8
            for (int ii = 0; ii < 16; ii++)
                g_state[(size_t)(slot + q * 16 + ii) * DHz + j] = R[ii];
        }
    }
}

// ---------------------------------------------------------------------------
// Pass C (FUSED): scan outputs + bonus + groupnorm + r-mult + tf32 k-permute.
// grid (NC, NBH), 128 threads.
// smem floats: k 0, e 4096, v 8192, r 12288, op 16384(8192),
//              lnw 24576, lnb 24640, bp 24704(128), gs 24832(2*4), gq 24840(2*4)
// total 24848 floats = 99392 B
// ---------------------------------------------------------------------------
#define SCM_FLOATS 24848

__global__ void __launch_bounds__(128) scanC_kernel(
    const float* __restrict__ u,
    const float* __restrict__ ln_w, const float* __restrict__ ln_b)
{
    extern __shared__ __align__(16) float sm[];
    float* k_s  = sm;
    float* e_s  = sm + 4096;
    float* v_s  = sm + 8192;
    float* r_s  = sm + 12288;
    float* op   = sm + 16384;
    float* lnw_s = sm + 24576;
    float* lnb_s = sm + 24640;
    float* bp   = sm + 24704;    // [64][2]
    float* gs   = sm + 24832;    // [2][4] sum partials
    float* gq   = sm + 24840;    // [2][4] sq partials

    int tid  = threadIdx.x;
    int lane = tid & 31;
    int j    = tid & 63;
    int half = tid >> 6;
    int c  = blockIdx.x;
    int bh = blockIdx.y;
    int b = bh >> 4, h = bh & 15;

    int base0 = (b * Tz + c * CL) * Dz + h * 64;

    #pragma unroll
    for (int it = 0; it < 8; it++) {
        int f  = it * 128 + tid;
        int t  = f >> 4;
        int i4 = (f & 15) << 2;
        int ga = base0 + t * Dz + i4;
        int sa = t * 64 + i4;
        *(float4*)&k_s[sa] = *(const float4*)&g_buf[5][ga];
        *(float4*)&e_s[sa] = *(const float4*)&g_buf[7][ga];
        *(float4*)&v_s[sa] = *(const float4*)&g_buf[6][ga];
        *(float4*)&r_s[sa] = *(const float4*)&g_buf[4][ga];
    }
    if (tid < 64) { lnw_s[tid] = ln_w[tid]; lnb_s[tid] = ln_b[tid]; }

    float s[32];
    {
        int slot = (bh * NC + c) * DHz;
        #pragma unroll 8
        for (int ii = 0; ii < 32; ii++)
            s[ii] = g_state[(size_t)(slot + half * 32 + ii) * DHz + j];
    }
    __syncthreads();

    // ---- bonus: bp[t][w] = partial sum over 32 i of r*exp(u+k) ----
    // warp w covers (t parity = tid>>6, i-half = (tid>>5)&1)
    {
        int jb = (tid & 31) + (((tid >> 5) & 1) << 5);   // i index, fixed/thread
        float u_val = u[h * 64 + jb];
        int wslot = (tid >> 5) & 1;
        #pragma unroll 4
        for (int it = 0; it < 32; it++) {
            int t = it * 2 + (tid >> 6);
            float term = r_s[t * 64 + jb] * __expf(u_val + k_s[t * 64 + jb]);
            #pragma unroll
            for (int off = 16; off > 0; off >>= 1)
                term += __shfl_xor_sync(0xffffffffu, term, off);
            if (lane == 0) bp[t * 2 + wslot] = term;
        }
    }

    // ---- scan: partial o per (t, j, half) ----
    float* myop = op + half * 4096;
    for (int t = 0; t < CL; t++) {
        float vj = v_s[t * 64 + j];
        const float4* rp = (const float4*)&r_s[t * 64 + half * 32];
        const float4* kp = (const float4*)&k_s[t * 64 + half * 32];
        const float4* ep = (const float4*)&e_s[t * 64 + half * 32];
        float o0 = 0.f, o1 = 0.f, o2 = 0.f, o3 = 0.f;
        #pragma unroll
        for (int q = 0; q < 8; q++) {
            float4 rv = rp[q], kv = kp[q], ev = ep[q];
            o0 += rv.x * s[q * 4 + 0]; s[q * 4 + 0] = ev.x * s[q * 4 + 0] + kv.x * vj;
            o1 += rv.y * s[q * 4 + 1]; s[q * 4 + 1] = ev.y * s[q * 4 + 1] + kv.y * vj;
            o2 += rv.z * s[q * 4 + 2]; s[q * 4 + 2] = ev.z * s[q * 4 + 2] + kv.z * vj;
            o3 += rv.w * s[q * 4 + 3]; s[q * 4 + 3] = ev.w * s[q * 4 + 3] + kv.w * vj;
        }
        myop[t * 64 + j] = ((o0 + o1) + (o2 + o3));
    }
    __syncthreads();

    // ---- combine + groupnorm + r-mult + permuted tf32 store ----
    // warp coverage: slot = tid>>5 : {t-even jlo, t-even jhi, t-odd jlo, t-odd jhi}
    float* __restrict__ go = g_buf[8];
    int pslot = tid >> 5;
    // permuted position within 64: group g=j>>3, w=j&7
    int pj = ((j >> 3) << 3) + (((j & 7) < 4) ? 2 * (j & 3) : 2 * (j & 3) + 1);
    for (int it = 0; it < 32; it++) {
        int t = it * 2 + (tid >> 6);
        float bsum = bp[t * 2] + bp[t * 2 + 1];
        float o = op[t * 64 + j] + op[4096 + t * 64 + j] + bsum * v_s[t * 64 + j];
        float ssum = o, ssq = o * o;
        #pragma unroll
        for (int off = 16; off > 0; off >>= 1) {
            ssum += __shfl_xor_sync(0xffffffffu, ssum, off);
            ssq  += __shfl_xor_sync(0xffffffffu, ssq,  off);
        }
        int pb = it & 1;
        if (lane == 0) { gs[pb * 4 + pslot] = ssum; gq[pb * 4 + pslot] = ssq; }
        __syncthreads();
        int sb = (tid >> 6) * 2;
        float sum = gs[pb * 4 + sb] + gs[pb * 4 + sb + 1];
        float sq  = gq[pb * 4 + sb] + gq[pb * 4 + sb + 1];
        float mean = sum * (1.f / 64.f);
        float var  = sq * (1.f / 64.f) - mean * mean;
        float rs   = rsqrtf(var + 1e-5f);
        float n = to_tf32(((o - mean) * rs * lnw_s[j] + lnb_s[j])
                          * r_s[t * 64 + j]);
        go[base0 + t * Dz + pj] = n;
    }
}

// ---------------------------------------------------------------------------
extern "C" void kernel_launch(void* const* d_in, const int* in_sizes, int n_in,
                              void* d_out, int out_size)
{
    const float* x    = (const float*)d_in[0];
    const float* W_r  = (const float*)d_in[1];
    const float* W_k  = (const float*)d_in[2];
    const float* W_v  = (const float*)d_in[3];
    const float* W_w  = (const float*)d_in[4];
    const float* W_o  = (const float*)d_in[5];
    const float* u    = (const float*)d_in[6];
    const float* tm_r = (const float*)d_in[7];
    const float* tm_k = (const float*)d_in[8];
    const float* tm_v = (const float*)d_in[9];
    const float* tm_w = (const float*)d_in[10];
    const float* ln_w = (const float*)d_in[11];
    const float* ln_b = (const float*)d_in[12];
    float* out = (float*)d_out;

    cudaFuncSetAttribute(scanA_kernel,
        cudaFuncAttributeMaxDynamicSharedMemorySize, 12288 * 4);
    cudaFuncSetAttribute(scanC_kernel,
        cudaFuncAttributeMaxDynamicSharedMemorySize, SCM_FLOATS * 4);
    cudaFuncSetAttribute(proj_gemm,
        cudaFuncAttributeMaxDynamicSharedMemorySize, GSMB);
    cudaFuncSetAttribute(out_gemm,
        cudaFuncAttributeMaxDynamicSharedMemorySize, GSMB);

    roundw_kernel<<<2560, 256>>>(
        (const float4*)W_r, (const float4*)W_k, (const float4*)W_v,
        (const float4*)W_w, (const float4*)W_o);

    mix_kernel<<<2048, 256>>>(
        (const float4*)x, (const float4*)tm_r, (const float4*)tm_k,
        (const float4*)tm_v, (const float4*)tm_w);

    proj_gemm<<<dim3(Nz / 128, Mz / 128, 4), 128, GSMB>>>();

    scanA_kernel<<<dim3(NC - 1, NBH), 128, 12288 * 4>>>();
    scanB_kernel<<<NBH, 256>>>();
    scanC_kernel<<<dim3(NC, NBH), 128, SCM_FLOATS * 4>>>(u, ln_w, ln_b);

    out_gemm<<<dim3(Nz / 128, Mz / 128), 128, GSMB>>>(out);
}

// round 11
// speedup vs baseline: 1.0791x; 1.0791x over previous
#include <cuda_runtime.h>
#include <cstdint>

#define Bz 4
#define Tz 1024
#define Dz 1024
#define Hz 16
#define DHz 64
#define Mz (Bz*Tz)        // 4096
#define Kz Dz
#define Nz Dz
#define MD (Mz*Dz)        // 4,194,304
#define NBH (Bz*Hz)       // 64
#define CL 64             // chunk length
#define NC (Tz/CL)        // 16 chunks

// 0..3 = xr,xk,xv,xw (tf32, k-permuted) ; 4=r ; 5=k ; 6=v ; 7=exp(w) (normal)
// 8=o (k-permuted tf32, written by fused scanC)
__device__ float g_buf[9][MD];
__device__ float g_wr[5 * Dz * Dz];               // tf32 k-permuted weights
__device__ float g_state[NBH * NC * DHz * DHz];   // chunk states
__device__ float g_wprod[NBH * NC * DHz];         // per-chunk decay products

__device__ __forceinline__ float to_tf32(float x)
{
    uint32_t d;
    asm("cvt.rna.tf32.f32 %0, %1;" : "=r"(d) : "f"(x));
    return __uint_as_float(d);
}
__device__ __forceinline__ uint32_t smem_to_u32(const void* p) {
    uint32_t a;
    asm("{ .reg .u64 t; cvta.to.shared.u64 t, %1; cvt.u32.u64 %0, t; }"
        : "=r"(a) : "l"(p));
    return a;
}
__device__ __forceinline__ void cp16(uint32_t dst, const void* src) {
    asm volatile("cp.async.cg.shared.global [%0], [%1], 16;"
                 :: "r"(dst), "l"(src));
}
__device__ __forceinline__ void cp_commit() {
    asm volatile("cp.async.commit_group;" ::: "memory");
}
__device__ __forceinline__ void mma_tf32(float c[4], const uint32_t a[4],
                                         const uint32_t b[2])
{
    asm volatile(
        "mma.sync.aligned.m16n8k8.row.col.f32.tf32.tf32.f32 "
        "{%0,%1,%2,%3}, {%4,%5,%6,%7}, {%8,%9}, {%0,%1,%2,%3};"
        : "+f"(c[0]), "+f"(c[1]), "+f"(c[2]), "+f"(c[3])
        : "r"(a[0]), "r"(a[1]), "r"(a[2]), "r"(a[3]),
          "r"(b[0]), "r"(b[1]));
}

// permute helper: 8 floats (a=k0..3, b=k4..7) -> [k0,k4,k1,k5] and [k2,k6,k3,k7]
__device__ __forceinline__ void perm_pair(const float4& a, const float4& b,
                                          float4& o0, float4& o1)
{
    o0 = make_float4(a.x, b.x, a.y, b.y);
    o1 = make_float4(a.z, b.z, a.w, b.w);
}

// ---------------------------------------------------------------------------
// round 5 weight matrices to tf32, k-permuted, into g_wr
// ---------------------------------------------------------------------------
__global__ void __launch_bounds__(256) roundw_kernel(
    const float4* __restrict__ a, const float4* __restrict__ b,
    const float4* __restrict__ c, const float4* __restrict__ d,
    const float4* __restrict__ e)
{
    int idx = blockIdx.x * 256 + threadIdx.x;      // 0..655359
    int which = idx >> 17;
    int off = idx & 131071;
    const float4* src = which == 0 ? a : which == 1 ? b : which == 2 ? c
                       : which == 3 ? d : e;
    float4 v0 = src[2 * off], v1 = src[2 * off + 1];
    v0.x = to_tf32(v0.x); v0.y = to_tf32(v0.y); v0.z = to_tf32(v0.z); v0.w = to_tf32(v0.w);
    v1.x = to_tf32(v1.x); v1.y = to_tf32(v1.y); v1.z = to_tf32(v1.z); v1.w = to_tf32(v1.w);
    float4 o0, o1;
    perm_pair(v0, v1, o0, o1);
    float4* dst = reinterpret_cast<float4*>(g_wr) + (size_t)which * 262144;
    dst[2 * off] = o0;
    dst[2 * off + 1] = o1;
}

// ---------------------------------------------------------------------------
// token-shift mix, tf32-rounded + k-permuted
// ---------------------------------------------------------------------------
__global__ void __launch_bounds__(256) mix_kernel(
    const float4* __restrict__ x,
    const float4* __restrict__ tmr, const float4* __restrict__ tmk,
    const float4* __restrict__ tmv, const float4* __restrict__ tmw)
{
    int idx = blockIdx.x * 256 + threadIdx.x;   // MD/8
    int m  = idx >> 7;
    int gg = idx & 127;
    int t  = m & (Tz - 1);

    float4 x0 = x[(m << 8) + 2 * gg];
    float4 x1 = x[(m << 8) + 2 * gg + 1];
    float4 p0 = make_float4(0.f, 0.f, 0.f, 0.f), p1 = p0;
    if (t != 0) {
        p0 = x[((m - 1) << 8) + 2 * gg];
        p1 = x[((m - 1) << 8) + 2 * gg + 1];
    }

    #define DO_MIX(TMV, DSTI)                                               \
    {                                                                       \
        float4 w0 = TMV[2 * gg], w1 = TMV[2 * gg + 1];                      \
        float4 a, b;                                                        \
        a.x = to_tf32(w0.x * x0.x + (1.f - w0.x) * p0.x);                   \
        a.y = to_tf32(w0.y * x0.y + (1.f - w0.y) * p0.y);                   \
        a.z = to_tf32(w0.z * x0.z + (1.f - w0.z) * p0.z);                   \
        a.w = to_tf32(w0.w * x0.w + (1.f - w0.w) * p0.w);                   \
        b.x = to_tf32(w1.x * x1.x + (1.f - w1.x) * p1.x);                   \
        b.y = to_tf32(w1.y * x1.y + (1.f - w1.y) * p1.y);                   \
        b.z = to_tf32(w1.z * x1.z + (1.f - w1.z) * p1.z);                   \
        b.w = to_tf32(w1.w * x1.w + (1.f - w1.w) * p1.w);                   \
        float4 o0, o1;                                                      \
        perm_pair(a, b, o0, o1);                                            \
        reinterpret_cast<float4*>(g_buf[DSTI])[2 * idx]     = o0;           \
        reinterpret_cast<float4*>(g_buf[DSTI])[2 * idx + 1] = o1;           \
    }
    DO_MIX(tmr, 0)
    DO_MIX(tmk, 1)
    DO_MIX(tmv, 2)
    DO_MIX(tmw, 3)
    #undef DO_MIX
}

// ---------------------------------------------------------------------------
// tf32 mma.sync GEMM on k-permuted operands (unchanged from round 9)
// ---------------------------------------------------------------------------
#define TB 4096
#define GSMB (3 * 2 * TB * 4)                 // 98304 bytes

__device__ __forceinline__ void gemm_body(
    const float* __restrict__ A,
    const float* __restrict__ W,
    float* __restrict__ C, int epi)
{
    extern __shared__ __align__(16) float sm[];
    float* As = sm;
    float* Bs = sm + 3 * TB;
    uint32_t a32 = smem_to_u32(As);
    uint32_t b32 = smem_to_u32(Bs);

    int tid  = threadIdx.x;
    int lane = tid & 31;
    int wid  = tid >> 5;
    int bm = blockIdx.y * 128;
    int bn = blockIdx.x * 128;

    int wm = (wid >> 1) * 64;
    int wn = (wid & 1) * 64;
    int frow = lane >> 2;
    int fk   = lane & 3;

    float acc[4][8][4];
    #pragma unroll
    for (int i = 0; i < 4; i++)
        #pragma unroll
        for (int j = 0; j < 8; j++)
            #pragma unroll
            for (int r = 0; r < 4; r++) acc[i][j][r] = 0.f;

    #define GSTAGE(CC, BUF)                                                  \
    {                                                                        \
        const char* ap = (const char*)(A + (size_t)bm * Kz + (CC) * 32);     \
        const char* bp = (const char*)(W + (size_t)bn * Kz + (CC) * 32);     \
        _Pragma("unroll")                                                    \
        for (int i = 0; i < 8; i++) {                                        \
            int lin = i * 128 + tid;                                         \
            int r = lin >> 3;                                                \
            int g = lin & 7;                                                 \
            int slot = (g + 2 * (r & 3)) & 7;                                \
            cp16(a32 + (BUF) * (TB * 4) + r * 128 + slot * 16,               \
                 ap + (size_t)r * (Kz * 4) + g * 16);                        \
            cp16(b32 + (BUF) * (TB * 4) + r * 128 + slot * 16,               \
                 bp + (size_t)r * (Kz * 4) + g * 16);                        \
        }                                                                    \
    }

    GSTAGE(0, 0) cp_commit();
    GSTAGE(1, 1) cp_commit();

    const int NIT = Kz >> 5;
    int buf = 0;
    for (int c = 0; c < NIT; c++) {
        asm volatile("cp.async.wait_group 1;" ::: "memory");
        __syncthreads();
        if (c + 2 < NIT) {
            int nb = (c + 2) % 3;
            if (nb == 0)      { GSTAGE(c + 2, 0) }
            else if (nb == 1) { GSTAGE(c + 2, 1) }
            else              { GSTAGE(c + 2, 2) }
        }
        cp_commit();

        const float* a_s = As + buf * TB;
        const float* b_s = Bs + buf * TB;
        #pragma unroll
        for (int ks = 0; ks < 4; ks++) {
            uint32_t afr[4][4], bfr[8][2];
            int slot = (2 * ks + (fk >> 1) + 2 * (frow & 3)) & 7;
            int fo = slot * 4 + (fk & 1) * 2;
            #pragma unroll
            for (int mt = 0; mt < 4; mt++) {
                int rr = wm + mt * 16 + frow;
                float2 u = *(const float2*)&a_s[rr * 32 + fo];
                float2 v = *(const float2*)&a_s[(rr + 8) * 32 + fo];
                afr[mt][0] = __float_as_uint(u.x);
                afr[mt][1] = __float_as_uint(v.x);
                afr[mt][2] = __float_as_uint(u.y);
                afr[mt][3] = __float_as_uint(v.y);
            }
            #pragma unroll
            for (int nt = 0; nt < 8; nt++) {
                int rn = wn + nt * 8 + frow;
                float2 w2 = *(const float2*)&b_s[rn * 32 + fo];
                bfr[nt][0] = __float_as_uint(w2.x);
                bfr[nt][1] = __float_as_uint(w2.y);
            }
            #pragma unroll
            for (int mt = 0; mt < 4; mt++)
                #pragma unroll
                for (int nt = 0; nt < 8; nt++)
                    mma_tf32(acc[mt][nt], afr[mt], bfr[nt]);
        }
        buf = (buf + 1) == 3 ? 0 : buf + 1;
    }
    #undef GSTAGE

    #pragma unroll
    for (int mt = 0; mt < 4; mt++) {
        int row = bm + wm + mt * 16 + frow;
        #pragma unroll
        for (int nt = 0; nt < 8; nt++) {
            int col = bn + wn + nt * 8 + fk * 2;
            float vv[4];
            #pragma unroll
            for (int r = 0; r < 4; r++) {
                float v = acc[mt][nt][r];
                if (epi == 1)      v = 1.f / (1.f + __expf(-v));
                else if (epi == 2) v = 0.999900004999833f / (1.f + __expf(-v));
                vv[r] = v;
            }
            *(float2*)&C[(size_t)row * Nz + col]       = make_float2(vv[0], vv[1]);
            *(float2*)&C[(size_t)(row + 8) * Nz + col] = make_float2(vv[2], vv[3]);
        }
    }
}

__global__ void __launch_bounds__(128, 2) proj_gemm()
{
    int which = blockIdx.z;
    int epi = (which == 0) ? 1 : (which == 3) ? 2 : 0;
    gemm_body(g_buf[which], g_wr + (size_t)which * (Dz * Dz),
              g_buf[4 + which], epi);
}

__global__ void __launch_bounds__(128, 2) out_gemm(float* __restrict__ out)
{
    gemm_body(g_buf[8], g_wr + (size_t)4 * (Dz * Dz), out, 0);
}

// ---------------------------------------------------------------------------
// Pass A: chunk-local scan, zero init. grid (NC-1, NBH), 128 threads.
// ---------------------------------------------------------------------------
__global__ void __launch_bounds__(128) scanA_kernel()
{
    extern __shared__ __align__(16) float sm[];
    float* k_s = sm;
    float* e_s = sm + 4096;
    float* v_s = sm + 8192;

    int tid  = threadIdx.x;
    int j    = tid & 63;
    int half = tid >> 6;
    int c  = blockIdx.x;
    int bh = blockIdx.y;
    int b = bh >> 4, h = bh & 15;

    int base0 = (b * Tz + c * CL) * Dz + h * 64;

    #pragma unroll
    for (int it = 0; it < 8; it++) {
        int f  = it * 128 + tid;
        int t  = f >> 4;
        int i4 = (f & 15) << 2;
        int ga = base0 + t * Dz + i4;
        int sa = t * 64 + i4;
        *(float4*)&k_s[sa] = *(const float4*)&g_buf[5][ga];
        *(float4*)&e_s[sa] = *(const float4*)&g_buf[7][ga];
        *(float4*)&v_s[sa] = *(const float4*)&g_buf[6][ga];
    }
    __syncthreads();

    float s[32];
    #pragma unroll
    for (int i = 0; i < 32; i++) s[i] = 0.f;

    for (int t = 0; t < CL; t++) {
        float vj = v_s[t * 64 + j];
        const float4* kp = (const float4*)&k_s[t * 64 + half * 32];
        const float4* ep = (const float4*)&e_s[t * 64 + half * 32];
        #pragma unroll
        for (int q = 0; q < 8; q++) {
            float4 kv = kp[q], ev = ep[q];
            s[q * 4 + 0] = ev.x * s[q * 4 + 0] + kv.x * vj;
            s[q * 4 + 1] = ev.y * s[q * 4 + 1] + kv.y * vj;
            s[q * 4 + 2] = ev.z * s[q * 4 + 2] + kv.z * vj;
            s[q * 4 + 3] = ev.w * s[q * 4 + 3] + kv.w * vj;
        }
    }

    int slot = (bh * NC + c) * DHz;
    #pragma unroll 8
    for (int ii = 0; ii < 32; ii++)
        g_state[(size_t)(slot + half * 32 + ii) * DHz + j] = s[ii];

    if (half == 0) {
        float w0 = 1.f, w1 = 1.f, w2 = 1.f, w3 = 1.f;
        #pragma unroll
        for (int t = 0; t < CL; t += 4) {
            w0 *= e_s[(t + 0) * 64 + j];
            w1 *= e_s[(t + 1) * 64 + j];
            w2 *= e_s[(t + 2) * 64 + j];
            w3 *= e_s[(t + 3) * 64 + j];
        }
        g_wprod[slot + j] = (w0 * w1) * (w2 * w3);
    }
}

// ---------------------------------------------------------------------------
// Pass B: sequential prefix over chunks. grid NBH, 256 threads.
// ---------------------------------------------------------------------------
__global__ void __launch_bounds__(256) scanB_kernel()
{
    __shared__ float s_w[64];
    int tid = threadIdx.x;
    int j   = tid & 63;
    int q   = tid >> 6;
    int bh = blockIdx.x;

    float R[16];
    #pragma unroll
    for (int i = 0; i < 16; i++) R[i] = 0.f;

    for (int c = 0; c < NC; c++) {
        int slot = (bh * NC + c) * DHz;
        if (c < NC - 1) {
            if (tid < 64) s_w[tid] = g_wprod[slot + tid];
            __syncthreads();
            #pragma unroll 8
            for (int ii = 0; ii < 16; ii++) {
                int i = q * 16 + ii;
                size_t a = (size_t)(slot + i) * DHz + j;
                float local = g_state[a];
                g_state[a] = R[ii];
                R[ii] = s_w[i] * R[ii] + local;
            }
            __syncthreads();
        } else {
            #pragma unroll 8
            for (int ii = 0; ii < 16; ii++)
                g_state[(size_t)(slot + q * 16 + ii) * DHz + j] = R[ii];
        }
    }
}

// ---------------------------------------------------------------------------
// Pass C (FUSED, barrier-free combine): scan outputs + bonus + groupnorm +
// r-mult + tf32 k-permute. grid (NC, NBH), 128 threads.
// Combine: warp w owns t = 4*it + w; lane holds j=lane and j=lane+32;
// bonus + groupnorm stats via warp shuffles only.
// smem floats: k 0, e 4096, v 8192, r 12288, op 16384(8192),
//              lnw 24576, lnb 24640 -> total 24704 floats = 98816 B
// ---------------------------------------------------------------------------
#define SCM_FLOATS 24704

__global__ void __launch_bounds__(128) scanC_kernel(
    const float* __restrict__ u,
    const float* __restrict__ ln_w, const float* __restrict__ ln_b)
{
    extern __shared__ __align__(16) float sm[];
    float* k_s  = sm;
    float* e_s  = sm + 4096;
    float* v_s  = sm + 8192;
    float* r_s  = sm + 12288;
    float* op   = sm + 16384;
    float* lnw_s = sm + 24576;
    float* lnb_s = sm + 24640;

    int tid  = threadIdx.x;
    int lane = tid & 31;
    int wid  = tid >> 5;
    int j    = tid & 63;
    int half = tid >> 6;
    int c  = blockIdx.x;
    int bh = blockIdx.y;
    int b = bh >> 4, h = bh & 15;

    int base0 = (b * Tz + c * CL) * Dz + h * 64;

    #pragma unroll
    for (int it = 0; it < 8; it++) {
        int f  = it * 128 + tid;
        int t  = f >> 4;
        int i4 = (f & 15) << 2;
        int ga = base0 + t * Dz + i4;
        int sa = t * 64 + i4;
        *(float4*)&k_s[sa] = *(const float4*)&g_buf[5][ga];
        *(float4*)&e_s[sa] = *(const float4*)&g_buf[7][ga];
        *(float4*)&v_s[sa] = *(const float4*)&g_buf[6][ga];
        *(float4*)&r_s[sa] = *(const float4*)&g_buf[4][ga];
    }
    if (tid < 64) { lnw_s[tid] = ln_w[tid]; lnb_s[tid] = ln_b[tid]; }

    float s[32];
    {
        int slot = (bh * NC + c) * DHz;
        #pragma unroll 8
        for (int ii = 0; ii < 32; ii++)
            s[ii] = g_state[(size_t)(slot + half * 32 + ii) * DHz + j];
    }
    __syncthreads();

    // ---- scan: partial o per (t, j, half) ----
    float* myop = op + half * 4096;
    for (int t = 0; t < CL; t++) {
        float vj = v_s[t * 64 + j];
        const float4* rp = (const float4*)&r_s[t * 64 + half * 32];
        const float4* kp = (const float4*)&k_s[t * 64 + half * 32];
        const float4* ep = (const float4*)&e_s[t * 64 + half * 32];
        float o0 = 0.f, o1 = 0.f, o2 = 0.f, o3 = 0.f;
        #pragma unroll
        for (int q = 0; q < 8; q++) {
            float4 rv = rp[q], kv = kp[q], ev = ep[q];
            o0 += rv.x * s[q * 4 + 0]; s[q * 4 + 0] = ev.x * s[q * 4 + 0] + kv.x * vj;
            o1 += rv.y * s[q * 4 + 1]; s[q * 4 + 1] = ev.y * s[q * 4 + 1] + kv.y * vj;
            o2 += rv.z * s[q * 4 + 2]; s[q * 4 + 2] = ev.z * s[q * 4 + 2] + kv.z * vj;
            o3 += rv.w * s[q * 4 + 3]; s[q * 4 + 3] = ev.w * s[q * 4 + 3] + kv.w * vj;
        }
        myop[t * 64 + j] = ((o0 + o1) + (o2 + o3));
    }
    __syncthreads();

    // ---- combine (barrier-free): warp w handles t = 4*it + w ----
    float* __restrict__ go = g_buf[8];
    float u0 = u[h * 64 + lane];
    float u1 = u[h * 64 + 32 + lane];
    float lw0 = lnw_s[lane],      lb0 = lnb_s[lane];
    float lw1 = lnw_s[lane + 32], lb1 = lnb_s[lane + 32];
    // permuted positions for j=lane and j=lane+32
    int pj0 = ((lane >> 3) << 3)
            + (((lane & 7) < 4) ? 2 * (lane & 3) : 2 * (lane & 3) + 1);
    int pj1 = pj0 + 32;

    #pragma unroll 4
    for (int it = 0; it < 16; it++) {
        int t = it * 4 + wid;
        int tb = t * 64;
        float r0 = r_s[tb + lane], r1 = r_s[tb + 32 + lane];
        float v0 = v_s[tb + lane], v1 = v_s[tb + 32 + lane];

        // bonus = sum_i r*exp(u+k)
        float term = r0 * __expf(u0 + k_s[tb + lane])
                   + r1 * __expf(u1 + k_s[tb + 32 + lane]);
        #pragma unroll
        for (int off = 16; off > 0; off >>= 1)
            term += __shfl_xor_sync(0xffffffffu, term, off);

        float o0 = op[tb + lane]      + op[4096 + tb + lane]      + term * v0;
        float o1 = op[tb + 32 + lane] + op[4096 + tb + 32 + lane] + term * v1;

        float ssum = o0 + o1;
        float ssq  = o0 * o0 + o1 * o1;
        #pragma unroll
        for (int off = 16; off > 0; off >>= 1) {
            ssum += __shfl_xor_sync(0xffffffffu, ssum, off);
            ssq  += __shfl_xor_sync(0xffffffffu, ssq,  off);
        }
        float mean = ssum * (1.f / 64.f);
        float var  = ssq * (1.f / 64.f) - mean * mean;
        float rsd  = rsqrtf(var + 1e-5f);

        float n0 = to_tf32(((o0 - mean) * rsd * lw0 + lb0) * r0);
        float n1 = to_tf32(((o1 - mean) * rsd * lw1 + lb1) * r1);
        go[base0 + t * Dz + pj0] = n0;
        go[base0 + t * Dz + pj1] = n1;
    }
}

// ---------------------------------------------------------------------------
extern "C" void kernel_launch(void* const* d_in, const int* in_sizes, int n_in,
                              void* d_out, int out_size)
{
    const float* x    = (const float*)d_in[0];
    const float* W_r  = (const float*)d_in[1];
    const float* W_k  = (const float*)d_in[2];
    const float* W_v  = (const float*)d_in[3];
    const float* W_w  = (const float*)d_in[4];
    const float* W_o  = (const float*)d_in[5];
    const float* u    = (const float*)d_in[6];
    const float* tm_r = (const float*)d_in[7];
    const float* tm_k = (const float*)d_in[8];
    const float* tm_v = (const float*)d_in[9];
    const float* tm_w = (const float*)d_in[10];
    const float* ln_w = (const float*)d_in[11];
    const float* ln_b = (const float*)d_in[12];
    float* out = (float*)d_out;

    cudaFuncSetAttribute(scanA_kernel,
        cudaFuncAttributeMaxDynamicSharedMemorySize, 12288 * 4);
    cudaFuncSetAttribute(scanC_kernel,
        cudaFuncAttributeMaxDynamicSharedMemorySize, SCM_FLOATS * 4);
    cudaFuncSetAttribute(proj_gemm,
        cudaFuncAttributeMaxDynamicSharedMemorySize, GSMB);
    cudaFuncSetAttribute(out_gemm,
        cudaFuncAttributeMaxDynamicSharedMemorySize, GSMB);

    roundw_kernel<<<2560, 256>>>(
        (const float4*)W_r, (const float4*)W_k, (const float4*)W_v,
        (const float4*)W_w, (const float4*)W_o);

    mix_kernel<<<2048, 256>>>(
        (const float4*)x, (const float4*)tm_r, (const float4*)tm_k,
        (const float4*)tm_v, (const float4*)tm_w);

    proj_gemm<<<dim3(Nz / 128, Mz / 128, 4), 128, GSMB>>>();

    scanA_kernel<<<dim3(NC - 1, NBH), 128, 12288 * 4>>>();
    scanB_kernel<<<NBH, 256>>>();
    scanC_kernel<<<dim3(NC, NBH), 128, SCM_FLOATS * 4>>>(u, ln_w, ln_b);

    out_gemm<<<dim3(Nz / 128, Mz / 128), 128, GSMB>>>(out);
}

// round 12
// speedup vs baseline: 1.0837x; 1.0043x over previous
#include <cuda_runtime.h>
#include <cstdint>

#define Bz 4
#define Tz 1024
#define Dz 1024
#define Hz 16
#define DHz 64
#define Mz (Bz*Tz)        // 4096
#define Kz Dz
#define Nz Dz
#define MD (Mz*Dz)        // 4,194,304
#define NBH (Bz*Hz)       // 64
#define CL 64             // chunk length
#define NC (Tz/CL)        // 16 chunks

// 0..3 = xr,xk,xv,xw (tf32, k-permuted) ; 4=r ; 5=k ; 6=v ; 7=exp(w) (normal)
// 8=o (k-permuted tf32, written by fused scanC)
__device__ float g_buf[9][MD];
__device__ float g_wr[5 * Dz * Dz];               // tf32 k-permuted weights
__device__ float g_state[NBH * NC * DHz * DHz];   // chunk states
__device__ float g_wprod[NBH * NC * DHz];         // per-chunk decay products

__device__ __forceinline__ float to_tf32(float x)
{
    uint32_t d;
    asm("cvt.rna.tf32.f32 %0, %1;" : "=r"(d) : "f"(x));
    return __uint_as_float(d);
}
__device__ __forceinline__ uint32_t smem_to_u32(const void* p) {
    uint32_t a;
    asm("{ .reg .u64 t; cvta.to.shared.u64 t, %1; cvt.u32.u64 %0, t; }"
        : "=r"(a) : "l"(p));
    return a;
}
__device__ __forceinline__ void cp16(uint32_t dst, const void* src) {
    asm volatile("cp.async.cg.shared.global [%0], [%1], 16;"
                 :: "r"(dst), "l"(src));
}
__device__ __forceinline__ void cp_commit() {
    asm volatile("cp.async.commit_group;" ::: "memory");
}
__device__ __forceinline__ void mma_tf32(float c[4], const uint32_t a[4],
                                         const uint32_t b[2])
{
    asm volatile(
        "mma.sync.aligned.m16n8k8.row.col.f32.tf32.tf32.f32 "
        "{%0,%1,%2,%3}, {%4,%5,%6,%7}, {%8,%9}, {%0,%1,%2,%3};"
        : "+f"(c[0]), "+f"(c[1]), "+f"(c[2]), "+f"(c[3])
        : "r"(a[0]), "r"(a[1]), "r"(a[2]), "r"(a[3]),
          "r"(b[0]), "r"(b[1]));
}

// permute helper: 8 floats (a=k0..3, b=k4..7) -> [k0,k4,k1,k5] and [k2,k6,k3,k7]
__device__ __forceinline__ void perm_pair(const float4& a, const float4& b,
                                          float4& o0, float4& o1)
{
    o0 = make_float4(a.x, b.x, a.y, b.y);
    o1 = make_float4(a.z, b.z, a.w, b.w);
}

// ---------------------------------------------------------------------------
// round 5 weight matrices to tf32, k-permuted, into g_wr
// ---------------------------------------------------------------------------
__global__ void __launch_bounds__(256) roundw_kernel(
    const float4* __restrict__ a, const float4* __restrict__ b,
    const float4* __restrict__ c, const float4* __restrict__ d,
    const float4* __restrict__ e)
{
    int idx = blockIdx.x * 256 + threadIdx.x;      // 0..655359
    int which = idx >> 17;
    int off = idx & 131071;
    const float4* src = which == 0 ? a : which == 1 ? b : which == 2 ? c
                       : which == 3 ? d : e;
    float4 v0 = src[2 * off], v1 = src[2 * off + 1];
    v0.x = to_tf32(v0.x); v0.y = to_tf32(v0.y); v0.z = to_tf32(v0.z); v0.w = to_tf32(v0.w);
    v1.x = to_tf32(v1.x); v1.y = to_tf32(v1.y); v1.z = to_tf32(v1.z); v1.w = to_tf32(v1.w);
    float4 o0, o1;
    perm_pair(v0, v1, o0, o1);
    float4* dst = reinterpret_cast<float4*>(g_wr) + (size_t)which * 262144;
    dst[2 * off] = o0;
    dst[2 * off + 1] = o1;
}

// ---------------------------------------------------------------------------
// token-shift mix, tf32-rounded + k-permuted
// ---------------------------------------------------------------------------
__global__ void __launch_bounds__(256) mix_kernel(
    const float4* __restrict__ x,
    const float4* __restrict__ tmr, const float4* __restrict__ tmk,
    const float4* __restrict__ tmv, const float4* __restrict__ tmw)
{
    int idx = blockIdx.x * 256 + threadIdx.x;   // MD/8
    int m  = idx >> 7;
    int gg = idx & 127;
    int t  = m & (Tz - 1);

    float4 x0 = x[(m << 8) + 2 * gg];
    float4 x1 = x[(m << 8) + 2 * gg + 1];
    float4 p0 = make_float4(0.f, 0.f, 0.f, 0.f), p1 = p0;
    if (t != 0) {
        p0 = x[((m - 1) << 8) + 2 * gg];
        p1 = x[((m - 1) << 8) + 2 * gg + 1];
    }

    #define DO_MIX(TMV, DSTI)                                               \
    {                                                                       \
        float4 w0 = TMV[2 * gg], w1 = TMV[2 * gg + 1];                      \
        float4 a, b;                                                        \
        a.x = to_tf32(w0.x * x0.x + (1.f - w0.x) * p0.x);                   \
        a.y = to_tf32(w0.y * x0.y + (1.f - w0.y) * p0.y);                   \
        a.z = to_tf32(w0.z * x0.z + (1.f - w0.z) * p0.z);                   \
        a.w = to_tf32(w0.w * x0.w + (1.f - w0.w) * p0.w);                   \
        b.x = to_tf32(w1.x * x1.x + (1.f - w1.x) * p1.x);                   \
        b.y = to_tf32(w1.y * x1.y + (1.f - w1.y) * p1.y);                   \
        b.z = to_tf32(w1.z * x1.z + (1.f - w1.z) * p1.z);                   \
        b.w = to_tf32(w1.w * x1.w + (1.f - w1.w) * p1.w);                   \
        float4 o0, o1;                                                      \
        perm_pair(a, b, o0, o1);                                            \
        reinterpret_cast<float4*>(g_buf[DSTI])[2 * idx]     = o0;           \
        reinterpret_cast<float4*>(g_buf[DSTI])[2 * idx + 1] = o1;           \
    }
    DO_MIX(tmr, 0)
    DO_MIX(tmk, 1)
    DO_MIX(tmv, 2)
    DO_MIX(tmw, 3)
    #undef DO_MIX
}

// ---------------------------------------------------------------------------
// tf32 mma.sync GEMM on k-permuted operands (unchanged from round 9)
// ---------------------------------------------------------------------------
#define TB 4096
#define GSMB (3 * 2 * TB * 4)                 // 98304 bytes

__device__ __forceinline__ void gemm_body(
    const float* __restrict__ A,
    const float* __restrict__ W,
    float* __restrict__ C, int epi)
{
    extern __shared__ __align__(16) float sm[];
    float* As = sm;
    float* Bs = sm + 3 * TB;
    uint32_t a32 = smem_to_u32(As);
    uint32_t b32 = smem_to_u32(Bs);

    int tid  = threadIdx.x;
    int lane = tid & 31;
    int wid  = tid >> 5;
    int bm = blockIdx.y * 128;
    int bn = blockIdx.x * 128;

    int wm = (wid >> 1) * 64;
    int wn = (wid & 1) * 64;
    int frow = lane >> 2;
    int fk   = lane & 3;

    float acc[4][8][4];
    #pragma unroll
    for (int i = 0; i < 4; i++)
        #pragma unroll
        for (int j = 0; j < 8; j++)
            #pragma unroll
            for (int r = 0; r < 4; r++) acc[i][j][r] = 0.f;

    #define GSTAGE(CC, BUF)                                                  \
    {                                                                        \
        const char* ap = (const char*)(A + (size_t)bm * Kz + (CC) * 32);     \
        const char* bp = (const char*)(W + (size_t)bn * Kz + (CC) * 32);     \
        _Pragma("unroll")                                                    \
        for (int i = 0; i < 8; i++) {                                        \
            int lin = i * 128 + tid;                                         \
            int r = lin >> 3;                                                \
            int g = lin & 7;                                                 \
            int slot = (g + 2 * (r & 3)) & 7;                                \
            cp16(a32 + (BUF) * (TB * 4) + r * 128 + slot * 16,               \
                 ap + (size_t)r * (Kz * 4) + g * 16);                        \
            cp16(b32 + (BUF) * (TB * 4) + r * 128 + slot * 16,               \
                 bp + (size_t)r * (Kz * 4) + g * 16);                        \
        }                                                                    \
    }

    GSTAGE(0, 0) cp_commit();
    GSTAGE(1, 1) cp_commit();

    const int NIT = Kz >> 5;
    int buf = 0;
    for (int c = 0; c < NIT; c++) {
        asm volatile("cp.async.wait_group 1;" ::: "memory");
        __syncthreads();
        if (c + 2 < NIT) {
            int nb = (c + 2) % 3;
            if (nb == 0)      { GSTAGE(c + 2, 0) }
            else if (nb == 1) { GSTAGE(c + 2, 1) }
            else              { GSTAGE(c + 2, 2) }
        }
        cp_commit();

        const float* a_s = As + buf * TB;
        const float* b_s = Bs + buf * TB;
        #pragma unroll
        for (int ks = 0; ks < 4; ks++) {
            uint32_t afr[4][4], bfr[8][2];
            int slot = (2 * ks + (fk >> 1) + 2 * (frow & 3)) & 7;
            int fo = slot * 4 + (fk & 1) * 2;
            #pragma unroll
            for (int mt = 0; mt < 4; mt++) {
                int rr = wm + mt * 16 + frow;
                float2 u = *(const float2*)&a_s[rr * 32 + fo];
                float2 v = *(const float2*)&a_s[(rr + 8) * 32 + fo];
                afr[mt][0] = __float_as_uint(u.x);
                afr[mt][1] = __float_as_uint(v.x);
                afr[mt][2] = __float_as_uint(u.y);
                afr[mt][3] = __float_as_uint(v.y);
            }
            #pragma unroll
            for (int nt = 0; nt < 8; nt++) {
                int rn = wn + nt * 8 + frow;
                float2 w2 = *(const float2*)&b_s[rn * 32 + fo];
                bfr[nt][0] = __float_as_uint(w2.x);
                bfr[nt][1] = __float_as_uint(w2.y);
            }
            #pragma unroll
            for (int mt = 0; mt < 4; mt++)
                #pragma unroll
                for (int nt = 0; nt < 8; nt++)
                    mma_tf32(acc[mt][nt], afr[mt], bfr[nt]);
        }
        buf = (buf + 1) == 3 ? 0 : buf + 1;
    }
    #undef GSTAGE

    #pragma unroll
    for (int mt = 0; mt < 4; mt++) {
        int row = bm + wm + mt * 16 + frow;
        #pragma unroll
        for (int nt = 0; nt < 8; nt++) {
            int col = bn + wn + nt * 8 + fk * 2;
            float vv[4];
            #pragma unroll
            for (int r = 0; r < 4; r++) {
                float v = acc[mt][nt][r];
                if (epi == 1)      v = 1.f / (1.f + __expf(-v));
                else if (epi == 2) v = 0.999900004999833f / (1.f + __expf(-v));
                vv[r] = v;
            }
            *(float2*)&C[(size_t)row * Nz + col]       = make_float2(vv[0], vv[1]);
            *(float2*)&C[(size_t)(row + 8) * Nz + col] = make_float2(vv[2], vv[3]);
        }
    }
}

__global__ void __launch_bounds__(128, 2) proj_gemm()
{
    int which = blockIdx.z;
    int epi = (which == 0) ? 1 : (which == 3) ? 2 : 0;
    gemm_body(g_buf[which], g_wr + (size_t)which * (Dz * Dz),
              g_buf[4 + which], epi);
}

__global__ void __launch_bounds__(128, 2) out_gemm(float* __restrict__ out)
{
    gemm_body(g_buf[8], g_wr + (size_t)4 * (Dz * Dz), out, 0);
}

// ---------------------------------------------------------------------------
// Pass A: chunk-local scan, zero init. grid (NC-1, NBH), 256 threads.
// 4-way i-split: thread (j = tid&63, q = tid>>6) owns state rows
// [q*16, q*16+16) of column j. k,e staged in smem (32KB); v read directly
// from global with register prefetch.
// ---------------------------------------------------------------------------
__global__ void __launch_bounds__(256) scanA_kernel()
{
    extern __shared__ __align__(16) float sm[];
    float* k_s = sm;            // [4096]
    float* e_s = sm + 4096;     // [4096]

    int tid = threadIdx.x;
    int j   = tid & 63;
    int q   = tid >> 6;         // 0..3
    int c  = blockIdx.x;
    int bh = blockIdx.y;
    int b = bh >> 4, h = bh & 15;

    int base0 = (b * Tz + c * CL) * Dz + h * 64;

    #pragma unroll
    for (int it = 0; it < 4; it++) {
        int f  = it * 256 + tid;
        int t  = f >> 4;
        int i4 = (f & 15) << 2;
        int ga = base0 + t * Dz + i4;
        int sa = t * 64 + i4;
        *(float4*)&k_s[sa] = *(const float4*)&g_buf[5][ga];
        *(float4*)&e_s[sa] = *(const float4*)&g_buf[7][ga];
    }
    __syncthreads();

    float s[16];
    #pragma unroll
    for (int i = 0; i < 16; i++) s[i] = 0.f;

    const float* __restrict__ gv = g_buf[6];
    float vj = gv[base0 + j];
    for (int t = 0; t < CL; t++) {
        float vn = 0.f;
        if (t + 1 < CL) vn = gv[base0 + (t + 1) * Dz + j];
        const float4* kp = (const float4*)&k_s[t * 64 + q * 16];
        const float4* ep = (const float4*)&e_s[t * 64 + q * 16];
        #pragma unroll
        for (int qq = 0; qq < 4; qq++) {
            float4 kv = kp[qq], ev = ep[qq];
            s[qq * 4 + 0] = ev.x * s[qq * 4 + 0] + kv.x * vj;
            s[qq * 4 + 1] = ev.y * s[qq * 4 + 1] + kv.y * vj;
            s[qq * 4 + 2] = ev.z * s[qq * 4 + 2] + kv.z * vj;
            s[qq * 4 + 3] = ev.w * s[qq * 4 + 3] + kv.w * vj;
        }
        vj = vn;
    }

    int slot = (bh * NC + c) * DHz;
    #pragma unroll 8
    for (int ii = 0; ii < 16; ii++)
        g_state[(size_t)(slot + q * 16 + ii) * DHz + j] = s[ii];

    if (q == 0) {
        float w0 = 1.f, w1 = 1.f, w2 = 1.f, w3 = 1.f;
        #pragma unroll
        for (int t = 0; t < CL; t += 4) {
            w0 *= e_s[(t + 0) * 64 + j];
            w1 *= e_s[(t + 1) * 64 + j];
            w2 *= e_s[(t + 2) * 64 + j];
            w3 *= e_s[(t + 3) * 64 + j];
        }
        g_wprod[slot + j] = (w0 * w1) * (w2 * w3);
    }
}

// ---------------------------------------------------------------------------
// Pass B: sequential prefix over chunks. grid NBH, 256 threads.
// ---------------------------------------------------------------------------
__global__ void __launch_bounds__(256) scanB_kernel()
{
    __shared__ float s_w[64];
    int tid = threadIdx.x;
    int j   = tid & 63;
    int q   = tid >> 6;
    int bh = blockIdx.x;

    float R[16];
    #pragma unroll
    for (int i = 0; i < 16; i++) R[i] = 0.f;

    for (int c = 0; c < NC; c++) {
        int slot = (bh * NC + c) * DHz;
        if (c < NC - 1) {
            if (tid < 64) s_w[tid] = g_wprod[slot + tid];
            __syncthreads();
            #pragma unroll 8
            for (int ii = 0; ii < 16; ii++) {
                int i = q * 16 + ii;
                size_t a = (size_t)(slot + i) * DHz + j;
                float local = g_state[a];
                g_state[a] = R[ii];
                R[ii] = s_w[i] * R[ii] + local;
            }
            __syncthreads();
        } else {
            #pragma unroll 8
            for (int ii = 0; ii < 16; ii++)
                g_state[(size_t)(slot + q * 16 + ii) * DHz + j] = R[ii];
        }
    }
}

// ---------------------------------------------------------------------------
// Pass C (FUSED, barrier-free combine): scan outputs + bonus + groupnorm +
// r-mult + tf32 k-permute. grid (NC, NBH), 128 threads.
// ---------------------------------------------------------------------------
#define SCM_FLOATS 24704

__global__ void __launch_bounds__(128) scanC_kernel(
    const float* __restrict__ u,
    const float* __restrict__ ln_w, const float* __restrict__ ln_b)
{
    extern __shared__ __align__(16) float sm[];
    float* k_s  = sm;
    float* e_s  = sm + 4096;
    float* v_s  = sm + 8192;
    float* r_s  = sm + 12288;
    float* op   = sm + 16384;
    float* lnw_s = sm + 24576;
    float* lnb_s = sm + 24640;

    int tid  = threadIdx.x;
    int lane = tid & 31;
    int wid  = tid >> 5;
    int j    = tid & 63;
    int half = tid >> 6;
    int c  = blockIdx.x;
    int bh = blockIdx.y;
    int b = bh >> 4, h = bh & 15;

    int base0 = (b * Tz + c * CL) * Dz + h * 64;

    #pragma unroll
    for (int it = 0; it < 8; it++) {
        int f  = it * 128 + tid;
        int t  = f >> 4;
        int i4 = (f & 15) << 2;
        int ga = base0 + t * Dz + i4;
        int sa = t * 64 + i4;
        *(float4*)&k_s[sa] = *(const float4*)&g_buf[5][ga];
        *(float4*)&e_s[sa] = *(const float4*)&g_buf[7][ga];
        *(float4*)&v_s[sa] = *(const float4*)&g_buf[6][ga];
        *(float4*)&r_s[sa] = *(const float4*)&g_buf[4][ga];
    }
    if (tid < 64) { lnw_s[tid] = ln_w[tid]; lnb_s[tid] = ln_b[tid]; }

    float s[32];
    {
        int slot = (bh * NC + c) * DHz;
        #pragma unroll 8
        for (int ii = 0; ii < 32; ii++)
            s[ii] = g_state[(size_t)(slot + half * 32 + ii) * DHz + j];
    }
    __syncthreads();

    // ---- scan: partial o per (t, j, half) ----
    float* myop = op + half * 4096;
    for (int t = 0; t < CL; t++) {
        float vj = v_s[t * 64 + j];
        const float4* rp = (const float4*)&r_s[t * 64 + half * 32];
        const float4* kp = (const float4*)&k_s[t * 64 + half * 32];
        const float4* ep = (const float4*)&e_s[t * 64 + half * 32];
        float o0 = 0.f, o1 = 0.f, o2 = 0.f, o3 = 0.f;
        #pragma unroll
        for (int q = 0; q < 8; q++) {
            float4 rv = rp[q], kv = kp[q], ev = ep[q];
            o0 += rv.x * s[q * 4 + 0]; s[q * 4 + 0] = ev.x * s[q * 4 + 0] + kv.x * vj;
            o1 += rv.y * s[q * 4 + 1]; s[q * 4 + 1] = ev.y * s[q * 4 + 1] + kv.y * vj;
            o2 += rv.z * s[q * 4 + 2]; s[q * 4 + 2] = ev.z * s[q * 4 + 2] + kv.z * vj;
            o3 += rv.w * s[q * 4 + 3]; s[q * 4 + 3] = ev.w * s[q * 4 + 3] + kv.w * vj;
        }
        myop[t * 64 + j] = ((o0 + o1) + (o2 + o3));
    }
    __syncthreads();

    // ---- combine (barrier-free): warp w handles t = 4*it + w ----
    float* __restrict__ go = g_buf[8];
    float u0 = u[h * 64 + lane];
    float u1 = u[h * 64 + 32 + lane];
    float lw0 = lnw_s[lane],      lb0 = lnb_s[lane];
    float lw1 = lnw_s[lane + 32], lb1 = lnb_s[lane + 32];
    int pj0 = ((lane >> 3) << 3)
            + (((lane & 7) < 4) ? 2 * (lane & 3) : 2 * (lane & 3) + 1);
    int pj1 = pj0 + 32;

    #pragma unroll 4
    for (int it = 0; it < 16; it++) {
        int t = it * 4 + wid;
        int tb = t * 64;
        float r0 = r_s[tb + lane], r1 = r_s[tb + 32 + lane];
        float v0 = v_s[tb + lane], v1 = v_s[tb + 32 + lane];

        float term = r0 * __expf(u0 + k_s[tb + lane])
                   + r1 * __expf(u1 + k_s[tb + 32 + lane]);
        #pragma unroll
        for (int off = 16; off > 0; off >>= 1)
            term += __shfl_xor_sync(0xffffffffu, term, off);

        float o0 = op[tb + lane]      + op[4096 + tb + lane]      + term * v0;
        float o1 = op[tb + 32 + lane] + op[4096 + tb + 32 + lane] + term * v1;

        float ssum = o0 + o1;
        float ssq  = o0 * o0 + o1 * o1;
        #pragma unroll
        for (int off = 16; off > 0; off >>= 1) {
            ssum += __shfl_xor_sync(0xffffffffu, ssum, off);
            ssq  += __shfl_xor_sync(0xffffffffu, ssq,  off);
        }
        float mean = ssum * (1.f / 64.f);
        float var  = ssq * (1.f / 64.f) - mean * mean;
        float rsd  = rsqrtf(var + 1e-5f);

        float n0 = to_tf32(((o0 - mean) * rsd * lw0 + lb0) * r0);
        float n1 = to_tf32(((o1 - mean) * rsd * lw1 + lb1) * r1);
        go[base0 + t * Dz + pj0] = n0;
        go[base0 + t * Dz + pj1] = n1;
    }
}

// ---------------------------------------------------------------------------
extern "C" void kernel_launch(void* const* d_in, const int* in_sizes, int n_in,
                              void* d_out, int out_size)
{
    const float* x    = (const float*)d_in[0];
    const float* W_r  = (const float*)d_in[1];
    const float* W_k  = (const float*)d_in[2];
    const float* W_v  = (const float*)d_in[3];
    const float* W_w  = (const float*)d_in[4];
    const float* W_o  = (const float*)d_in[5];
    const float* u    = (const float*)d_in[6];
    const float* tm_r = (const float*)d_in[7];
    const float* tm_k = (const float*)d_in[8];
    const float* tm_v = (const float*)d_in[9];
    const float* tm_w = (const float*)d_in[10];
    const float* ln_w = (const float*)d_in[11];
    const float* ln_b = (const float*)d_in[12];
    float* out = (float*)d_out;

    cudaFuncSetAttribute(scanA_kernel,
        cudaFuncAttributeMaxDynamicSharedMemorySize, 8192 * 4);
    cudaFuncSetAttribute(scanC_kernel,
        cudaFuncAttributeMaxDynamicSharedMemorySize, SCM_FLOATS * 4);
    cudaFuncSetAttribute(proj_gemm,
        cudaFuncAttributeMaxDynamicSharedMemorySize, GSMB);
    cudaFuncSetAttribute(out_gemm,
        cudaFuncAttributeMaxDynamicSharedMemorySize, GSMB);

    roundw_kernel<<<2560, 256>>>(
        (const float4*)W_r, (const float4*)W_k, (const float4*)W_v,
        (const float4*)W_w, (const float4*)W_o);

    mix_kernel<<<2048, 256>>>(
        (const float4*)x, (const float4*)tm_r, (const float4*)tm_k,
        (const float4*)tm_v, (const float4*)tm_w);

    proj_gemm<<<dim3(Nz / 128, Mz / 128, 4), 128, GSMB>>>();

    scanA_kernel<<<dim3(NC - 1, NBH), 256, 8192 * 4>>>();
    scanB_kernel<<<NBH, 256>>>();
    scanC_kernel<<<dim3(NC, NBH), 128, SCM_FLOATS * 4>>>(u, ln_w, ln_b);

    out_gemm<<<dim3(Nz / 128, Mz / 128), 128, GSMB>>>(out);
}

// round 13
// speedup vs baseline: 1.1439x; 1.0556x over previous
#include <cuda_runtime.h>
#include <cstdint>

#define Bz 4
#define Tz 1024
#define Dz 1024
#define Hz 16
#define DHz 64
#define Mz (Bz*Tz)        // 4096
#define Kz Dz
#define Nz Dz
#define MD (Mz*Dz)        // 4,194,304
#define NBH (Bz*Hz)       // 64
#define CL 64             // chunk length
#define NC (Tz/CL)        // 16 chunks

// 0..3 = xr,xk,xv,xw (tf32, k-permuted) ; 4=r ; 5=k ; 6=v ; 7=exp(w) (normal)
// 8=o (k-permuted tf32, written by fused scanC)
__device__ float g_buf[9][MD];
__device__ float g_wr[5 * Dz * Dz];               // tf32 k-permuted weights
__device__ float g_state[NBH * NC * DHz * DHz];   // chunk states
__device__ float g_wprod[NBH * NC * DHz];         // per-chunk decay products

__device__ __forceinline__ float to_tf32(float x)
{
    uint32_t d;
    asm("cvt.rna.tf32.f32 %0, %1;" : "=r"(d) : "f"(x));
    return __uint_as_float(d);
}
__device__ __forceinline__ uint32_t smem_to_u32(const void* p) {
    uint32_t a;
    asm("{ .reg .u64 t; cvta.to.shared.u64 t, %1; cvt.u32.u64 %0, t; }"
        : "=r"(a) : "l"(p));
    return a;
}
__device__ __forceinline__ void cp16(uint32_t dst, const void* src) {
    asm volatile("cp.async.cg.shared.global [%0], [%1], 16;"
                 :: "r"(dst), "l"(src));
}
__device__ __forceinline__ void cp_commit() {
    asm volatile("cp.async.commit_group;" ::: "memory");
}
__device__ __forceinline__ void mma_tf32(float c[4], const uint32_t a[4],
                                         const uint32_t b[2])
{
    asm volatile(
        "mma.sync.aligned.m16n8k8.row.col.f32.tf32.tf32.f32 "
        "{%0,%1,%2,%3}, {%4,%5,%6,%7}, {%8,%9}, {%0,%1,%2,%3};"
        : "+f"(c[0]), "+f"(c[1]), "+f"(c[2]), "+f"(c[3])
        : "r"(a[0]), "r"(a[1]), "r"(a[2]), "r"(a[3]),
          "r"(b[0]), "r"(b[1]));
}

// permute helper: 8 floats (a=k0..3, b=k4..7) -> [k0,k4,k1,k5] and [k2,k6,k3,k7]
__device__ __forceinline__ void perm_pair(const float4& a, const float4& b,
                                          float4& o0, float4& o1)
{
    o0 = make_float4(a.x, b.x, a.y, b.y);
    o1 = make_float4(a.z, b.z, a.w, b.w);
}

// ---------------------------------------------------------------------------
// round 5 weight matrices to tf32, k-permuted, into g_wr
// ---------------------------------------------------------------------------
__global__ void __launch_bounds__(256) roundw_kernel(
    const float4* __restrict__ a, const float4* __restrict__ b,
    const float4* __restrict__ c, const float4* __restrict__ d,
    const float4* __restrict__ e)
{
    int idx = blockIdx.x * 256 + threadIdx.x;      // 0..655359
    int which = idx >> 17;
    int off = idx & 131071;
    const float4* src = which == 0 ? a : which == 1 ? b : which == 2 ? c
                       : which == 3 ? d : e;
    float4 v0 = src[2 * off], v1 = src[2 * off + 1];
    v0.x = to_tf32(v0.x); v0.y = to_tf32(v0.y); v0.z = to_tf32(v0.z); v0.w = to_tf32(v0.w);
    v1.x = to_tf32(v1.x); v1.y = to_tf32(v1.y); v1.z = to_tf32(v1.z); v1.w = to_tf32(v1.w);
    float4 o0, o1;
    perm_pair(v0, v1, o0, o1);
    float4* dst = reinterpret_cast<float4*>(g_wr) + (size_t)which * 262144;
    dst[2 * off] = o0;
    dst[2 * off + 1] = o1;
}

// ---------------------------------------------------------------------------
// token-shift mix, tf32-rounded + k-permuted
// ---------------------------------------------------------------------------
__global__ void __launch_bounds__(256) mix_kernel(
    const float4* __restrict__ x,
    const float4* __restrict__ tmr, const float4* __restrict__ tmk,
    const float4* __restrict__ tmv, const float4* __restrict__ tmw)
{
    int idx = blockIdx.x * 256 + threadIdx.x;   // MD/8
    int m  = idx >> 7;
    int gg = idx & 127;
    int t  = m & (Tz - 1);

    float4 x0 = x[(m << 8) + 2 * gg];
    float4 x1 = x[(m << 8) + 2 * gg + 1];
    float4 p0 = make_float4(0.f, 0.f, 0.f, 0.f), p1 = p0;
    if (t != 0) {
        p0 = x[((m - 1) << 8) + 2 * gg];
        p1 = x[((m - 1) << 8) + 2 * gg + 1];
    }

    #define DO_MIX(TMV, DSTI)                                               \
    {                                                                       \
        float4 w0 = TMV[2 * gg], w1 = TMV[2 * gg + 1];                      \
        float4 a, b;                                                        \
        a.x = to_tf32(w0.x * x0.x + (1.f - w0.x) * p0.x);                   \
        a.y = to_tf32(w0.y * x0.y + (1.f - w0.y) * p0.y);                   \
        a.z = to_tf32(w0.z * x0.z + (1.f - w0.z) * p0.z);                   \
        a.w = to_tf32(w0.w * x0.w + (1.f - w0.w) * p0.w);                   \
        b.x = to_tf32(w1.x * x1.x + (1.f - w1.x) * p1.x);                   \
        b.y = to_tf32(w1.y * x1.y + (1.f - w1.y) * p1.y);                   \
        b.z = to_tf32(w1.z * x1.z + (1.f - w1.z) * p1.z);                   \
        b.w = to_tf32(w1.w * x1.w + (1.f - w1.w) * p1.w);                   \
        float4 o0, o1;                                                      \
        perm_pair(a, b, o0, o1);                                            \
        reinterpret_cast<float4*>(g_buf[DSTI])[2 * idx]     = o0;           \
        reinterpret_cast<float4*>(g_buf[DSTI])[2 * idx + 1] = o1;           \
    }
    DO_MIX(tmr, 0)
    DO_MIX(tmk, 1)
    DO_MIX(tmv, 2)
    DO_MIX(tmw, 3)
    #undef DO_MIX
}

// ---------------------------------------------------------------------------
// tf32 mma.sync GEMM on k-permuted operands.
// CTA tile 128x128, BK=32, 8 warps (2m x 4n), warp tile 64x32.
// 3-stage cp.async pipeline, swizzled pad-free smem, LDS.64 fragment loads,
// 2 CTAs/SM.
// ---------------------------------------------------------------------------
#define TB 4096
#define GSMB (3 * 2 * TB * 4)                 // 98304 bytes

__device__ __forceinline__ void gemm_body(
    const float* __restrict__ A,
    const float* __restrict__ W,
    float* __restrict__ C, int epi)
{
    extern __shared__ __align__(16) float sm[];
    float* As = sm;                  // [3][TB]
    float* Bs = sm + 3 * TB;
    uint32_t a32 = smem_to_u32(As);
    uint32_t b32 = smem_to_u32(Bs);

    int tid  = threadIdx.x;          // 0..255
    int lane = tid & 31;
    int wid  = tid >> 5;             // 0..7
    int bm = blockIdx.y * 128;
    int bn = blockIdx.x * 128;

    int wm = (wid >> 2) * 64;        // 0 / 64
    int wn = (wid & 3) * 32;         // 0/32/64/96
    int frow = lane >> 2;
    int fk   = lane & 3;

    float acc[4][4][4];
    #pragma unroll
    for (int i = 0; i < 4; i++)
        #pragma unroll
        for (int j = 0; j < 4; j++)
            #pragma unroll
            for (int r = 0; r < 4; r++) acc[i][j][r] = 0.f;

    // stage: 128 rows x 8 granules(16B) per matrix; 256 threads -> 4 iters
    #define GSTAGE(CC, BUF)                                                  \
    {                                                                        \
        const char* ap = (const char*)(A + (size_t)bm * Kz + (CC) * 32);     \
        const char* bp = (const char*)(W + (size_t)bn * Kz + (CC) * 32);     \
        _Pragma("unroll")                                                    \
        for (int i = 0; i < 4; i++) {                                        \
            int lin = i * 256 + tid;                                         \
            int r = lin >> 3;                                                \
            int g = lin & 7;                                                 \
            int slot = (g + 2 * (r & 3)) & 7;                                \
            cp16(a32 + (BUF) * (TB * 4) + r * 128 + slot * 16,               \
                 ap + (size_t)r * (Kz * 4) + g * 16);                        \
            cp16(b32 + (BUF) * (TB * 4) + r * 128 + slot * 16,               \
                 bp + (size_t)r * (Kz * 4) + g * 16);                        \
        }                                                                    \
    }

    GSTAGE(0, 0) cp_commit();
    GSTAGE(1, 1) cp_commit();

    const int NIT = Kz >> 5;         // 32
    int buf = 0;
    for (int c = 0; c < NIT; c++) {
        asm volatile("cp.async.wait_group 1;" ::: "memory");
        __syncthreads();
        if (c + 2 < NIT) {
            int nb = (c + 2) % 3;
            if (nb == 0)      { GSTAGE(c + 2, 0) }
            else if (nb == 1) { GSTAGE(c + 2, 1) }
            else              { GSTAGE(c + 2, 2) }
        }
        cp_commit();

        const float* a_s = As + buf * TB;
        const float* b_s = Bs + buf * TB;
        #pragma unroll
        for (int ks = 0; ks < 4; ks++) {
            uint32_t afr[4][4], bfr[4][2];
            int slot = (2 * ks + (fk >> 1) + 2 * (frow & 3)) & 7;
            int fo = slot * 4 + (fk & 1) * 2;
            #pragma unroll
            for (int mt = 0; mt < 4; mt++) {
                int rr = wm + mt * 16 + frow;
                float2 u = *(const float2*)&a_s[rr * 32 + fo];
                float2 v = *(const float2*)&a_s[(rr + 8) * 32 + fo];
                afr[mt][0] = __float_as_uint(u.x);
                afr[mt][1] = __float_as_uint(v.x);
                afr[mt][2] = __float_as_uint(u.y);
                afr[mt][3] = __float_as_uint(v.y);
            }
            #pragma unroll
            for (int nt = 0; nt < 4; nt++) {
                int rn = wn + nt * 8 + frow;
                float2 w2 = *(const float2*)&b_s[rn * 32 + fo];
                bfr[nt][0] = __float_as_uint(w2.x);
                bfr[nt][1] = __float_as_uint(w2.y);
            }
            #pragma unroll
            for (int mt = 0; mt < 4; mt++)
                #pragma unroll
                for (int nt = 0; nt < 4; nt++)
                    mma_tf32(acc[mt][nt], afr[mt], bfr[nt]);
        }
        buf = (buf + 1) == 3 ? 0 : buf + 1;
    }
    #undef GSTAGE

    #pragma unroll
    for (int mt = 0; mt < 4; mt++) {
        int row = bm + wm + mt * 16 + frow;
        #pragma unroll
        for (int nt = 0; nt < 4; nt++) {
            int col = bn + wn + nt * 8 + fk * 2;
            float vv[4];
            #pragma unroll
            for (int r = 0; r < 4; r++) {
                float v = acc[mt][nt][r];
                if (epi == 1)      v = 1.f / (1.f + __expf(-v));
                else if (epi == 2) v = 0.999900004999833f / (1.f + __expf(-v));
                vv[r] = v;
            }
            *(float2*)&C[(size_t)row * Nz + col]       = make_float2(vv[0], vv[1]);
            *(float2*)&C[(size_t)(row + 8) * Nz + col] = make_float2(vv[2], vv[3]);
        }
    }
}

__global__ void __launch_bounds__(256, 2) proj_gemm()
{
    int which = blockIdx.z;
    int epi = (which == 0) ? 1 : (which == 3) ? 2 : 0;
    gemm_body(g_buf[which], g_wr + (size_t)which * (Dz * Dz),
              g_buf[4 + which], epi);
}

__global__ void __launch_bounds__(256, 2) out_gemm(float* __restrict__ out)
{
    gemm_body(g_buf[8], g_wr + (size_t)4 * (Dz * Dz), out, 0);
}

// ---------------------------------------------------------------------------
// Pass A: chunk-local scan, zero init. grid (NC-1, NBH), 128 threads.
// (round-11 config: 2-way i-split, k/e/v staged in smem, measured 51us)
// ---------------------------------------------------------------------------
__global__ void __launch_bounds__(128) scanA_kernel()
{
    extern __shared__ __align__(16) float sm[];
    float* k_s = sm;
    float* e_s = sm + 4096;
    float* v_s = sm + 8192;

    int tid  = threadIdx.x;
    int j    = tid & 63;
    int half = tid >> 6;
    int c  = blockIdx.x;
    int bh = blockIdx.y;
    int b = bh >> 4, h = bh & 15;

    int base0 = (b * Tz + c * CL) * Dz + h * 64;

    #pragma unroll
    for (int it = 0; it < 8; it++) {
        int f  = it * 128 + tid;
        int t  = f >> 4;
        int i4 = (f & 15) << 2;
        int ga = base0 + t * Dz + i4;
        int sa = t * 64 + i4;
        *(float4*)&k_s[sa] = *(const float4*)&g_buf[5][ga];
        *(float4*)&e_s[sa] = *(const float4*)&g_buf[7][ga];
        *(float4*)&v_s[sa] = *(const float4*)&g_buf[6][ga];
    }
    __syncthreads();

    float s[32];
    #pragma unroll
    for (int i = 0; i < 32; i++) s[i] = 0.f;

    for (int t = 0; t < CL; t++) {
        float vj = v_s[t * 64 + j];
        const float4* kp = (const float4*)&k_s[t * 64 + half * 32];
        const float4* ep = (const float4*)&e_s[t * 64 + half * 32];
        #pragma unroll
        for (int q = 0; q < 8; q++) {
            float4 kv = kp[q], ev = ep[q];
            s[q * 4 + 0] = ev.x * s[q * 4 + 0] + kv.x * vj;
            s[q * 4 + 1] = ev.y * s[q * 4 + 1] + kv.y * vj;
            s[q * 4 + 2] = ev.z * s[q * 4 + 2] + kv.z * vj;
            s[q * 4 + 3] = ev.w * s[q * 4 + 3] + kv.w * vj;
        }
    }

    int slot = (bh * NC + c) * DHz;
    #pragma unroll 8
    for (int ii = 0; ii < 32; ii++)
        g_state[(size_t)(slot + half * 32 + ii) * DHz + j] = s[ii];

    if (half == 0) {
        float w0 = 1.f, w1 = 1.f, w2 = 1.f, w3 = 1.f;
        #pragma unroll
        for (int t = 0; t < CL; t += 4) {
            w0 *= e_s[(t + 0) * 64 + j];
            w1 *= e_s[(t + 1) * 64 + j];
            w2 *= e_s[(t + 2) * 64 + j];
            w3 *= e_s[(t + 3) * 64 + j];
        }
        g_wprod[slot + j] = (w0 * w1) * (w2 * w3);
    }
}

// ---------------------------------------------------------------------------
// Pass B: sequential prefix over chunks. grid NBH, 256 threads.
// ---------------------------------------------------------------------------
__global__ void __launch_bounds__(256) scanB_kernel()
{
    __shared__ float s_w[64];
    int tid = threadIdx.x;
    int j   = tid & 63;
    int q   = tid >> 6;
    int bh = blockIdx.x;

    float R[16];
    #pragma unroll
    for (int i = 0; i < 16; i++) R[i] = 0.f;

    for (int c = 0; c < NC; c++) {
        int slot = (bh * NC + c) * DHz;
        if (c < NC - 1) {
            if (tid < 64) s_w[tid] = g_wprod[slot + tid];
            __syncthreads();
            #pragma unroll 8
            for (int ii = 0; ii < 16; ii++) {
                int i = q * 16 + ii;
                size_t a = (size_t)(slot + i) * DHz + j;
                float local = g_state[a];
                g_state[a] = R[ii];
                R[ii] = s_w[i] * R[ii] + local;
            }
            __syncthreads();
        } else {
            #pragma unroll 8
            for (int ii = 0; ii < 16; ii++)
                g_state[(size_t)(slot + q * 16 + ii) * DHz + j] = R[ii];
        }
    }
}

// ---------------------------------------------------------------------------
// Pass C (FUSED, barrier-free combine): scan outputs + bonus + groupnorm +
// r-mult + tf32 k-permute. grid (NC, NBH), 128 threads.
// ---------------------------------------------------------------------------
#define SCM_FLOATS 24704

__global__ void __launch_bounds__(128) scanC_kernel(
    const float* __restrict__ u,
    const float* __restrict__ ln_w, const float* __restrict__ ln_b)
{
    extern __shared__ __align__(16) float sm[];
    float* k_s  = sm;
    float* e_s  = sm + 4096;
    float* v_s  = sm + 8192;
    float* r_s  = sm + 12288;
    float* op   = sm + 16384;
    float* lnw_s = sm + 24576;
    float* lnb_s = sm + 24640;

    int tid  = threadIdx.x;
    int lane = tid & 31;
    int wid  = tid >> 5;
    int j    = tid & 63;
    int half = tid >> 6;
    int c  = blockIdx.x;
    int bh = blockIdx.y;
    int b = bh >> 4, h = bh & 15;

    int base0 = (b * Tz + c * CL) * Dz + h * 64;

    #pragma unroll
    for (int it = 0; it < 8; it++) {
        int f  = it * 128 + tid;
        int t  = f >> 4;
        int i4 = (f & 15) << 2;
        int ga = base0 + t * Dz + i4;
        int sa = t * 64 + i4;
        *(float4*)&k_s[sa] = *(const float4*)&g_buf[5][ga];
        *(float4*)&e_s[sa] = *(const float4*)&g_buf[7][ga];
        *(float4*)&v_s[sa] = *(const float4*)&g_buf[6][ga];
        *(float4*)&r_s[sa] = *(const float4*)&g_buf[4][ga];
    }
    if (tid < 64) { lnw_s[tid] = ln_w[tid]; lnb_s[tid] = ln_b[tid]; }

    float s[32];
    {
        int slot = (bh * NC + c) * DHz;
        #pragma unroll 8
        for (int ii = 0; ii < 32; ii++)
            s[ii] = g_state[(size_t)(slot + half * 32 + ii) * DHz + j];
    }
    __syncthreads();

    // ---- scan: partial o per (t, j, half) ----
    float* myop = op + half * 4096;
    for (int t = 0; t < CL; t++) {
        float vj = v_s[t * 64 + j];
        const float4* rp = (const float4*)&r_s[t * 64 + half * 32];
        const float4* kp = (const float4*)&k_s[t * 64 + half * 32];
        const float4* ep = (const float4*)&e_s[t * 64 + half * 32];
        float o0 = 0.f, o1 = 0.f, o2 = 0.f, o3 = 0.f;
        #pragma unroll
        for (int q = 0; q < 8; q++) {
            float4 rv = rp[q], kv = kp[q], ev = ep[q];
            o0 += rv.x * s[q * 4 + 0]; s[q * 4 + 0] = ev.x * s[q * 4 + 0] + kv.x * vj;
            o1 += rv.y * s[q * 4 + 1]; s[q * 4 + 1] = ev.y * s[q * 4 + 1] + kv.y * vj;
            o2 += rv.z * s[q * 4 + 2]; s[q * 4 + 2] = ev.z * s[q * 4 + 2] + kv.z * vj;
            o3 += rv.w * s[q * 4 + 3]; s[q * 4 + 3] = ev.w * s[q * 4 + 3] + kv.w * vj;
        }
        myop[t * 64 + j] = ((o0 + o1) + (o2 + o3));
    }
    __syncthreads();

    // ---- combine (barrier-free): warp w handles t = 4*it + w ----
    float* __restrict__ go = g_buf[8];
    float u0 = u[h * 64 + lane];
    float u1 = u[h * 64 + 32 + lane];
    float lw0 = lnw_s[lane],      lb0 = lnb_s[lane];
    float lw1 = lnw_s[lane + 32], lb1 = lnb_s[lane + 32];
    int pj0 = ((lane >> 3) << 3)
            + (((lane & 7) < 4) ? 2 * (lane & 3) : 2 * (lane & 3) + 1);
    int pj1 = pj0 + 32;

    #pragma unroll 4
    for (int it = 0; it < 16; it++) {
        int t = it * 4 + wid;
        int tb = t * 64;
        float r0 = r_s[tb + lane], r1 = r_s[tb + 32 + lane];
        float v0 = v_s[tb + lane], v1 = v_s[tb + 32 + lane];

        float term = r0 * __expf(u0 + k_s[tb + lane])
                   + r1 * __expf(u1 + k_s[tb + 32 + lane]);
        #pragma unroll
        for (int off = 16; off > 0; off >>= 1)
            term += __shfl_xor_sync(0xffffffffu, term, off);

        float o0 = op[tb + lane]      + op[4096 + tb + lane]      + term * v0;
        float o1 = op[tb + 32 + lane] + op[4096 + tb + 32 + lane] + term * v1;

        float ssum = o0 + o1;
        float ssq  = o0 * o0 + o1 * o1;
        #pragma unroll
        for (int off = 16; off > 0; off >>= 1) {
            ssum += __shfl_xor_sync(0xffffffffu, ssum, off);
            ssq  += __shfl_xor_sync(0xffffffffu, ssq,  off);
        }
        float mean = ssum * (1.f / 64.f);
        float var  = ssq * (1.f / 64.f) - mean * mean;
        float rsd  = rsqrtf(var + 1e-5f);

        float n0 = to_tf32(((o0 - mean) * rsd * lw0 + lb0) * r0);
        float n1 = to_tf32(((o1 - mean) * rsd * lw1 + lb1) * r1);
        go[base0 + t * Dz + pj0] = n0;
        go[base0 + t * Dz + pj1] = n1;
    }
}

// ---------------------------------------------------------------------------
extern "C" void kernel_launch(void* const* d_in, const int* in_sizes, int n_in,
                              void* d_out, int out_size)
{
    const float* x    = (const float*)d_in[0];
    const float* W_r  = (const float*)d_in[1];
    const float* W_k  = (const float*)d_in[2];
    const float* W_v  = (const float*)d_in[3];
    const float* W_w  = (const float*)d_in[4];
    const float* W_o  = (const float*)d_in[5];
    const float* u    = (const float*)d_in[6];
    const float* tm_r = (const float*)d_in[7];
    const float* tm_k = (const float*)d_in[8];
    const float* tm_v = (const float*)d_in[9];
    const float* tm_w = (const float*)d_in[10];
    const float* ln_w = (const float*)d_in[11];
    const float* ln_b = (const float*)d_in[12];
    float* out = (float*)d_out;

    cudaFuncSetAttribute(scanA_kernel,
        cudaFuncAttributeMaxDynamicSharedMemorySize, 12288 * 4);
    cudaFuncSetAttribute(scanC_kernel,
        cudaFuncAttributeMaxDynamicSharedMemorySize, SCM_FLOATS * 4);
    cudaFuncSetAttribute(proj_gemm,
        cudaFuncAttributeMaxDynamicSharedMemorySize, GSMB);
    cudaFuncSetAttribute(out_gemm,
        cudaFuncAttributeMaxDynamicSharedMemorySize, GSMB);

    roundw_kernel<<<2560, 256>>>(
        (const float4*)W_r, (const float4*)W_k, (const float4*)W_v,
        (const float4*)W_w, (const float4*)W_o);

    mix_kernel<<<2048, 256>>>(
        (const float4*)x, (const float4*)tm_r, (const float4*)tm_k,
        (const float4*)tm_v, (const float4*)tm_w);

    proj_gemm<<<dim3(Nz / 128, Mz / 128, 4), 256, GSMB>>>();

    scanA_kernel<<<dim3(NC - 1, NBH), 128, 12288 * 4>>>();
    scanB_kernel<<<NBH, 256>>>();
    scanC_kernel<<<dim3(NC, NBH), 128, SCM_FLOATS * 4>>>(u, ln_w, ln_b);

    out_gemm<<<dim3(Nz / 128, Mz / 128), 256, GSMB>>>(out);
}

// round 14
// speedup vs baseline: 1.5090x; 1.3192x over previous
#include <cuda_runtime.h>
#include <cuda_fp16.h>
#include <cstdint>

#define Bz 4
#define Tz 1024
#define Dz 1024
#define Hz 16
#define DHz 64
#define Mz (Bz*Tz)        // 4096
#define Kz Dz
#define Nz Dz
#define MD (Mz*Dz)        // 4,194,304
#define NBH (Bz*Hz)       // 64
#define CL 64             // chunk length
#define NC (Tz/CL)        // 16 chunks

// fp32 scan operands: 0=r, 1=k, 2=v, 3=e (written by proj GEMM epilogue)
__device__ float g_buf[4][MD];
// fp16 GEMM operands (k-word-permuted)
__device__ __half g_hA[4][MD];            // mix outputs
__device__ __half g_hW[5 * Dz * Dz];      // weights
__device__ __half g_hO[MD];               // gnorm output
__device__ float g_state[NBH * NC * DHz * DHz];
__device__ float g_wprod[NBH * NC * DHz];

__device__ __forceinline__ uint32_t f2h2(float a, float b)
{
    __half2 h = __floats2half2_rn(a, b);
    return *reinterpret_cast<uint32_t*>(&h);
}
__device__ __forceinline__ uint32_t smem_to_u32(const void* p) {
    uint32_t a;
    asm("{ .reg .u64 t; cvta.to.shared.u64 t, %1; cvt.u32.u64 %0, t; }"
        : "=r"(a) : "l"(p));
    return a;
}
__device__ __forceinline__ void cp16(uint32_t dst, const void* src) {
    asm volatile("cp.async.cg.shared.global [%0], [%1], 16;"
                 :: "r"(dst), "l"(src));
}
__device__ __forceinline__ void cp_commit() {
    asm volatile("cp.async.commit_group;" ::: "memory");
}
__device__ __forceinline__ void mma_f16(float c[4], const uint32_t a[4],
                                        const uint32_t b[2])
{
    asm volatile(
        "mma.sync.aligned.m16n8k16.row.col.f32.f16.f16.f32 "
        "{%0,%1,%2,%3}, {%4,%5,%6,%7}, {%8,%9}, {%0,%1,%2,%3};"
        : "+f"(c[0]), "+f"(c[1]), "+f"(c[2]), "+f"(c[3])
        : "r"(a[0]), "r"(a[1]), "r"(a[2]), "r"(a[3]),
          "r"(b[0]), "r"(b[1]));
}

// pack 16 floats -> 8 half2 words, permuted [0,4,1,5] [2,6,3,7]
__device__ __forceinline__ void pack_perm16(const float* f, uint4& o0, uint4& o1)
{
    uint32_t w[8];
    #pragma unroll
    for (int i = 0; i < 8; i++) w[i] = f2h2(f[2 * i], f[2 * i + 1]);
    o0 = make_uint4(w[0], w[4], w[1], w[5]);
    o1 = make_uint4(w[2], w[6], w[3], w[7]);
}

// ---------------------------------------------------------------------------
// weights -> fp16, word-permuted. one thread per 16-half group.
// ---------------------------------------------------------------------------
__global__ void __launch_bounds__(256) roundw_kernel(
    const float4* __restrict__ a, const float4* __restrict__ b,
    const float4* __restrict__ c, const float4* __restrict__ d,
    const float4* __restrict__ e)
{
    int idx = blockIdx.x * 256 + threadIdx.x;      // 0..327679
    int which = idx >> 16;
    int off = idx & 65535;
    const float4* src = which == 0 ? a : which == 1 ? b : which == 2 ? c
                       : which == 3 ? d : e;
    float f[16];
    #pragma unroll
    for (int i = 0; i < 4; i++)
        *(float4*)&f[i * 4] = src[4 * off + i];
    uint4 o0, o1;
    pack_perm16(f, o0, o1);
    uint4* dst = reinterpret_cast<uint4*>(g_hW) + (size_t)which * 131072;
    dst[2 * off] = o0;
    dst[2 * off + 1] = o1;
}

// ---------------------------------------------------------------------------
// token-shift mix -> fp16 word-permuted. one thread per 16-half group.
// ---------------------------------------------------------------------------
__global__ void __launch_bounds__(256) mix_kernel(
    const float4* __restrict__ x,
    const float4* __restrict__ tmr, const float4* __restrict__ tmk,
    const float4* __restrict__ tmv, const float4* __restrict__ tmw)
{
    int idx = blockIdx.x * 256 + threadIdx.x;   // MD/16 = 262144
    int m  = idx >> 6;
    int gg = idx & 63;
    int t  = m & (Tz - 1);

    float xc[16], xp[16];
    #pragma unroll
    for (int i = 0; i < 4; i++)
        *(float4*)&xc[i * 4] = x[(m << 8) + gg * 4 + i];
    if (t != 0) {
        #pragma unroll
        for (int i = 0; i < 4; i++)
            *(float4*)&xp[i * 4] = x[((m - 1) << 8) + gg * 4 + i];
    } else {
        #pragma unroll
        for (int i = 0; i < 16; i++) xp[i] = 0.f;
    }

    #define DO_MIX(TMV, DSTI)                                               \
    {                                                                       \
        float tm[16], mx[16];                                               \
        _Pragma("unroll")                                                   \
        for (int i = 0; i < 4; i++)                                         \
            *(float4*)&tm[i * 4] = TMV[gg * 4 + i];                         \
        _Pragma("unroll")                                                   \
        for (int i = 0; i < 16; i++)                                        \
            mx[i] = tm[i] * xc[i] + (1.f - tm[i]) * xp[i];                  \
        uint4 o0, o1;                                                       \
        pack_perm16(mx, o0, o1);                                            \
        uint4* dst = reinterpret_cast<uint4*>(g_hA[DSTI]);                  \
        dst[2 * idx] = o0;                                                  \
        dst[2 * idx + 1] = o1;                                              \
    }
    DO_MIX(tmr, 0)
    DO_MIX(tmk, 1)
    DO_MIX(tmv, 2)
    DO_MIX(tmw, 3)
    #undef DO_MIX
}

// ---------------------------------------------------------------------------
// fp16 mma.sync GEMM on word-permuted operands.
// CTA tile 128x128, BK=64 halves (128B/row), 8 warps (2m x 4n), warp 64x32.
// 3-stage cp.async pipeline, swizzled smem, LDS.64 fragments, 2 CTAs/SM.
// C output fp32. epi: 0 id, 1 sigmoid, 2 sigmoid*e^-1e-4
// ---------------------------------------------------------------------------
#define TB 4096                               // 32-bit words per tile buffer
#define GSMB (3 * 2 * TB * 4)                 // 98304 bytes

__device__ __forceinline__ void gemm_body(
    const __half* __restrict__ A,
    const __half* __restrict__ W,
    float* __restrict__ C, int epi)
{
    extern __shared__ __align__(16) float sm[];
    float* As = sm;                  // [3][TB] words
    float* Bs = sm + 3 * TB;
    uint32_t a32 = smem_to_u32(As);
    uint32_t b32 = smem_to_u32(Bs);

    int tid  = threadIdx.x;          // 0..255
    int lane = tid & 31;
    int wid  = tid >> 5;             // 0..7
    int bm = blockIdx.y * 128;
    int bn = blockIdx.x * 128;

    int wm = (wid >> 2) * 64;
    int wn = (wid & 3) * 32;
    int frow = lane >> 2;
    int fk   = lane & 3;

    float acc[4][4][4];
    #pragma unroll
    for (int i = 0; i < 4; i++)
        #pragma unroll
        for (int j = 0; j < 4; j++)
            #pragma unroll
            for (int r = 0; r < 4; r++) acc[i][j][r] = 0.f;

    // stage: 128 rows x 128B (64 halves) per matrix per iter
    #define GSTAGE(CC, BUF)                                                  \
    {                                                                        \
        const char* ap = (const char*)(A + (size_t)bm * Kz + (CC) * 64);     \
        const char* bp = (const char*)(W + (size_t)bn * Kz + (CC) * 64);     \
        _Pragma("unroll")                                                    \
        for (int i = 0; i < 4; i++) {                                        \
            int lin = i * 256 + tid;                                         \
            int r = lin >> 3;                                                \
            int g = lin & 7;                                                 \
            int slot = (g + 2 * (r & 3)) & 7;                                \
            cp16(a32 + (BUF) * (TB * 4) + r * 128 + slot * 16,               \
                 ap + (size_t)r * (Kz * 2) + g * 16);                        \
            cp16(b32 + (BUF) * (TB * 4) + r * 128 + slot * 16,               \
                 bp + (size_t)r * (Kz * 2) + g * 16);                        \
        }                                                                    \
    }

    GSTAGE(0, 0) cp_commit();
    GSTAGE(1, 1) cp_commit();

    const int NIT = Kz >> 6;         // 16
    int buf = 0;
    for (int c = 0; c < NIT; c++) {
        asm volatile("cp.async.wait_group 1;" ::: "memory");
        __syncthreads();
        if (c + 2 < NIT) {
            int nb = (c + 2) % 3;
            if (nb == 0)      { GSTAGE(c + 2, 0) }
            else if (nb == 1) { GSTAGE(c + 2, 1) }
            else              { GSTAGE(c + 2, 2) }
        }
        cp_commit();

        const float* a_s = As + buf * TB;
        const float* b_s = Bs + buf * TB;
        #pragma unroll
        for (int ks = 0; ks < 4; ks++) {     // each ks = 16 halves (8 words)
            uint32_t afr[4][4], bfr[4][2];
            int slot = (2 * ks + (fk >> 1) + 2 * (frow & 3)) & 7;
            int fo = slot * 4 + (fk & 1) * 2;   // word offset in 32-word row
            #pragma unroll
            for (int mt = 0; mt < 4; mt++) {
                int rr = wm + mt * 16 + frow;
                float2 u = *(const float2*)&a_s[rr * 32 + fo];
                float2 v = *(const float2*)&a_s[(rr + 8) * 32 + fo];
                afr[mt][0] = __float_as_uint(u.x);
                afr[mt][1] = __float_as_uint(v.x);
                afr[mt][2] = __float_as_uint(u.y);
                afr[mt][3] = __float_as_uint(v.y);
            }
            #pragma unroll
            for (int nt = 0; nt < 4; nt++) {
                int rn = wn + nt * 8 + frow;
                float2 w2 = *(const float2*)&b_s[rn * 32 + fo];
                bfr[nt][0] = __float_as_uint(w2.x);
                bfr[nt][1] = __float_as_uint(w2.y);
            }
            #pragma unroll
            for (int mt = 0; mt < 4; mt++)
                #pragma unroll
                for (int nt = 0; nt < 4; nt++)
                    mma_f16(acc[mt][nt], afr[mt], bfr[nt]);
        }
        buf = (buf + 1) == 3 ? 0 : buf + 1;
    }
    #undef GSTAGE

    #pragma unroll
    for (int mt = 0; mt < 4; mt++) {
        int row = bm + wm + mt * 16 + frow;
        #pragma unroll
        for (int nt = 0; nt < 4; nt++) {
            int col = bn + wn + nt * 8 + fk * 2;
            float vv[4];
            #pragma unroll
            for (int r = 0; r < 4; r++) {
                float v = acc[mt][nt][r];
                if (epi == 1)      v = 1.f / (1.f + __expf(-v));
                else if (epi == 2) v = 0.999900004999833f / (1.f + __expf(-v));
                vv[r] = v;
            }
            *(float2*)&C[(size_t)row * Nz + col]       = make_float2(vv[0], vv[1]);
            *(float2*)&C[(size_t)(row + 8) * Nz + col] = make_float2(vv[2], vv[3]);
        }
    }
}

__global__ void __launch_bounds__(256, 2) proj_gemm()
{
    int which = blockIdx.z;
    int epi = (which == 0) ? 1 : (which == 3) ? 2 : 0;
    gemm_body(g_hA[which], g_hW + (size_t)which * (Dz * Dz),
              g_buf[which], epi);
}

// out GEMM writes fp32 result; A comes from fused gnorm output (half)
__global__ void __launch_bounds__(256, 2) out_gemm(float* __restrict__ out)
{
    gemm_body(g_hO, g_hW + (size_t)4 * (Dz * Dz), out, 0);
}

// ---------------------------------------------------------------------------
// Pass A: chunk-local scan, zero init. grid (NC-1, NBH), 128 threads.
// ---------------------------------------------------------------------------
__global__ void __launch_bounds__(128) scanA_kernel()
{
    extern __shared__ __align__(16) float sm[];
    float* k_s = sm;
    float* e_s = sm + 4096;
    float* v_s = sm + 8192;

    int tid  = threadIdx.x;
    int j    = tid & 63;
    int half = tid >> 6;
    int c  = blockIdx.x;
    int bh = blockIdx.y;
    int b = bh >> 4, h = bh & 15;

    int base0 = (b * Tz + c * CL) * Dz + h * 64;

    #pragma unroll
    for (int it = 0; it < 8; it++) {
        int f  = it * 128 + tid;
        int t  = f >> 4;
        int i4 = (f & 15) << 2;
        int ga = base0 + t * Dz + i4;
        int sa = t * 64 + i4;
        *(float4*)&k_s[sa] = *(const float4*)&g_buf[1][ga];
        *(float4*)&e_s[sa] = *(const float4*)&g_buf[3][ga];
        *(float4*)&v_s[sa] = *(const float4*)&g_buf[2][ga];
    }
    __syncthreads();

    float s[32];
    #pragma unroll
    for (int i = 0; i < 32; i++) s[i] = 0.f;

    for (int t = 0; t < CL; t++) {
        float vj = v_s[t * 64 + j];
        const float4* kp = (const float4*)&k_s[t * 64 + half * 32];
        const float4* ep = (const float4*)&e_s[t * 64 + half * 32];
        #pragma unroll
        for (int q = 0; q < 8; q++) {
            float4 kv = kp[q], ev = ep[q];
            s[q * 4 + 0] = ev.x * s[q * 4 + 0] + kv.x * vj;
            s[q * 4 + 1] = ev.y * s[q * 4 + 1] + kv.y * vj;
            s[q * 4 + 2] = ev.z * s[q * 4 + 2] + kv.z * vj;
            s[q * 4 + 3] = ev.w * s[q * 4 + 3] + kv.w * vj;
        }
    }

    int slot = (bh * NC + c) * DHz;
    #pragma unroll 8
    for (int ii = 0; ii < 32; ii++)
        g_state[(size_t)(slot + half * 32 + ii) * DHz + j] = s[ii];

    if (half == 0) {
        float w0 = 1.f, w1 = 1.f, w2 = 1.f, w3 = 1.f;
        #pragma unroll
        for (int t = 0; t < CL; t += 4) {
            w0 *= e_s[(t + 0) * 64 + j];
            w1 *= e_s[(t + 1) * 64 + j];
            w2 *= e_s[(t + 2) * 64 + j];
            w3 *= e_s[(t + 3) * 64 + j];
        }
        g_wprod[slot + j] = (w0 * w1) * (w2 * w3);
    }
}

// ---------------------------------------------------------------------------
// Pass B: sequential prefix over chunks. grid NBH, 256 threads.
// ---------------------------------------------------------------------------
__global__ void __launch_bounds__(256) scanB_kernel()
{
    __shared__ float s_w[64];
    int tid = threadIdx.x;
    int j   = tid & 63;
    int q   = tid >> 6;
    int bh = blockIdx.x;

    float R[16];
    #pragma unroll
    for (int i = 0; i < 16; i++) R[i] = 0.f;

    for (int c = 0; c < NC; c++) {
        int slot = (bh * NC + c) * DHz;
        if (c < NC - 1) {
            if (tid < 64) s_w[tid] = g_wprod[slot + tid];
            __syncthreads();
            #pragma unroll 8
            for (int ii = 0; ii < 16; ii++) {
                int i = q * 16 + ii;
                size_t a = (size_t)(slot + i) * DHz + j;
                float local = g_state[a];
                g_state[a] = R[ii];
                R[ii] = s_w[i] * R[ii] + local;
            }
            __syncthreads();
        } else {
            #pragma unroll 8
            for (int ii = 0; ii < 16; ii++)
                g_state[(size_t)(slot + q * 16 + ii) * DHz + j] = R[ii];
        }
    }
}

// ---------------------------------------------------------------------------
// Pass C (FUSED): scan outputs + bonus + groupnorm + r-mult + fp16 permute.
// grid (NC, NBH), 128 threads. Barrier-free combine.
// ---------------------------------------------------------------------------
#define SCM_FLOATS 24704

// permuted half index for original half index j (word-pair permutation)
__device__ __forceinline__ int perm_half(int j)
{
    int w  = j >> 1;
    int g  = w >> 3;
    int ww = w & 7;
    int pw = (ww < 4) ? 2 * ww : 2 * (ww - 4) + 1;
    return ((g * 8 + pw) << 1) | (j & 1);
}

__global__ void __launch_bounds__(128) scanC_kernel(
    const float* __restrict__ u,
    const float* __restrict__ ln_w, const float* __restrict__ ln_b)
{
    extern __shared__ __align__(16) float sm[];
    float* k_s  = sm;
    float* e_s  = sm + 4096;
    float* v_s  = sm + 8192;
    float* r_s  = sm + 12288;
    float* op   = sm + 16384;
    float* lnw_s = sm + 24576;
    float* lnb_s = sm + 24640;

    int tid  = threadIdx.x;
    int lane = tid & 31;
    int wid  = tid >> 5;
    int j    = tid & 63;
    int half = tid >> 6;
    int c  = blockIdx.x;
    int bh = blockIdx.y;
    int b = bh >> 4, h = bh & 15;

    int base0 = (b * Tz + c * CL) * Dz + h * 64;

    #pragma unroll
    for (int it = 0; it < 8; it++) {
        int f  = it * 128 + tid;
        int t  = f >> 4;
        int i4 = (f & 15) << 2;
        int ga = base0 + t * Dz + i4;
        int sa = t * 64 + i4;
        *(float4*)&k_s[sa] = *(const float4*)&g_buf[1][ga];
        *(float4*)&e_s[sa] = *(const float4*)&g_buf[3][ga];
        *(float4*)&v_s[sa] = *(const float4*)&g_buf[2][ga];
        *(float4*)&r_s[sa] = *(const float4*)&g_buf[0][ga];
    }
    if (tid < 64) { lnw_s[tid] = ln_w[tid]; lnb_s[tid] = ln_b[tid]; }

    float s[32];
    {
        int slot = (bh * NC + c) * DHz;
        #pragma unroll 8
        for (int ii = 0; ii < 32; ii++)
            s[ii] = g_state[(size_t)(slot + half * 32 + ii) * DHz + j];
    }
    __syncthreads();

    // ---- scan: partial o per (t, j, half) ----
    float* myop = op + half * 4096;
    for (int t = 0; t < CL; t++) {
        float vj = v_s[t * 64 + j];
        const float4* rp = (const float4*)&r_s[t * 64 + half * 32];
        const float4* kp = (const float4*)&k_s[t * 64 + half * 32];
        const float4* ep = (const float4*)&e_s[t * 64 + half * 32];
        float o0 = 0.f, o1 = 0.f, o2 = 0.f, o3 = 0.f;
        #pragma unroll
        for (int q = 0; q < 8; q++) {
            float4 rv = rp[q], kv = kp[q], ev = ep[q];
            o0 += rv.x * s[q * 4 + 0]; s[q * 4 + 0] = ev.x * s[q * 4 + 0] + kv.x * vj;
            o1 += rv.y * s[q * 4 + 1]; s[q * 4 + 1] = ev.y * s[q * 4 + 1] + kv.y * vj;
            o2 += rv.z * s[q * 4 + 2]; s[q * 4 + 2] = ev.z * s[q * 4 + 2] + kv.z * vj;
            o3 += rv.w * s[q * 4 + 3]; s[q * 4 + 3] = ev.w * s[q * 4 + 3] + kv.w * vj;
        }
        myop[t * 64 + j] = ((o0 + o1) + (o2 + o3));
    }
    __syncthreads();

    // ---- combine (barrier-free): warp w handles t = 4*it + w ----
    float u0 = u[h * 64 + lane];
    float u1 = u[h * 64 + 32 + lane];
    float lw0 = lnw_s[lane],      lb0 = lnb_s[lane];
    float lw1 = lnw_s[lane + 32], lb1 = lnb_s[lane + 32];
    int pj0 = perm_half(lane);
    int pj1 = perm_half(lane + 32);

    #pragma unroll 4
    for (int it = 0; it < 16; it++) {
        int t = it * 4 + wid;
        int tb = t * 64;
        float r0 = r_s[tb + lane], r1 = r_s[tb + 32 + lane];
        float v0 = v_s[tb + lane], v1 = v_s[tb + 32 + lane];

        float term = r0 * __expf(u0 + k_s[tb + lane])
                   + r1 * __expf(u1 + k_s[tb + 32 + lane]);
        #pragma unroll
        for (int off = 16; off > 0; off >>= 1)
            term += __shfl_xor_sync(0xffffffffu, term, off);

        float o0 = op[tb + lane]      + op[4096 + tb + lane]      + term * v0;
        float o1 = op[tb + 32 + lane] + op[4096 + tb + 32 + lane] + term * v1;

        float ssum = o0 + o1;
        float ssq  = o0 * o0 + o1 * o1;
        #pragma unroll
        for (int off = 16; off > 0; off >>= 1) {
            ssum += __shfl_xor_sync(0xffffffffu, ssum, off);
            ssq  += __shfl_xor_sync(0xffffffffu, ssq,  off);
        }
        float mean = ssum * (1.f / 64.f);
        float var  = ssq * (1.f / 64.f) - mean * mean;
        float rsd  = rsqrtf(var + 1e-5f);

        float n0 = ((o0 - mean) * rsd * lw0 + lb0) * r0;
        float n1 = ((o1 - mean) * rsd * lw1 + lb1) * r1;
        g_hO[base0 + t * Dz + pj0] = __float2half_rn(n0);
        g_hO[base0 + t * Dz + pj1] = __float2half_rn(n1);
    }
}

// ---------------------------------------------------------------------------
extern "C" void kernel_launch(void* const* d_in, const int* in_sizes, int n_in,
                              void* d_out, int out_size)
{
    const float* x    = (const float*)d_in[0];
    const float* W_r  = (const float*)d_in[1];
    const float* W_k  = (const float*)d_in[2];
    const float* W_v  = (const float*)d_in[3];
    const float* W_w  = (const float*)d_in[4];
    const float* W_o  = (const float*)d_in[5];
    const float* u    = (const float*)d_in[6];
    const float* tm_r = (const float*)d_in[7];
    const float* tm_k = (const float*)d_in[8];
    const float* tm_v = (const float*)d_in[9];
    const float* tm_w = (const float*)d_in[10];
    const float* ln_w = (const float*)d_in[11];
    const float* ln_b = (const float*)d_in[12];
    float* out = (float*)d_out;

    cudaFuncSetAttribute(scanA_kernel,
        cudaFuncAttributeMaxDynamicSharedMemorySize, 12288 * 4);
    cudaFuncSetAttribute(scanC_kernel,
        cudaFuncAttributeMaxDynamicSharedMemorySize, SCM_FLOATS * 4);
    cudaFuncSetAttribute(proj_gemm,
        cudaFuncAttributeMaxDynamicSharedMemorySize, GSMB);
    cudaFuncSetAttribute(out_gemm,
        cudaFuncAttributeMaxDynamicSharedMemorySize, GSMB);

    roundw_kernel<<<1280, 256>>>(
        (const float4*)W_r, (const float4*)W_k, (const float4*)W_v,
        (const float4*)W_w, (const float4*)W_o);

    mix_kernel<<<1024, 256>>>(
        (const float4*)x, (const float4*)tm_r, (const float4*)tm_k,
        (const float4*)tm_v, (const float4*)tm_w);

    proj_gemm<<<dim3(Nz / 128, Mz / 128, 4), 256, GSMB>>>();

    scanA_kernel<<<dim3(NC - 1, NBH), 128, 12288 * 4>>>();
    scanB_kernel<<<NBH, 256>>>();
    scanC_kernel<<<dim3(NC, NBH), 128, SCM_FLOATS * 4>>>(u, ln_w, ln_b);

    out_gemm<<<dim3(Nz / 128, Mz / 128), 256, GSMB>>>(out);
}

// round 15
// speedup vs baseline: 1.6287x; 1.0793x over previous
#include <cuda_runtime.h>
#include <cuda_fp16.h>
#include <cstdint>

#define Bz 4
#define Tz 1024
#define Dz 1024
#define Hz 16
#define DHz 64
#define Mz (Bz*Tz)        // 4096
#define Kz Dz
#define Nz Dz
#define MD (Mz*Dz)        // 4,194,304
#define NBH (Bz*Hz)       // 64
#define CL 64             // chunk length
#define NC (Tz/CL)        // 16 chunks

// fp32 scan operands: 0=r, 1=k, 2=v, 3=e (written by proj GEMM epilogue)
__device__ float g_buf[4][MD];
// fp16 GEMM operands (k-word-permuted)
__device__ __half g_hA[4][MD];            // mix outputs
__device__ __half g_hW[5 * Dz * Dz];      // weights
__device__ __half g_hO[MD];               // gnorm output
__device__ float g_state[NBH * NC * DHz * DHz];
__device__ float g_wprod[NBH * NC * DHz];

__device__ __forceinline__ float to_tf32(float x)
{
    uint32_t d;
    asm("cvt.rna.tf32.f32 %0, %1;" : "=r"(d) : "f"(x));
    return __uint_as_float(d);
}
__device__ __forceinline__ uint32_t f2h2(float a, float b)
{
    __half2 h = __floats2half2_rn(a, b);
    return *reinterpret_cast<uint32_t*>(&h);
}
__device__ __forceinline__ uint32_t smem_to_u32(const void* p) {
    uint32_t a;
    asm("{ .reg .u64 t; cvta.to.shared.u64 t, %1; cvt.u32.u64 %0, t; }"
        : "=r"(a) : "l"(p));
    return a;
}
__device__ __forceinline__ void cp16(uint32_t dst, const void* src) {
    asm volatile("cp.async.cg.shared.global [%0], [%1], 16;"
                 :: "r"(dst), "l"(src));
}
__device__ __forceinline__ void cp_commit() {
    asm volatile("cp.async.commit_group;" ::: "memory");
}
__device__ __forceinline__ void mma_f16(float c[4], const uint32_t a[4],
                                        const uint32_t b[2])
{
    asm volatile(
        "mma.sync.aligned.m16n8k16.row.col.f32.f16.f16.f32 "
        "{%0,%1,%2,%3}, {%4,%5,%6,%7}, {%8,%9}, {%0,%1,%2,%3};"
        : "+f"(c[0]), "+f"(c[1]), "+f"(c[2]), "+f"(c[3])
        : "r"(a[0]), "r"(a[1]), "r"(a[2]), "r"(a[3]),
          "r"(b[0]), "r"(b[1]));
}
__device__ __forceinline__ void mma_tf32(float c[4], const uint32_t a[4],
                                         const uint32_t b[2])
{
    asm volatile(
        "mma.sync.aligned.m16n8k8.row.col.f32.tf32.tf32.f32 "
        "{%0,%1,%2,%3}, {%4,%5,%6,%7}, {%8,%9}, {%0,%1,%2,%3};"
        : "+f"(c[0]), "+f"(c[1]), "+f"(c[2]), "+f"(c[3])
        : "r"(a[0]), "r"(a[1]), "r"(a[2]), "r"(a[3]),
          "r"(b[0]), "r"(b[1]));
}

// pack 16 floats -> 8 half2 words, permuted [0,4,1,5] [2,6,3,7]
__device__ __forceinline__ void pack_perm16(const float* f, uint4& o0, uint4& o1)
{
    uint32_t w[8];
    #pragma unroll
    for (int i = 0; i < 8; i++) w[i] = f2h2(f[2 * i], f[2 * i + 1]);
    o0 = make_uint4(w[0], w[4], w[1], w[5]);
    o1 = make_uint4(w[2], w[6], w[3], w[7]);
}

// ---------------------------------------------------------------------------
// weights -> fp16, word-permuted. one thread per 16-half group.
// ---------------------------------------------------------------------------
__global__ void __launch_bounds__(256) roundw_kernel(
    const float4* __restrict__ a, const float4* __restrict__ b,
    const float4* __restrict__ c, const float4* __restrict__ d,
    const float4* __restrict__ e)
{
    int idx = blockIdx.x * 256 + threadIdx.x;      // 0..327679
    int which = idx >> 16;
    int off = idx & 65535;
    const float4* src = which == 0 ? a : which == 1 ? b : which == 2 ? c
                       : which == 3 ? d : e;
    float f[16];
    #pragma unroll
    for (int i = 0; i < 4; i++)
        *(float4*)&f[i * 4] = src[4 * off + i];
    uint4 o0, o1;
    pack_perm16(f, o0, o1);
    uint4* dst = reinterpret_cast<uint4*>(g_hW) + (size_t)which * 131072;
    dst[2 * off] = o0;
    dst[2 * off + 1] = o1;
}

// ---------------------------------------------------------------------------
// token-shift mix -> fp16 word-permuted. one thread per 16-half group.
// ---------------------------------------------------------------------------
__global__ void __launch_bounds__(256) mix_kernel(
    const float4* __restrict__ x,
    const float4* __restrict__ tmr, const float4* __restrict__ tmk,
    const float4* __restrict__ tmv, const float4* __restrict__ tmw)
{
    int idx = blockIdx.x * 256 + threadIdx.x;   // MD/16 = 262144
    int m  = idx >> 6;
    int gg = idx & 63;
    int t  = m & (Tz - 1);

    float xc[16], xp[16];
    #pragma unroll
    for (int i = 0; i < 4; i++)
        *(float4*)&xc[i * 4] = x[(m << 8) + gg * 4 + i];
    if (t != 0) {
        #pragma unroll
        for (int i = 0; i < 4; i++)
            *(float4*)&xp[i * 4] = x[((m - 1) << 8) + gg * 4 + i];
    } else {
        #pragma unroll
        for (int i = 0; i < 16; i++) xp[i] = 0.f;
    }

    #define DO_MIX(TMV, DSTI)                                               \
    {                                                                       \
        float tm[16], mx[16];                                               \
        _Pragma("unroll")                                                   \
        for (int i = 0; i < 4; i++)                                         \
            *(float4*)&tm[i * 4] = TMV[gg * 4 + i];                         \
        _Pragma("unroll")                                                   \
        for (int i = 0; i < 16; i++)                                        \
            mx[i] = tm[i] * xc[i] + (1.f - tm[i]) * xp[i];                  \
        uint4 o0, o1;                                                       \
        pack_perm16(mx, o0, o1);                                            \
        uint4* dst = reinterpret_cast<uint4*>(g_hA[DSTI]);                  \
        dst[2 * idx] = o0;                                                  \
        dst[2 * idx + 1] = o1;                                              \
    }
    DO_MIX(tmr, 0)
    DO_MIX(tmk, 1)
    DO_MIX(tmv, 2)
    DO_MIX(tmw, 3)
    #undef DO_MIX
}

// ---------------------------------------------------------------------------
// fp16 mma.sync GEMM on word-permuted operands (unchanged from round 14)
// ---------------------------------------------------------------------------
#define TB 4096                               // 32-bit words per tile buffer
#define GSMB (3 * 2 * TB * 4)                 // 98304 bytes

__device__ __forceinline__ void gemm_body(
    const __half* __restrict__ A,
    const __half* __restrict__ W,
    float* __restrict__ C, int epi)
{
    extern __shared__ __align__(16) float sm[];
    float* As = sm;
    float* Bs = sm + 3 * TB;
    uint32_t a32 = smem_to_u32(As);
    uint32_t b32 = smem_to_u32(Bs);

    int tid  = threadIdx.x;
    int lane = tid & 31;
    int wid  = tid >> 5;
    int bm = blockIdx.y * 128;
    int bn = blockIdx.x * 128;

    int wm = (wid >> 2) * 64;
    int wn = (wid & 3) * 32;
    int frow = lane >> 2;
    int fk   = lane & 3;

    float acc[4][4][4];
    #pragma unroll
    for (int i = 0; i < 4; i++)
        #pragma unroll
        for (int j = 0; j < 4; j++)
            #pragma unroll
            for (int r = 0; r < 4; r++) acc[i][j][r] = 0.f;

    #define GSTAGE(CC, BUF)                                                  \
    {                                                                        \
        const char* ap = (const char*)(A + (size_t)bm * Kz + (CC) * 64);     \
        const char* bp = (const char*)(W + (size_t)bn * Kz + (CC) * 64);     \
        _Pragma("unroll")                                                    \
        for (int i = 0; i < 4; i++) {                                        \
            int lin = i * 256 + tid;                                         \
            int r = lin >> 3;                                                \
            int g = lin & 7;                                                 \
            int slot = (g + 2 * (r & 3)) & 7;                                \
            cp16(a32 + (BUF) * (TB * 4) + r * 128 + slot * 16,               \
                 ap + (size_t)r * (Kz * 2) + g * 16);                        \
            cp16(b32 + (BUF) * (TB * 4) + r * 128 + slot * 16,               \
                 bp + (size_t)r * (Kz * 2) + g * 16);                        \
        }                                                                    \
    }

    GSTAGE(0, 0) cp_commit();
    GSTAGE(1, 1) cp_commit();

    const int NIT = Kz >> 6;         // 16
    int buf = 0;
    for (int c = 0; c < NIT; c++) {
        asm volatile("cp.async.wait_group 1;" ::: "memory");
        __syncthreads();
        if (c + 2 < NIT) {
            int nb = (c + 2) % 3;
            if (nb == 0)      { GSTAGE(c + 2, 0) }
            else if (nb == 1) { GSTAGE(c + 2, 1) }
            else              { GSTAGE(c + 2, 2) }
        }
        cp_commit();

        const float* a_s = As + buf * TB;
        const float* b_s = Bs + buf * TB;
        #pragma unroll
        for (int ks = 0; ks < 4; ks++) {
            uint32_t afr[4][4], bfr[4][2];
            int slot = (2 * ks + (fk >> 1) + 2 * (frow & 3)) & 7;
            int fo = slot * 4 + (fk & 1) * 2;
            #pragma unroll
            for (int mt = 0; mt < 4; mt++) {
                int rr = wm + mt * 16 + frow;
                float2 u = *(const float2*)&a_s[rr * 32 + fo];
                float2 v = *(const float2*)&a_s[(rr + 8) * 32 + fo];
                afr[mt][0] = __float_as_uint(u.x);
                afr[mt][1] = __float_as_uint(v.x);
                afr[mt][2] = __float_as_uint(u.y);
                afr[mt][3] = __float_as_uint(v.y);
            }
            #pragma unroll
            for (int nt = 0; nt < 4; nt++) {
                int rn = wn + nt * 8 + frow;
                float2 w2 = *(const float2*)&b_s[rn * 32 + fo];
                bfr[nt][0] = __float_as_uint(w2.x);
                bfr[nt][1] = __float_as_uint(w2.y);
            }
            #pragma unroll
            for (int mt = 0; mt < 4; mt++)
                #pragma unroll
                for (int nt = 0; nt < 4; nt++)
                    mma_f16(acc[mt][nt], afr[mt], bfr[nt]);
        }
        buf = (buf + 1) == 3 ? 0 : buf + 1;
    }
    #undef GSTAGE

    #pragma unroll
    for (int mt = 0; mt < 4; mt++) {
        int row = bm + wm + mt * 16 + frow;
        #pragma unroll
        for (int nt = 0; nt < 4; nt++) {
            int col = bn + wn + nt * 8 + fk * 2;
            float vv[4];
            #pragma unroll
            for (int r = 0; r < 4; r++) {
                float v = acc[mt][nt][r];
                if (epi == 1)      v = 1.f / (1.f + __expf(-v));
                else if (epi == 2) v = 0.999900004999833f / (1.f + __expf(-v));
                vv[r] = v;
            }
            *(float2*)&C[(size_t)row * Nz + col]       = make_float2(vv[0], vv[1]);
            *(float2*)&C[(size_t)(row + 8) * Nz + col] = make_float2(vv[2], vv[3]);
        }
    }
}

__global__ void __launch_bounds__(256, 2) proj_gemm()
{
    int which = blockIdx.z;
    int epi = (which == 0) ? 1 : (which == 3) ? 2 : 0;
    gemm_body(g_hA[which], g_hW + (size_t)which * (Dz * Dz),
              g_buf[which], epi);
}

__global__ void __launch_bounds__(256, 2) out_gemm(float* __restrict__ out)
{
    gemm_body(g_hO, g_hW + (size_t)4 * (Dz * Dz), out, 0);
}

// ---------------------------------------------------------------------------
// Pass A (tensor-core): S_local = K'^T @ V via tf32 mma, where
// K'[t][i] = k[t][i] * prod_{t'>t} e[t'][i]. grid (NC-1, NBH), 128 threads.
// threads 0-63: per-channel suffix product -> Ap[i][t] (tf32) + wprod.
// threads 64-127: transpose v from global -> Bp[j][t] (tf32).
// Then 4 warps compute S (M=64,N=64,K=64) with m16n8k8; row pad 68
// (banks 4*frow+fk conflict-free on fragment loads).
// smem: k_s 4096, e_s 4096, Ap 64*68=4352, Bp 4352 -> 16896 floats (67.6KB)
// ---------------------------------------------------------------------------
#define SA_FLOATS 16896

__global__ void __launch_bounds__(128) scanA_kernel()
{
    extern __shared__ __align__(16) float sm[];
    float* k_s = sm;             // [64t][64i]
    float* e_s = sm + 4096;
    float* Ap  = sm + 8192;      // [64i][68]
    float* Bp  = sm + 12544;     // [64j][68]

    int tid = threadIdx.x;
    int lane = tid & 31;
    int wid  = tid >> 5;
    int c  = blockIdx.x;
    int bh = blockIdx.y;
    int b = bh >> 4, h = bh & 15;

    int base0 = (b * Tz + c * CL) * Dz + h * 64;
    int slot  = (bh * NC + c) * DHz;

    #pragma unroll
    for (int it = 0; it < 8; it++) {
        int f  = it * 128 + tid;
        int t  = f >> 4;
        int i4 = (f & 15) << 2;
        int ga = base0 + t * Dz + i4;
        int sa = t * 64 + i4;
        *(float4*)&k_s[sa] = *(const float4*)&g_buf[1][ga];
        *(float4*)&e_s[sa] = *(const float4*)&g_buf[3][ga];
    }
    __syncthreads();

    if (tid < 64) {
        int i = tid;
        float sp = 1.f;
        #pragma unroll 4
        for (int t = CL - 1; t >= 0; t--) {
            Ap[i * 68 + t] = to_tf32(k_s[t * 64 + i] * sp);
            sp *= e_s[t * 64 + i];
        }
        g_wprod[slot + i] = sp;
    } else {
        int j = tid - 64;
        const float* __restrict__ gv = g_buf[2];
        #pragma unroll 4
        for (int t = 0; t < CL; t++)
            Bp[j * 68 + t] = to_tf32(gv[base0 + t * Dz + j]);
    }
    __syncthreads();

    // S[i][j] = sum_t Ap[i][t] * Bp[j][t]; warp wid owns rows [wid*16, +16)
    int wm = wid * 16;
    int frow = lane >> 2;
    int fk   = lane & 3;

    float acc[8][4];
    #pragma unroll
    for (int n = 0; n < 8; n++)
        #pragma unroll
        for (int r = 0; r < 4; r++) acc[n][r] = 0.f;

    #pragma unroll
    for (int ko = 0; ko < 64; ko += 8) {
        uint32_t a[4];
        const float* p = &Ap[(wm + frow) * 68 + ko + fk];
        a[0] = __float_as_uint(p[0]);
        a[1] = __float_as_uint(p[8 * 68]);
        a[2] = __float_as_uint(p[4]);
        a[3] = __float_as_uint(p[8 * 68 + 4]);
        #pragma unroll
        for (int nt = 0; nt < 8; nt++) {
            const float* q = &Bp[(nt * 8 + frow) * 68 + ko + fk];
            uint32_t bb[2];
            bb[0] = __float_as_uint(q[0]);
            bb[1] = __float_as_uint(q[4]);
            mma_tf32(acc[nt], a, bb);
        }
    }

    #pragma unroll
    for (int nt = 0; nt < 8; nt++) {
        int col = nt * 8 + fk * 2;
        *(float2*)&g_state[(size_t)(slot + wm + frow) * DHz + col] =
            make_float2(acc[nt][0], acc[nt][1]);
        *(float2*)&g_state[(size_t)(slot + wm + frow + 8) * DHz + col] =
            make_float2(acc[nt][2], acc[nt][3]);
    }
}

// ---------------------------------------------------------------------------
// Pass B: sequential prefix over chunks. grid NBH, 256 threads.
// ---------------------------------------------------------------------------
__global__ void __launch_bounds__(256) scanB_kernel()
{
    __shared__ float s_w[64];
    int tid = threadIdx.x;
    int j   = tid & 63;
    int q   = tid >> 6;
    int bh = blockIdx.x;

    float R[16];
    #pragma unroll
    for (int i = 0; i < 16; i++) R[i] = 0.f;

    for (int c = 0; c < NC; c++) {
        int slot = (bh * NC + c) * DHz;
        if (c < NC - 1) {
            if (tid < 64) s_w[tid] = g_wprod[slot + tid];
            __syncthreads();
            #pragma unroll 8
            for (int ii = 0; ii < 16; ii++) {
                int i = q * 16 + ii;
                size_t a = (size_t)(slot + i) * DHz + j;
                float local = g_state[a];
                g_state[a] = R[ii];
                R[ii] = s_w[i] * R[ii] + local;
            }
            __syncthreads();
        } else {
            #pragma unroll 8
            for (int ii = 0; ii < 16; ii++)
                g_state[(size_t)(slot + q * 16 + ii) * DHz + j] = R[ii];
        }
    }
}

// ---------------------------------------------------------------------------
// Pass C (FUSED): scan outputs + bonus + groupnorm + r-mult + fp16 permute.
// grid (NC, NBH), 128 threads. Barrier-free combine. (unchanged)
// ---------------------------------------------------------------------------
#define SCM_FLOATS 24704

__device__ __forceinline__ int perm_half(int j)
{
    int w  = j >> 1;
    int g  = w >> 3;
    int ww = w & 7;
    int pw = (ww < 4) ? 2 * ww : 2 * (ww - 4) + 1;
    return ((g * 8 + pw) << 1) | (j & 1);
}

__global__ void __launch_bounds__(128) scanC_kernel(
    const float* __restrict__ u,
    const float* __restrict__ ln_w, const float* __restrict__ ln_b)
{
    extern __shared__ __align__(16) float sm[];
    float* k_s  = sm;
    float* e_s  = sm + 4096;
    float* v_s  = sm + 8192;
    float* r_s  = sm + 12288;
    float* op   = sm + 16384;
    float* lnw_s = sm + 24576;
    float* lnb_s = sm + 24640;

    int tid  = threadIdx.x;
    int lane = tid & 31;
    int wid  = tid >> 5;
    int j    = tid & 63;
    int half = tid >> 6;
    int c  = blockIdx.x;
    int bh = blockIdx.y;
    int b = bh >> 4, h = bh & 15;

    int base0 = (b * Tz + c * CL) * Dz + h * 64;

    #pragma unroll
    for (int it = 0; it < 8; it++) {
        int f  = it * 128 + tid;
        int t  = f >> 4;
        int i4 = (f & 15) << 2;
        int ga = base0 + t * Dz + i4;
        int sa = t * 64 + i4;
        *(float4*)&k_s[sa] = *(const float4*)&g_buf[1][ga];
        *(float4*)&e_s[sa] = *(const float4*)&g_buf[3][ga];
        *(float4*)&v_s[sa] = *(const float4*)&g_buf[2][ga];
        *(float4*)&r_s[sa] = *(const float4*)&g_buf[0][ga];
    }
    if (tid < 64) { lnw_s[tid] = ln_w[tid]; lnb_s[tid] = ln_b[tid]; }

    float s[32];
    {
        int slot = (bh * NC + c) * DHz;
        #pragma unroll 8
        for (int ii = 0; ii < 32; ii++)
            s[ii] = g_state[(size_t)(slot + half * 32 + ii) * DHz + j];
    }
    __syncthreads();

    float* myop = op + half * 4096;
    for (int t = 0; t < CL; t++) {
        float vj = v_s[t * 64 + j];
        const float4* rp = (const float4*)&r_s[t * 64 + half * 32];
        const float4* kp = (const float4*)&k_s[t * 64 + half * 32];
        const float4* ep = (const float4*)&e_s[t * 64 + half * 32];
        float o0 = 0.f, o1 = 0.f, o2 = 0.f, o3 = 0.f;
        #pragma unroll
        for (int q = 0; q < 8; q++) {
            float4 rv = rp[q], kv = kp[q], ev = ep[q];
            o0 += rv.x * s[q * 4 + 0]; s[q * 4 + 0] = ev.x * s[q * 4 + 0] + kv.x * vj;
            o1 += rv.y * s[q * 4 + 1]; s[q * 4 + 1] = ev.y * s[q * 4 + 1] + kv.y * vj;
            o2 += rv.z * s[q * 4 + 2]; s[q * 4 + 2] = ev.z * s[q * 4 + 2] + kv.z * vj;
            o3 += rv.w * s[q * 4 + 3]; s[q * 4 + 3] = ev.w * s[q * 4 + 3] + kv.w * vj;
        }
        myop[t * 64 + j] = ((o0 + o1) + (o2 + o3));
    }
    __syncthreads();

    float u0 = u[h * 64 + lane];
    float u1 = u[h * 64 + 32 + lane];
    float lw0 = lnw_s[lane],      lb0 = lnb_s[lane];
    float lw1 = lnw_s[lane + 32], lb1 = lnb_s[lane + 32];
    int pj0 = perm_half(lane);
    int pj1 = perm_half(lane + 32);

    #pragma unroll 4
    for (int it = 0; it < 16; it++) {
        int t = it * 4 + wid;
        int tb = t * 64;
        float r0 = r_s[tb + lane], r1 = r_s[tb + 32 + lane];
        float v0 = v_s[tb + lane], v1 = v_s[tb + 32 + lane];

        float term = r0 * __expf(u0 + k_s[tb + lane])
                   + r1 * __expf(u1 + k_s[tb + 32 + lane]);
        #pragma unroll
        for (int off = 16; off > 0; off >>= 1)
            term += __shfl_xor_sync(0xffffffffu, term, off);

        float o0 = op[tb + lane]      + op[4096 + tb + lane]      + term * v0;
        float o1 = op[tb + 32 + lane] + op[4096 + tb + 32 + lane] + term * v1;

        float ssum = o0 + o1;
        float ssq  = o0 * o0 + o1 * o1;
        #pragma unroll
        for (int off = 16; off > 0; off >>= 1) {
            ssum += __shfl_xor_sync(0xffffffffu, ssum, off);
            ssq  += __shfl_xor_sync(0xffffffffu, ssq,  off);
        }
        float mean = ssum * (1.f / 64.f);
        float var  = ssq * (1.f / 64.f) - mean * mean;
        float rsd  = rsqrtf(var + 1e-5f);

        float n0 = ((o0 - mean) * rsd * lw0 + lb0) * r0;
        float n1 = ((o1 - mean) * rsd * lw1 + lb1) * r1;
        g_hO[base0 + t * Dz + pj0] = __float2half_rn(n0);
        g_hO[base0 + t * Dz + pj1] = __float2half_rn(n1);
    }
}

// ---------------------------------------------------------------------------
extern "C" void kernel_launch(void* const* d_in, const int* in_sizes, int n_in,
                              void* d_out, int out_size)
{
    const float* x    = (const float*)d_in[0];
    const float* W_r  = (const float*)d_in[1];
    const float* W_k  = (const float*)d_in[2];
    const float* W_v  = (const float*)d_in[3];
    const float* W_w  = (const float*)d_in[4];
    const float* W_o  = (const float*)d_in[5];
    const float* u    = (const float*)d_in[6];
    const float* tm_r = (const float*)d_in[7];
    const float* tm_k = (const float*)d_in[8];
    const float* tm_v = (const float*)d_in[9];
    const float* tm_w = (const float*)d_in[10];
    const float* ln_w = (const float*)d_in[11];
    const float* ln_b = (const float*)d_in[12];
    float* out = (float*)d_out;

    cudaFuncSetAttribute(scanA_kernel,
        cudaFuncAttributeMaxDynamicSharedMemorySize, SA_FLOATS * 4);
    cudaFuncSetAttribute(scanC_kernel,
        cudaFuncAttributeMaxDynamicSharedMemorySize, SCM_FLOATS * 4);
    cudaFuncSetAttribute(proj_gemm,
        cudaFuncAttributeMaxDynamicSharedMemorySize, GSMB);
    cudaFuncSetAttribute(out_gemm,
        cudaFuncAttributeMaxDynamicSharedMemorySize, GSMB);

    roundw_kernel<<<1280, 256>>>(
        (const float4*)W_r, (const float4*)W_k, (const float4*)W_v,
        (const float4*)W_w, (const float4*)W_o);

    mix_kernel<<<1024, 256>>>(
        (const float4*)x, (const float4*)tm_r, (const float4*)tm_k,
        (const float4*)tm_v, (const float4*)tm_w);

    proj_gemm<<<dim3(Nz / 128, Mz / 128, 4), 256, GSMB>>>();

    scanA_kernel<<<dim3(NC - 1, NBH), 128, SA_FLOATS * 4>>>();
    scanB_kernel<<<NBH, 256>>>();
    scanC_kernel<<<dim3(NC, NBH), 128, SCM_FLOATS * 4>>>(u, ln_w, ln_b);

    out_gemm<<<dim3(Nz / 128, Mz / 128), 256, GSMB>>>(out);
}

// round 16
// speedup vs baseline: 1.6366x; 1.0048x over previous
#include <cuda_runtime.h>
#include <cuda_fp16.h>
#include <cstdint>

#define Bz 4
#define Tz 1024
#define Dz 1024
#define Hz 16
#define DHz 64
#define Mz (Bz*Tz)        // 4096
#define Kz Dz
#define Nz Dz
#define MD (Mz*Dz)        // 4,194,304
#define NBH (Bz*Hz)       // 64
#define CL 64             // chunk length
#define NC (Tz/CL)        // 16 chunks

// fp32 scan operands: 0=r, 1=k, 2=v, 3=e (written by proj GEMM epilogue)
__device__ float g_buf[4][MD];
// fp16 GEMM operands (k-word-permuted)
__device__ __half g_hA[4][MD];            // mix outputs
__device__ __half g_hW[5 * Dz * Dz];      // weights
__device__ __half g_hO[MD];               // gnorm output
__device__ float g_state[NBH * NC * DHz * DHz];
__device__ float g_wprod[NBH * NC * DHz];

__device__ __forceinline__ float to_tf32(float x)
{
    uint32_t d;
    asm("cvt.rna.tf32.f32 %0, %1;" : "=r"(d) : "f"(x));
    return __uint_as_float(d);
}
__device__ __forceinline__ uint32_t f2h2(float a, float b)
{
    __half2 h = __floats2half2_rn(a, b);
    return *reinterpret_cast<uint32_t*>(&h);
}
__device__ __forceinline__ uint32_t smem_to_u32(const void* p) {
    uint32_t a;
    asm("{ .reg .u64 t; cvta.to.shared.u64 t, %1; cvt.u32.u64 %0, t; }"
        : "=r"(a) : "l"(p));
    return a;
}
__device__ __forceinline__ void cp16(uint32_t dst, const void* src) {
    asm volatile("cp.async.cg.shared.global [%0], [%1], 16;"
                 :: "r"(dst), "l"(src));
}
__device__ __forceinline__ void cp_commit() {
    asm volatile("cp.async.commit_group;" ::: "memory");
}
__device__ __forceinline__ void mma_f16(float c[4], const uint32_t a[4],
                                        const uint32_t b[2])
{
    asm volatile(
        "mma.sync.aligned.m16n8k16.row.col.f32.f16.f16.f32 "
        "{%0,%1,%2,%3}, {%4,%5,%6,%7}, {%8,%9}, {%0,%1,%2,%3};"
        : "+f"(c[0]), "+f"(c[1]), "+f"(c[2]), "+f"(c[3])
        : "r"(a[0]), "r"(a[1]), "r"(a[2]), "r"(a[3]),
          "r"(b[0]), "r"(b[1]));
}
__device__ __forceinline__ void mma_tf32(float c[4], const uint32_t a[4],
                                         const uint32_t b[2])
{
    asm volatile(
        "mma.sync.aligned.m16n8k8.row.col.f32.tf32.tf32.f32 "
        "{%0,%1,%2,%3}, {%4,%5,%6,%7}, {%8,%9}, {%0,%1,%2,%3};"
        : "+f"(c[0]), "+f"(c[1]), "+f"(c[2]), "+f"(c[3])
        : "r"(a[0]), "r"(a[1]), "r"(a[2]), "r"(a[3]),
          "r"(b[0]), "r"(b[1]));
}

// pack 16 floats -> 8 half2 words, permuted [0,4,1,5] [2,6,3,7]
__device__ __forceinline__ void pack_perm16(const float* f, uint4& o0, uint4& o1)
{
    uint32_t w[8];
    #pragma unroll
    for (int i = 0; i < 8; i++) w[i] = f2h2(f[2 * i], f[2 * i + 1]);
    o0 = make_uint4(w[0], w[4], w[1], w[5]);
    o1 = make_uint4(w[2], w[6], w[3], w[7]);
}

// ---------------------------------------------------------------------------
// weights -> fp16, word-permuted. one thread per 16-half group.
// ---------------------------------------------------------------------------
__global__ void __launch_bounds__(256) roundw_kernel(
    const float4* __restrict__ a, const float4* __restrict__ b,
    const float4* __restrict__ c, const float4* __restrict__ d,
    const float4* __restrict__ e)
{
    int idx = blockIdx.x * 256 + threadIdx.x;      // 0..327679
    int which = idx >> 16;
    int off = idx & 65535;
    const float4* src = which == 0 ? a : which == 1 ? b : which == 2 ? c
                       : which == 3 ? d : e;
    float f[16];
    #pragma unroll
    for (int i = 0; i < 4; i++)
        *(float4*)&f[i * 4] = src[4 * off + i];
    uint4 o0, o1;
    pack_perm16(f, o0, o1);
    uint4* dst = reinterpret_cast<uint4*>(g_hW) + (size_t)which * 131072;
    dst[2 * off] = o0;
    dst[2 * off + 1] = o1;
}

// ---------------------------------------------------------------------------
// token-shift mix -> fp16 word-permuted. one thread per 16-half group.
// ---------------------------------------------------------------------------
__global__ void __launch_bounds__(256) mix_kernel(
    const float4* __restrict__ x,
    const float4* __restrict__ tmr, const float4* __restrict__ tmk,
    const float4* __restrict__ tmv, const float4* __restrict__ tmw)
{
    int idx = blockIdx.x * 256 + threadIdx.x;   // MD/16 = 262144
    int m  = idx >> 6;
    int gg = idx & 63;
    int t  = m & (Tz - 1);

    float xc[16], xp[16];
    #pragma unroll
    for (int i = 0; i < 4; i++)
        *(float4*)&xc[i * 4] = x[(m << 8) + gg * 4 + i];
    if (t != 0) {
        #pragma unroll
        for (int i = 0; i < 4; i++)
            *(float4*)&xp[i * 4] = x[((m - 1) << 8) + gg * 4 + i];
    } else {
        #pragma unroll
        for (int i = 0; i < 16; i++) xp[i] = 0.f;
    }

    #define DO_MIX(TMV, DSTI)                                               \
    {                                                                       \
        float tm[16], mx[16];                                               \
        _Pragma("unroll")                                                   \
        for (int i = 0; i < 4; i++)                                         \
            *(float4*)&tm[i * 4] = TMV[gg * 4 + i];                         \
        _Pragma("unroll")                                                   \
        for (int i = 0; i < 16; i++)                                        \
            mx[i] = tm[i] * xc[i] + (1.f - tm[i]) * xp[i];                  \
        uint4 o0, o1;                                                       \
        pack_perm16(mx, o0, o1);                                            \
        uint4* dst = reinterpret_cast<uint4*>(g_hA[DSTI]);                  \
        dst[2 * idx] = o0;                                                  \
        dst[2 * idx + 1] = o1;                                              \
    }
    DO_MIX(tmr, 0)
    DO_MIX(tmk, 1)
    DO_MIX(tmv, 2)
    DO_MIX(tmw, 3)
    #undef DO_MIX
}

// ---------------------------------------------------------------------------
// fp16 mma.sync GEMM on word-permuted operands (unchanged)
// ---------------------------------------------------------------------------
#define TB 4096                               // 32-bit words per tile buffer
#define GSMB (3 * 2 * TB * 4)                 // 98304 bytes

__device__ __forceinline__ void gemm_body(
    const __half* __restrict__ A,
    const __half* __restrict__ W,
    float* __restrict__ C, int epi)
{
    extern __shared__ __align__(16) float sm[];
    float* As = sm;
    float* Bs = sm + 3 * TB;
    uint32_t a32 = smem_to_u32(As);
    uint32_t b32 = smem_to_u32(Bs);

    int tid  = threadIdx.x;
    int lane = tid & 31;
    int wid  = tid >> 5;
    int bm = blockIdx.y * 128;
    int bn = blockIdx.x * 128;

    int wm = (wid >> 2) * 64;
    int wn = (wid & 3) * 32;
    int frow = lane >> 2;
    int fk   = lane & 3;

    float acc[4][4][4];
    #pragma unroll
    for (int i = 0; i < 4; i++)
        #pragma unroll
        for (int j = 0; j < 4; j++)
            #pragma unroll
            for (int r = 0; r < 4; r++) acc[i][j][r] = 0.f;

    #define GSTAGE(CC, BUF)                                                  \
    {                                                                        \
        const char* ap = (const char*)(A + (size_t)bm * Kz + (CC) * 64);     \
        const char* bp = (const char*)(W + (size_t)bn * Kz + (CC) * 64);     \
        _Pragma("unroll")                                                    \
        for (int i = 0; i < 4; i++) {                                        \
            int lin = i * 256 + tid;                                         \
            int r = lin >> 3;                                                \
            int g = lin & 7;                                                 \
            int slot = (g + 2 * (r & 3)) & 7;                                \
            cp16(a32 + (BUF) * (TB * 4) + r * 128 + slot * 16,               \
                 ap + (size_t)r * (Kz * 2) + g * 16);                        \
            cp16(b32 + (BUF) * (TB * 4) + r * 128 + slot * 16,               \
                 bp + (size_t)r * (Kz * 2) + g * 16);                        \
        }                                                                    \
    }

    GSTAGE(0, 0) cp_commit();
    GSTAGE(1, 1) cp_commit();

    const int NIT = Kz >> 6;         // 16
    int buf = 0;
    for (int c = 0; c < NIT; c++) {
        asm volatile("cp.async.wait_group 1;" ::: "memory");
        __syncthreads();
        if (c + 2 < NIT) {
            int nb = (c + 2) % 3;
            if (nb == 0)      { GSTAGE(c + 2, 0) }
            else if (nb == 1) { GSTAGE(c + 2, 1) }
            else              { GSTAGE(c + 2, 2) }
        }
        cp_commit();

        const float* a_s = As + buf * TB;
        const float* b_s = Bs + buf * TB;
        #pragma unroll
        for (int ks = 0; ks < 4; ks++) {
            uint32_t afr[4][4], bfr[4][2];
            int slot = (2 * ks + (fk >> 1) + 2 * (frow & 3)) & 7;
            int fo = slot * 4 + (fk & 1) * 2;
            #pragma unroll
            for (int mt = 0; mt < 4; mt++) {
                int rr = wm + mt * 16 + frow;
                float2 u = *(const float2*)&a_s[rr * 32 + fo];
                float2 v = *(const float2*)&a_s[(rr + 8) * 32 + fo];
                afr[mt][0] = __float_as_uint(u.x);
                afr[mt][1] = __float_as_uint(v.x);
                afr[mt][2] = __float_as_uint(u.y);
                afr[mt][3] = __float_as_uint(v.y);
            }
            #pragma unroll
            for (int nt = 0; nt < 4; nt++) {
                int rn = wn + nt * 8 + frow;
                float2 w2 = *(const float2*)&b_s[rn * 32 + fo];
                bfr[nt][0] = __float_as_uint(w2.x);
                bfr[nt][1] = __float_as_uint(w2.y);
            }
            #pragma unroll
            for (int mt = 0; mt < 4; mt++)
                #pragma unroll
                for (int nt = 0; nt < 4; nt++)
                    mma_f16(acc[mt][nt], afr[mt], bfr[nt]);
        }
        buf = (buf + 1) == 3 ? 0 : buf + 1;
    }
    #undef GSTAGE

    #pragma unroll
    for (int mt = 0; mt < 4; mt++) {
        int row = bm + wm + mt * 16 + frow;
        #pragma unroll
        for (int nt = 0; nt < 4; nt++) {
            int col = bn + wn + nt * 8 + fk * 2;
            float vv[4];
            #pragma unroll
            for (int r = 0; r < 4; r++) {
                float v = acc[mt][nt][r];
                if (epi == 1)      v = 1.f / (1.f + __expf(-v));
                else if (epi == 2) v = 0.999900004999833f / (1.f + __expf(-v));
                vv[r] = v;
            }
            *(float2*)&C[(size_t)row * Nz + col]       = make_float2(vv[0], vv[1]);
            *(float2*)&C[(size_t)(row + 8) * Nz + col] = make_float2(vv[2], vv[3]);
        }
    }
}

__global__ void __launch_bounds__(256, 2) proj_gemm()
{
    int which = blockIdx.z;
    int epi = (which == 0) ? 1 : (which == 3) ? 2 : 0;
    gemm_body(g_hA[which], g_hW + (size_t)which * (Dz * Dz),
              g_buf[which], epi);
}

__global__ void __launch_bounds__(256, 2) out_gemm(float* __restrict__ out)
{
    gemm_body(g_hO, g_hW + (size_t)4 * (Dz * Dz), out, 0);
}

// ---------------------------------------------------------------------------
// Pass A (tensor-core, latency-optimized): S_local = K'^T @ V, 256 threads.
// Phase 1: all 256 threads preload k,e (float4).
// Phase 2: threads 0-127 = suffix products, 2 per channel (upper t[32,63]
//          direct + P_hi; lower t[0,31] unscaled);
//          threads 128-255 = v transpose, 2 per column (32 loads, unroll 8).
// Phase 3: lower threads scale by P_hi; wprod = P_lo*P_hi.
// Phase 4: warps 0-3 do 64x64x64 tf32 MMA -> g_state.
// smem: k_s 4096, e_s 4096, Ap 4352, Bp 4352, phi 64 -> 16960 floats
// ---------------------------------------------------------------------------
#define SA_FLOATS 16960

__global__ void __launch_bounds__(256) scanA_kernel()
{
    extern __shared__ __align__(16) float sm[];
    float* k_s = sm;             // [64t][64i]
    float* e_s = sm + 4096;
    float* Ap  = sm + 8192;      // [64i][68]
    float* Bp  = sm + 12544;     // [64j][68]
    float* phi = sm + 16896;     // [64]

    int tid = threadIdx.x;
    int lane = tid & 31;
    int wid  = tid >> 5;
    int c  = blockIdx.x;
    int bh = blockIdx.y;
    int b = bh >> 4, h = bh & 15;

    int base0 = (b * Tz + c * CL) * Dz + h * 64;
    int slot  = (bh * NC + c) * DHz;

    #pragma unroll
    for (int it = 0; it < 4; it++) {
        int f  = it * 256 + tid;
        int t  = f >> 4;
        int i4 = (f & 15) << 2;
        int ga = base0 + t * Dz + i4;
        int sa = t * 64 + i4;
        *(float4*)&k_s[sa] = *(const float4*)&g_buf[1][ga];
        *(float4*)&e_s[sa] = *(const float4*)&g_buf[3][ga];
    }
    __syncthreads();

    if (tid < 128) {
        int i = tid & 63;
        if (tid >= 64) {
            // upper half: t = 63..32, final values
            float sp = 1.f;
            #pragma unroll 8
            for (int t = CL - 1; t >= 32; t--) {
                Ap[i * 68 + t] = to_tf32(k_s[t * 64 + i] * sp);
                sp *= e_s[t * 64 + i];
            }
            phi[i] = sp;
        } else {
            // lower half: t = 31..0, unscaled (missing P_hi factor)
            float sp = 1.f;
            #pragma unroll 8
            for (int t = 31; t >= 0; t--) {
                Ap[i * 68 + t] = k_s[t * 64 + i] * sp;
                sp *= e_s[t * 64 + i];
            }
            Bp[i * 68 + 67] = sp;   // stash P_lo in unused pad slot
        }
    } else {
        // v transpose: 2 threads per column j, 32 t each
        int idx = tid - 128;
        int j  = idx & 63;
        int th = (idx >> 6) * 32;
        const float* __restrict__ gv = g_buf[2];
        #pragma unroll 8
        for (int tt = 0; tt < 32; tt++)
            Bp[j * 68 + th + tt] = to_tf32(gv[base0 + (th + tt) * Dz + j]);
    }
    __syncthreads();

    if (tid < 64) {
        int i = tid;
        float ph = phi[i];
        float plo = Bp[i * 68 + 67];
        g_wprod[slot + i] = plo * ph;
        #pragma unroll 8
        for (int t = 0; t < 32; t++)
            Ap[i * 68 + t] = to_tf32(Ap[i * 68 + t] * ph);
    }
    __syncthreads();

    if (wid < 4) {
        int wm = wid * 16;
        int frow = lane >> 2;
        int fk   = lane & 3;

        float acc[8][4];
        #pragma unroll
        for (int n = 0; n < 8; n++)
            #pragma unroll
            for (int r = 0; r < 4; r++) acc[n][r] = 0.f;

        #pragma unroll
        for (int ko = 0; ko < 64; ko += 8) {
            uint32_t a[4];
            const float* p = &Ap[(wm + frow) * 68 + ko + fk];
            a[0] = __float_as_uint(p[0]);
            a[1] = __float_as_uint(p[8 * 68]);
            a[2] = __float_as_uint(p[4]);
            a[3] = __float_as_uint(p[8 * 68 + 4]);
            #pragma unroll
            for (int nt = 0; nt < 8; nt++) {
                const float* q = &Bp[(nt * 8 + frow) * 68 + ko + fk];
                uint32_t bb[2];
                bb[0] = __float_as_uint(q[0]);
                bb[1] = __float_as_uint(q[4]);
                mma_tf32(acc[nt], a, bb);
            }
        }

        #pragma unroll
        for (int nt = 0; nt < 8; nt++) {
            int col = nt * 8 + fk * 2;
            *(float2*)&g_state[(size_t)(slot + wm + frow) * DHz + col] =
                make_float2(acc[nt][0], acc[nt][1]);
            *(float2*)&g_state[(size_t)(slot + wm + frow + 8) * DHz + col] =
                make_float2(acc[nt][2], acc[nt][3]);
        }
    }
}

// ---------------------------------------------------------------------------
// Pass B: sequential prefix over chunks. grid NBH, 256 threads.
// ---------------------------------------------------------------------------
__global__ void __launch_bounds__(256) scanB_kernel()
{
    __shared__ float s_w[64];
    int tid = threadIdx.x;
    int j   = tid & 63;
    int q   = tid >> 6;
    int bh = blockIdx.x;

    float R[16];
    #pragma unroll
    for (int i = 0; i < 16; i++) R[i] = 0.f;

    for (int c = 0; c < NC; c++) {
        int slot = (bh * NC + c) * DHz;
        if (c < NC - 1) {
            if (tid < 64) s_w[tid] = g_wprod[slot + tid];
            __syncthreads();
            #pragma unroll 8
            for (int ii = 0; ii < 16; ii++) {
                int i = q * 16 + ii;
                size_t a = (size_t)(slot + i) * DHz + j;
                float local = g_state[a];
                g_state[a] = R[ii];
                R[ii] = s_w[i] * R[ii] + local;
            }
            __syncthreads();
        } else {
            #pragma unroll 8
            for (int ii = 0; ii < 16; ii++)
                g_state[(size_t)(slot + q * 16 + ii) * DHz + j] = R[ii];
        }
    }
}

// ---------------------------------------------------------------------------
// Pass C (FUSED): scan outputs + bonus + groupnorm + r-mult + fp16 permute.
// grid (NC, NBH), 128 threads. Barrier-free combine. (unchanged)
// ---------------------------------------------------------------------------
#define SCM_FLOATS 24704

__device__ __forceinline__ int perm_half(int j)
{
    int w  = j >> 1;
    int g  = w >> 3;
    int ww = w & 7;
    int pw = (ww < 4) ? 2 * ww : 2 * (ww - 4) + 1;
    return ((g * 8 + pw) << 1) | (j & 1);
}

__global__ void __launch_bounds__(128) scanC_kernel(
    const float* __restrict__ u,
    const float* __restrict__ ln_w, const float* __restrict__ ln_b)
{
    extern __shared__ __align__(16) float sm[];
    float* k_s  = sm;
    float* e_s  = sm + 4096;
    float* v_s  = sm + 8192;
    float* r_s  = sm + 12288;
    float* op   = sm + 16384;
    float* lnw_s = sm + 24576;
    float* lnb_s = sm + 24640;

    int tid  = threadIdx.x;
    int lane = tid & 31;
    int wid  = tid >> 5;
    int j    = tid & 63;
    int half = tid >> 6;
    int c  = blockIdx.x;
    int bh = blockIdx.y;
    int b = bh >> 4, h = bh & 15;

    int base0 = (b * Tz + c * CL) * Dz + h * 64;

    #pragma unroll
    for (int it = 0; it < 8; it++) {
        int f  = it * 128 + tid;
        int t  = f >> 4;
        int i4 = (f & 15) << 2;
        int ga = base0 + t * Dz + i4;
        int sa = t * 64 + i4;
        *(float4*)&k_s[sa] = *(const float4*)&g_buf[1][ga];
        *(float4*)&e_s[sa] = *(const float4*)&g_buf[3][ga];
        *(float4*)&v_s[sa] = *(const float4*)&g_buf[2][ga];
        *(float4*)&r_s[sa] = *(const float4*)&g_buf[0][ga];
    }
    if (tid < 64) { lnw_s[tid] = ln_w[tid]; lnb_s[tid] = ln_b[tid]; }

    float s[32];
    {
        int slot = (bh * NC + c) * DHz;
        #pragma unroll 8
        for (int ii = 0; ii < 32; ii++)
            s[ii] = g_state[(size_t)(slot + half * 32 + ii) * DHz + j];
    }
    __syncthreads();

    float* myop = op + half * 4096;
    for (int t = 0; t < CL; t++) {
        float vj = v_s[t * 64 + j];
        const float4* rp = (const float4*)&r_s[t * 64 + half * 32];
        const float4* kp = (const float4*)&k_s[t * 64 + half * 32];
        const float4* ep = (const float4*)&e_s[t * 64 + half * 32];
        float o0 = 0.f, o1 = 0.f, o2 = 0.f, o3 = 0.f;
        #pragma unroll
        for (int q = 0; q < 8; q++) {
            float4 rv = rp[q], kv = kp[q], ev = ep[q];
            o0 += rv.x * s[q * 4 + 0]; s[q * 4 + 0] = ev.x * s[q * 4 + 0] + kv.x * vj;
            o1 += rv.y * s[q * 4 + 1]; s[q * 4 + 1] = ev.y * s[q * 4 + 1] + kv.y * vj;
            o2 += rv.z * s[q * 4 + 2]; s[q * 4 + 2] = ev.z * s[q * 4 + 2] + kv.z * vj;
            o3 += rv.w * s[q * 4 + 3]; s[q * 4 + 3] = ev.w * s[q * 4 + 3] + kv.w * vj;
        }
        myop[t * 64 + j] = ((o0 + o1) + (o2 + o3));
    }
    __syncthreads();

    float u0 = u[h * 64 + lane];
    float u1 = u[h * 64 + 32 + lane];
    float lw0 = lnw_s[lane],      lb0 = lnb_s[lane];
    float lw1 = lnw_s[lane + 32], lb1 = lnb_s[lane + 32];
    int pj0 = perm_half(lane);
    int pj1 = perm_half(lane + 32);

    #pragma unroll 4
    for (int it = 0; it < 16; it++) {
        int t = it * 4 + wid;
        int tb = t * 64;
        float r0 = r_s[tb + lane], r1 = r_s[tb + 32 + lane];
        float v0 = v_s[tb + lane], v1 = v_s[tb + 32 + lane];

        float term = r0 * __expf(u0 + k_s[tb + lane])
                   + r1 * __expf(u1 + k_s[tb + 32 + lane]);
        #pragma unroll
        for (int off = 16; off > 0; off >>= 1)
            term += __shfl_xor_sync(0xffffffffu, term, off);

        float o0 = op[tb + lane]      + op[4096 + tb + lane]      + term * v0;
        float o1 = op[tb + 32 + lane] + op[4096 + tb + 32 + lane] + term * v1;

        float ssum = o0 + o1;
        float ssq  = o0 * o0 + o1 * o1;
        #pragma unroll
        for (int off = 16; off > 0; off >>= 1) {
            ssum += __shfl_xor_sync(0xffffffffu, ssum, off);
            ssq  += __shfl_xor_sync(0xffffffffu, ssq,  off);
        }
        float mean = ssum * (1.f / 64.f);
        float var  = ssq * (1.f / 64.f) - mean * mean;
        float rsd  = rsqrtf(var + 1e-5f);

        float n0 = ((o0 - mean) * rsd * lw0 + lb0) * r0;
        float n1 = ((o1 - mean) * rsd * lw1 + lb1) * r1;
        g_hO[base0 + t * Dz + pj0] = __float2half_rn(n0);
        g_hO[base0 + t * Dz + pj1] = __float2half_rn(n1);
    }
}

// ---------------------------------------------------------------------------
extern "C" void kernel_launch(void* const* d_in, const int* in_sizes, int n_in,
                              void* d_out, int out_size)
{
    const float* x    = (const float*)d_in[0];
    const float* W_r  = (const float*)d_in[1];
    const float* W_k  = (const float*)d_in[2];
    const float* W_v  = (const float*)d_in[3];
    const float* W_w  = (const float*)d_in[4];
    const float* W_o  = (const float*)d_in[5];
    const float* u    = (const float*)d_in[6];
    const float* tm_r = (const float*)d_in[7];
    const float* tm_k = (const float*)d_in[8];
    const float* tm_v = (const float*)d_in[9];
    const float* tm_w = (const float*)d_in[10];
    const float* ln_w = (const float*)d_in[11];
    const float* ln_b = (const float*)d_in[12];
    float* out = (float*)d_out;

    cudaFuncSetAttribute(scanA_kernel,
        cudaFuncAttributeMaxDynamicSharedMemorySize, SA_FLOATS * 4);
    cudaFuncSetAttribute(scanC_kernel,
        cudaFuncAttributeMaxDynamicSharedMemorySize, SCM_FLOATS * 4);
    cudaFuncSetAttribute(proj_gemm,
        cudaFuncAttributeMaxDynamicSharedMemorySize, GSMB);
    cudaFuncSetAttribute(out_gemm,
        cudaFuncAttributeMaxDynamicSharedMemorySize, GSMB);

    roundw_kernel<<<1280, 256>>>(
        (const float4*)W_r, (const float4*)W_k, (const float4*)W_v,
        (const float4*)W_w, (const float4*)W_o);

    mix_kernel<<<1024, 256>>>(
        (const float4*)x, (const float4*)tm_r, (const float4*)tm_k,
        (const float4*)tm_v, (const float4*)tm_w);

    proj_gemm<<<dim3(Nz / 128, Mz / 128, 4), 256, GSMB>>>();

    scanA_kernel<<<dim3(NC - 1, NBH), 256, SA_FLOATS * 4>>>();
    scanB_kernel<<<NBH, 256>>>();
    scanC_kernel<<<dim3(NC, NBH), 128, SCM_FLOATS * 4>>>(u, ln_w, ln_b);

    out_gemm<<<dim3(Nz / 128, Mz / 128), 256, GSMB>>>(out);
}

// round 17
// speedup vs baseline: 1.6506x; 1.0086x over previous
#include <cuda_runtime.h>
#include <cuda_fp16.h>
#include <cstdint>

#define Bz 4
#define Tz 1024
#define Dz 1024
#define Hz 16
#define DHz 64
#define Mz (Bz*Tz)        // 4096
#define Kz Dz
#define Nz Dz
#define MD (Mz*Dz)        // 4,194,304
#define NBH (Bz*Hz)       // 64
#define CL 64             // chunk length
#define NC (Tz/CL)        // 16 chunks

// fp32 scan operands: 0=r, 1=k, 2=v, 3=e (written by proj GEMM epilogue)
__device__ float g_buf[4][MD];
// fp16 GEMM operands (k-word-permuted)
__device__ __half g_hA[4][MD];            // mix outputs
__device__ __half g_hW[5 * Dz * Dz];      // weights
__device__ __half g_hO[MD];               // gnorm output
__device__ float g_state[NBH * NC * DHz * DHz];
__device__ float g_wprod[NBH * NC * DHz];

__device__ __forceinline__ float to_tf32(float x)
{
    uint32_t d;
    asm("cvt.rna.tf32.f32 %0, %1;" : "=r"(d) : "f"(x));
    return __uint_as_float(d);
}
__device__ __forceinline__ uint32_t f2h2(float a, float b)
{
    __half2 h = __floats2half2_rn(a, b);
    return *reinterpret_cast<uint32_t*>(&h);
}
__device__ __forceinline__ uint32_t smem_to_u32(const void* p) {
    uint32_t a;
    asm("{ .reg .u64 t; cvta.to.shared.u64 t, %1; cvt.u32.u64 %0, t; }"
        : "=r"(a) : "l"(p));
    return a;
}
__device__ __forceinline__ void cp16(uint32_t dst, const void* src) {
    asm volatile("cp.async.cg.shared.global [%0], [%1], 16;"
                 :: "r"(dst), "l"(src));
}
__device__ __forceinline__ void cp_commit() {
    asm volatile("cp.async.commit_group;" ::: "memory");
}
__device__ __forceinline__ void mma_f16(float c[4], const uint32_t a[4],
                                        const uint32_t b[2])
{
    asm volatile(
        "mma.sync.aligned.m16n8k16.row.col.f32.f16.f16.f32 "
        "{%0,%1,%2,%3}, {%4,%5,%6,%7}, {%8,%9}, {%0,%1,%2,%3};"
        : "+f"(c[0]), "+f"(c[1]), "+f"(c[2]), "+f"(c[3])
        : "r"(a[0]), "r"(a[1]), "r"(a[2]), "r"(a[3]),
          "r"(b[0]), "r"(b[1]));
}
__device__ __forceinline__ void mma_tf32(float c[4], const uint32_t a[4],
                                         const uint32_t b[2])
{
    asm volatile(
        "mma.sync.aligned.m16n8k8.row.col.f32.tf32.tf32.f32 "
        "{%0,%1,%2,%3}, {%4,%5,%6,%7}, {%8,%9}, {%0,%1,%2,%3};"
        : "+f"(c[0]), "+f"(c[1]), "+f"(c[2]), "+f"(c[3])
        : "r"(a[0]), "r"(a[1]), "r"(a[2]), "r"(a[3]),
          "r"(b[0]), "r"(b[1]));
}

// pack 16 floats -> 8 half2 words, permuted [0,4,1,5] [2,6,3,7]
__device__ __forceinline__ void pack_perm16(const float* f, uint4& o0, uint4& o1)
{
    uint32_t w[8];
    #pragma unroll
    for (int i = 0; i < 8; i++) w[i] = f2h2(f[2 * i], f[2 * i + 1]);
    o0 = make_uint4(w[0], w[4], w[1], w[5]);
    o1 = make_uint4(w[2], w[6], w[3], w[7]);
}

// ---------------------------------------------------------------------------
// weights -> fp16, word-permuted. one thread per 16-half group.
// ---------------------------------------------------------------------------
__global__ void __launch_bounds__(256) roundw_kernel(
    const float4* __restrict__ a, const float4* __restrict__ b,
    const float4* __restrict__ c, const float4* __restrict__ d,
    const float4* __restrict__ e)
{
    int idx = blockIdx.x * 256 + threadIdx.x;      // 0..327679
    int which = idx >> 16;
    int off = idx & 65535;
    const float4* src = which == 0 ? a : which == 1 ? b : which == 2 ? c
                       : which == 3 ? d : e;
    float f[16];
    #pragma unroll
    for (int i = 0; i < 4; i++)
        *(float4*)&f[i * 4] = src[4 * off + i];
    uint4 o0, o1;
    pack_perm16(f, o0, o1);
    uint4* dst = reinterpret_cast<uint4*>(g_hW) + (size_t)which * 131072;
    dst[2 * off] = o0;
    dst[2 * off + 1] = o1;
}

// ---------------------------------------------------------------------------
// token-shift mix -> fp16 word-permuted. one thread per 16-half group.
// ---------------------------------------------------------------------------
__global__ void __launch_bounds__(256) mix_kernel(
    const float4* __restrict__ x,
    const float4* __restrict__ tmr, const float4* __restrict__ tmk,
    const float4* __restrict__ tmv, const float4* __restrict__ tmw)
{
    int idx = blockIdx.x * 256 + threadIdx.x;   // MD/16 = 262144
    int m  = idx >> 6;
    int gg = idx & 63;
    int t  = m & (Tz - 1);

    float xc[16], xp[16];
    #pragma unroll
    for (int i = 0; i < 4; i++)
        *(float4*)&xc[i * 4] = x[(m << 8) + gg * 4 + i];
    if (t != 0) {
        #pragma unroll
        for (int i = 0; i < 4; i++)
            *(float4*)&xp[i * 4] = x[((m - 1) << 8) + gg * 4 + i];
    } else {
        #pragma unroll
        for (int i = 0; i < 16; i++) xp[i] = 0.f;
    }

    #define DO_MIX(TMV, DSTI)                                               \
    {                                                                       \
        float tm[16], mx[16];                                               \
        _Pragma("unroll")                                                   \
        for (int i = 0; i < 4; i++)                                         \
            *(float4*)&tm[i * 4] = TMV[gg * 4 + i];                         \
        _Pragma("unroll")                                                   \
        for (int i = 0; i < 16; i++)                                        \
            mx[i] = tm[i] * xc[i] + (1.f - tm[i]) * xp[i];                  \
        uint4 o0, o1;                                                       \
        pack_perm16(mx, o0, o1);                                            \
        uint4* dst = reinterpret_cast<uint4*>(g_hA[DSTI]);                  \
        dst[2 * idx] = o0;                                                  \
        dst[2 * idx + 1] = o1;                                              \
    }
    DO_MIX(tmr, 0)
    DO_MIX(tmk, 1)
    DO_MIX(tmv, 2)
    DO_MIX(tmw, 3)
    #undef DO_MIX
}

// ---------------------------------------------------------------------------
// fp16 mma.sync GEMM on word-permuted operands (unchanged)
// ---------------------------------------------------------------------------
#define TB 4096                               // 32-bit words per tile buffer
#define GSMB (3 * 2 * TB * 4)                 // 98304 bytes

__device__ __forceinline__ void gemm_body(
    const __half* __restrict__ A,
    const __half* __restrict__ W,
    float* __restrict__ C, int epi)
{
    extern __shared__ __align__(16) float sm[];
    float* As = sm;
    float* Bs = sm + 3 * TB;
    uint32_t a32 = smem_to_u32(As);
    uint32_t b32 = smem_to_u32(Bs);

    int tid  = threadIdx.x;
    int lane = tid & 31;
    int wid  = tid >> 5;
    int bm = blockIdx.y * 128;
    int bn = blockIdx.x * 128;

    int wm = (wid >> 2) * 64;
    int wn = (wid & 3) * 32;
    int frow = lane >> 2;
    int fk   = lane & 3;

    float acc[4][4][4];
    #pragma unroll
    for (int i = 0; i < 4; i++)
        #pragma unroll
        for (int j = 0; j < 4; j++)
            #pragma unroll
            for (int r = 0; r < 4; r++) acc[i][j][r] = 0.f;

    #define GSTAGE(CC, BUF)                                                  \
    {                                                                        \
        const char* ap = (const char*)(A + (size_t)bm * Kz + (CC) * 64);     \
        const char* bp = (const char*)(W + (size_t)bn * Kz + (CC) * 64);     \
        _Pragma("unroll")                                                    \
        for (int i = 0; i < 4; i++) {                                        \
            int lin = i * 256 + tid;                                         \
            int r = lin >> 3;                                                \
            int g = lin & 7;                                                 \
            int slot = (g + 2 * (r & 3)) & 7;                                \
            cp16(a32 + (BUF) * (TB * 4) + r * 128 + slot * 16,               \
                 ap + (size_t)r * (Kz * 2) + g * 16);                        \
            cp16(b32 + (BUF) * (TB * 4) + r * 128 + slot * 16,               \
                 bp + (size_t)r * (Kz * 2) + g * 16);                        \
        }                                                                    \
    }

    GSTAGE(0, 0) cp_commit();
    GSTAGE(1, 1) cp_commit();

    const int NIT = Kz >> 6;         // 16
    int buf = 0;
    for (int c = 0; c < NIT; c++) {
        asm volatile("cp.async.wait_group 1;" ::: "memory");
        __syncthreads();
        if (c + 2 < NIT) {
            int nb = (c + 2) % 3;
            if (nb == 0)      { GSTAGE(c + 2, 0) }
            else if (nb == 1) { GSTAGE(c + 2, 1) }
            else              { GSTAGE(c + 2, 2) }
        }
        cp_commit();

        const float* a_s = As + buf * TB;
        const float* b_s = Bs + buf * TB;
        #pragma unroll
        for (int ks = 0; ks < 4; ks++) {
            uint32_t afr[4][4], bfr[4][2];
            int slot = (2 * ks + (fk >> 1) + 2 * (frow & 3)) & 7;
            int fo = slot * 4 + (fk & 1) * 2;
            #pragma unroll
            for (int mt = 0; mt < 4; mt++) {
                int rr = wm + mt * 16 + frow;
                float2 u = *(const float2*)&a_s[rr * 32 + fo];
                float2 v = *(const float2*)&a_s[(rr + 8) * 32 + fo];
                afr[mt][0] = __float_as_uint(u.x);
                afr[mt][1] = __float_as_uint(v.x);
                afr[mt][2] = __float_as_uint(u.y);
                afr[mt][3] = __float_as_uint(v.y);
            }
            #pragma unroll
            for (int nt = 0; nt < 4; nt++) {
                int rn = wn + nt * 8 + frow;
                float2 w2 = *(const float2*)&b_s[rn * 32 + fo];
                bfr[nt][0] = __float_as_uint(w2.x);
                bfr[nt][1] = __float_as_uint(w2.y);
            }
            #pragma unroll
            for (int mt = 0; mt < 4; mt++)
                #pragma unroll
                for (int nt = 0; nt < 4; nt++)
                    mma_f16(acc[mt][nt], afr[mt], bfr[nt]);
        }
        buf = (buf + 1) == 3 ? 0 : buf + 1;
    }
    #undef GSTAGE

    #pragma unroll
    for (int mt = 0; mt < 4; mt++) {
        int row = bm + wm + mt * 16 + frow;
        #pragma unroll
        for (int nt = 0; nt < 4; nt++) {
            int col = bn + wn + nt * 8 + fk * 2;
            float vv[4];
            #pragma unroll
            for (int r = 0; r < 4; r++) {
                float v = acc[mt][nt][r];
                if (epi == 1)      v = 1.f / (1.f + __expf(-v));
                else if (epi == 2) v = 0.999900004999833f / (1.f + __expf(-v));
                vv[r] = v;
            }
            *(float2*)&C[(size_t)row * Nz + col]       = make_float2(vv[0], vv[1]);
            *(float2*)&C[(size_t)(row + 8) * Nz + col] = make_float2(vv[2], vv[3]);
        }
    }
}

__global__ void __launch_bounds__(256, 2) proj_gemm()
{
    int which = blockIdx.z;
    int epi = (which == 0) ? 1 : (which == 3) ? 2 : 0;
    gemm_body(g_hA[which], g_hW + (size_t)which * (Dz * Dz),
              g_buf[which], epi);
}

__global__ void __launch_bounds__(256, 2) out_gemm(float* __restrict__ out)
{
    gemm_body(g_hO, g_hW + (size_t)4 * (Dz * Dz), out, 0);
}

// ---------------------------------------------------------------------------
// Pass A (tensor-core): unchanged from round 16
// ---------------------------------------------------------------------------
#define SA_FLOATS 16960

__global__ void __launch_bounds__(256) scanA_kernel()
{
    extern __shared__ __align__(16) float sm[];
    float* k_s = sm;
    float* e_s = sm + 4096;
    float* Ap  = sm + 8192;
    float* Bp  = sm + 12544;
    float* phi = sm + 16896;

    int tid = threadIdx.x;
    int lane = tid & 31;
    int wid  = tid >> 5;
    int c  = blockIdx.x;
    int bh = blockIdx.y;
    int b = bh >> 4, h = bh & 15;

    int base0 = (b * Tz + c * CL) * Dz + h * 64;
    int slot  = (bh * NC + c) * DHz;

    #pragma unroll
    for (int it = 0; it < 4; it++) {
        int f  = it * 256 + tid;
        int t  = f >> 4;
        int i4 = (f & 15) << 2;
        int ga = base0 + t * Dz + i4;
        int sa = t * 64 + i4;
        *(float4*)&k_s[sa] = *(const float4*)&g_buf[1][ga];
        *(float4*)&e_s[sa] = *(const float4*)&g_buf[3][ga];
    }
    __syncthreads();

    if (tid < 128) {
        int i = tid & 63;
        if (tid >= 64) {
            float sp = 1.f;
            #pragma unroll 8
            for (int t = CL - 1; t >= 32; t--) {
                Ap[i * 68 + t] = to_tf32(k_s[t * 64 + i] * sp);
                sp *= e_s[t * 64 + i];
            }
            phi[i] = sp;
        } else {
            float sp = 1.f;
            #pragma unroll 8
            for (int t = 31; t >= 0; t--) {
                Ap[i * 68 + t] = k_s[t * 64 + i] * sp;
                sp *= e_s[t * 64 + i];
            }
            Bp[i * 68 + 67] = sp;
        }
    } else {
        int idx = tid - 128;
        int j  = idx & 63;
        int th = (idx >> 6) * 32;
        const float* __restrict__ gv = g_buf[2];
        #pragma unroll 8
        for (int tt = 0; tt < 32; tt++)
            Bp[j * 68 + th + tt] = to_tf32(gv[base0 + (th + tt) * Dz + j]);
    }
    __syncthreads();

    if (tid < 64) {
        int i = tid;
        float ph = phi[i];
        float plo = Bp[i * 68 + 67];
        g_wprod[slot + i] = plo * ph;
        #pragma unroll 8
        for (int t = 0; t < 32; t++)
            Ap[i * 68 + t] = to_tf32(Ap[i * 68 + t] * ph);
    }
    __syncthreads();

    if (wid < 4) {
        int wm = wid * 16;
        int frow = lane >> 2;
        int fk   = lane & 3;

        float acc[8][4];
        #pragma unroll
        for (int n = 0; n < 8; n++)
            #pragma unroll
            for (int r = 0; r < 4; r++) acc[n][r] = 0.f;

        #pragma unroll
        for (int ko = 0; ko < 64; ko += 8) {
            uint32_t a[4];
            const float* p = &Ap[(wm + frow) * 68 + ko + fk];
            a[0] = __float_as_uint(p[0]);
            a[1] = __float_as_uint(p[8 * 68]);
            a[2] = __float_as_uint(p[4]);
            a[3] = __float_as_uint(p[8 * 68 + 4]);
            #pragma unroll
            for (int nt = 0; nt < 8; nt++) {
                const float* q = &Bp[(nt * 8 + frow) * 68 + ko + fk];
                uint32_t bb[2];
                bb[0] = __float_as_uint(q[0]);
                bb[1] = __float_as_uint(q[4]);
                mma_tf32(acc[nt], a, bb);
            }
        }

        #pragma unroll
        for (int nt = 0; nt < 8; nt++) {
            int col = nt * 8 + fk * 2;
            *(float2*)&g_state[(size_t)(slot + wm + frow) * DHz + col] =
                make_float2(acc[nt][0], acc[nt][1]);
            *(float2*)&g_state[(size_t)(slot + wm + frow + 8) * DHz + col] =
                make_float2(acc[nt][2], acc[nt][3]);
        }
    }
}

// ---------------------------------------------------------------------------
// Pass B: sequential prefix over chunks. grid NBH, 256 threads. (unchanged)
// ---------------------------------------------------------------------------
__global__ void __launch_bounds__(256) scanB_kernel()
{
    __shared__ float s_w[64];
    int tid = threadIdx.x;
    int j   = tid & 63;
    int q   = tid >> 6;
    int bh = blockIdx.x;

    float R[16];
    #pragma unroll
    for (int i = 0; i < 16; i++) R[i] = 0.f;

    for (int c = 0; c < NC; c++) {
        int slot = (bh * NC + c) * DHz;
        if (c < NC - 1) {
            if (tid < 64) s_w[tid] = g_wprod[slot + tid];
            __syncthreads();
            #pragma unroll 8
            for (int ii = 0; ii < 16; ii++) {
                int i = q * 16 + ii;
                size_t a = (size_t)(slot + i) * DHz + j;
                float local = g_state[a];
                g_state[a] = R[ii];
                R[ii] = s_w[i] * R[ii] + local;
            }
            __syncthreads();
        } else {
            #pragma unroll 8
            for (int ii = 0; ii < 16; ii++)
                g_state[(size_t)(slot + q * 16 + ii) * DHz + j] = R[ii];
        }
    }
}

// ---------------------------------------------------------------------------
// Pass C (TENSOR): sub-chunked masked matmul. grid (NC, NBH), 128 threads.
// Per sub (16 steps): o = Rp@S + strictLT(Rp@Kp^T)@V + bonus.v
//                     S <- diag(qf).S + Ksuf^T@V
// smem (floats): Rp 0[4352], Kp 4352, KsT 8704, Vt 13056, St 17408,
//   SCm 21760[16x20], op 22080[4096], qf 26176[4x64], lnw 26432, lnb 26496
// ---------------------------------------------------------------------------
#define SCM_FLOATS 26560

__device__ __forceinline__ int perm_half(int j)
{
    int w  = j >> 1;
    int g  = w >> 3;
    int ww = w & 7;
    int pw = (ww < 4) ? 2 * ww : 2 * (ww - 4) + 1;
    return ((g * 8 + pw) << 1) | (j & 1);
}

__global__ void __launch_bounds__(128) scanC_kernel(
    const float* __restrict__ u,
    const float* __restrict__ ln_w, const float* __restrict__ ln_b)
{
    extern __shared__ __align__(16) float sm[];
    float* Rp  = sm;             // [64t][68i]
    float* Kp  = sm + 4352;      // [64s][68i]
    float* KsT = sm + 8704;      // [64i][68s]
    float* Vt  = sm + 13056;     // [64j][68t]
    float* St  = sm + 17408;     // [64j][68i]
    float* SCm = sm + 21760;     // [16t][20s]
    float* op  = sm + 22080;     // [64t][64j]
    float* qf  = sm + 26176;     // [4][64]
    float* lnw_s = sm + 26432;
    float* lnb_s = sm + 26496;

    int tid  = threadIdx.x;
    int lane = tid & 31;
    int wid  = tid >> 5;
    int frow = lane >> 2;
    int fk   = lane & 3;
    int c  = blockIdx.x;
    int bh = blockIdx.y;
    int b = bh >> 4, h = bh & 15;

    int base0 = (b * Tz + c * CL) * Dz + h * 64;
    int slot  = (bh * NC + c) * DHz;

    // ---- generation phase ----
    if (tid < 64) {
        int i = tid;
        for (int sub = 0; sub < 4; sub++) {
            float kreg[16], ereg[16], rreg[16];
            #pragma unroll
            for (int uu = 0; uu < 16; uu++) {
                int t = sub * 16 + uu;
                kreg[uu] = g_buf[1][base0 + t * Dz + i];
                ereg[uu] = g_buf[3][base0 + t * Dz + i];
                rreg[uu] = g_buf[0][base0 + t * Dz + i];
            }
            float q = 1.f;
            #pragma unroll
            for (int uu = 0; uu < 16; uu++) {
                int t = sub * 16 + uu;
                Rp[t * 68 + i] = to_tf32(rreg[uu] * q);
                q *= ereg[uu];
                float qc = fmaxf(q, 1e-30f);
                Kp[t * 68 + i] = to_tf32(__fdividef(kreg[uu], qc));
            }
            qf[sub * 64 + i] = q;
            float suf = 1.f;
            #pragma unroll
            for (int uu = 15; uu >= 0; uu--) {
                KsT[i * 68 + sub * 16 + uu] = to_tf32(kreg[uu] * suf);
                suf *= ereg[uu];
            }
        }
    } else {
        int j = tid - 64;
        #pragma unroll 8
        for (int t = 0; t < 64; t++)
            Vt[j * 68 + t] = to_tf32(g_buf[2][base0 + t * Dz + j]);
        #pragma unroll 8
        for (int i2 = 0; i2 < 64; i2++)
            St[j * 68 + i2] = to_tf32(g_state[(size_t)(slot + i2) * DHz + j]);
        lnw_s[j] = ln_w[j];
        lnb_s[j] = ln_b[j];
    }

    // acc_S init from g_state (fp32)
    int wm = wid * 16;
    float accS[8][4];
    #pragma unroll
    for (int nt = 0; nt < 8; nt++) {
        float2 x0 = *(const float2*)
            &g_state[(size_t)(slot + wm + frow) * DHz + nt * 8 + fk * 2];
        float2 x1 = *(const float2*)
            &g_state[(size_t)(slot + wm + frow + 8) * DHz + nt * 8 + fk * 2];
        accS[nt][0] = x0.x; accS[nt][1] = x0.y;
        accS[nt][2] = x1.x; accS[nt][3] = x1.y;
    }
    __syncthreads();

    // ---- sub-chunk loop ----
    for (int sub = 0; sub < 4; sub++) {
        int tb = sub * 16;
        float acco[2][4];
        #pragma unroll
        for (int n = 0; n < 2; n++)
            #pragma unroll
            for (int r = 0; r < 4; r++) acco[n][r] = 0.f;
        float accsc[4] = {0.f, 0.f, 0.f, 0.f};

        // (a) o += Rp_sub @ S ; (b) scores (warps 0,1)
        #pragma unroll
        for (int ko = 0; ko < 64; ko += 8) {
            uint32_t a[4];
            a[0] = __float_as_uint(Rp[(tb + frow) * 68 + ko + fk]);
            a[1] = __float_as_uint(Rp[(tb + frow + 8) * 68 + ko + fk]);
            a[2] = __float_as_uint(Rp[(tb + frow) * 68 + ko + fk + 4]);
            a[3] = __float_as_uint(Rp[(tb + frow + 8) * 68 + ko + fk + 4]);
            #pragma unroll
            for (int nt = 0; nt < 2; nt++) {
                int jb = wm + nt * 8;
                uint32_t bb[2];
                bb[0] = __float_as_uint(St[(jb + frow) * 68 + ko + fk]);
                bb[1] = __float_as_uint(St[(jb + frow) * 68 + ko + fk + 4]);
                mma_tf32(acco[nt], a, bb);
            }
            if (wid < 2) {
                uint32_t bb[2];
                bb[0] = __float_as_uint(Kp[(tb + wid * 8 + frow) * 68 + ko + fk]);
                bb[1] = __float_as_uint(Kp[(tb + wid * 8 + frow) * 68 + ko + fk + 4]);
                mma_tf32(accsc, a, bb);
            }
        }
        if (wid < 2) {
            int s0 = wid * 8 + fk * 2;
            SCm[frow * 20 + s0]           = (s0     < frow)     ? to_tf32(accsc[0]) : 0.f;
            SCm[frow * 20 + s0 + 1]       = (s0 + 1 < frow)     ? to_tf32(accsc[1]) : 0.f;
            SCm[(frow + 8) * 20 + s0]     = (s0     < frow + 8) ? to_tf32(accsc[2]) : 0.f;
            SCm[(frow + 8) * 20 + s0 + 1] = (s0 + 1 < frow + 8) ? to_tf32(accsc[3]) : 0.f;
        }
        __syncthreads();

        // (c) o += SCm @ V_sub
        #pragma unroll
        for (int ks = 0; ks < 16; ks += 8) {
            uint32_t a[4];
            a[0] = __float_as_uint(SCm[frow * 20 + ks + fk]);
            a[1] = __float_as_uint(SCm[(frow + 8) * 20 + ks + fk]);
            a[2] = __float_as_uint(SCm[frow * 20 + ks + fk + 4]);
            a[3] = __float_as_uint(SCm[(frow + 8) * 20 + ks + fk + 4]);
            #pragma unroll
            for (int nt = 0; nt < 2; nt++) {
                int jb = wm + nt * 8;
                uint32_t bb[2];
                bb[0] = __float_as_uint(Vt[(jb + frow) * 68 + tb + ks + fk]);
                bb[1] = __float_as_uint(Vt[(jb + frow) * 68 + tb + ks + fk + 4]);
                mma_tf32(acco[nt], a, bb);
            }
        }
        // write o rows
        #pragma unroll
        for (int nt = 0; nt < 2; nt++) {
            int jb = wm + nt * 8 + fk * 2;
            *(float2*)&op[(tb + frow) * 64 + jb] =
                make_float2(acco[nt][0], acco[nt][1]);
            *(float2*)&op[(tb + frow + 8) * 64 + jb] =
                make_float2(acco[nt][2], acco[nt][3]);
        }

        // (d) S <- qf.S + Ksuf^T @ V_sub
        float q0 = qf[sub * 64 + wm + frow];
        float q1 = qf[sub * 64 + wm + frow + 8];
        #pragma unroll
        for (int nt = 0; nt < 8; nt++) {
            accS[nt][0] *= q0; accS[nt][1] *= q0;
            accS[nt][2] *= q1; accS[nt][3] *= q1;
        }
        #pragma unroll
        for (int ks = 0; ks < 16; ks += 8) {
            uint32_t a[4];
            a[0] = __float_as_uint(KsT[(wm + frow) * 68 + tb + ks + fk]);
            a[1] = __float_as_uint(KsT[(wm + frow + 8) * 68 + tb + ks + fk]);
            a[2] = __float_as_uint(KsT[(wm + frow) * 68 + tb + ks + fk + 4]);
            a[3] = __float_as_uint(KsT[(wm + frow + 8) * 68 + tb + ks + fk + 4]);
            #pragma unroll
            for (int nt = 0; nt < 8; nt++) {
                uint32_t bb[2];
                bb[0] = __float_as_uint(Vt[(nt * 8 + frow) * 68 + tb + ks + fk]);
                bb[1] = __float_as_uint(Vt[(nt * 8 + frow) * 68 + tb + ks + fk + 4]);
                mma_tf32(accS[nt], a, bb);
            }
        }
        if (sub < 3) {
            #pragma unroll
            for (int nt = 0; nt < 8; nt++) {
                int j0 = nt * 8 + fk * 2;
                St[j0 * 68 + wm + frow]           = to_tf32(accS[nt][0]);
                St[(j0 + 1) * 68 + wm + frow]     = to_tf32(accS[nt][1]);
                St[j0 * 68 + wm + frow + 8]       = to_tf32(accS[nt][2]);
                St[(j0 + 1) * 68 + wm + frow + 8] = to_tf32(accS[nt][3]);
            }
        }
        __syncthreads();
    }

    // ---- combine: bonus + groupnorm + r-mult + fp16 permuted store ----
    float u0 = u[h * 64 + lane];
    float u1 = u[h * 64 + 32 + lane];
    float lw0 = lnw_s[lane],      lb0 = lnb_s[lane];
    float lw1 = lnw_s[lane + 32], lb1 = lnb_s[lane + 32];
    int pj0 = perm_half(lane);
    int pj1 = perm_half(lane + 32);

    #pragma unroll 4
    for (int it = 0; it < 16; it++) {
        int t = it * 4 + wid;
        int gb = base0 + t * Dz;
        float r0 = g_buf[0][gb + lane], r1 = g_buf[0][gb + 32 + lane];
        float k0 = g_buf[1][gb + lane], k1 = g_buf[1][gb + 32 + lane];
        float v0 = g_buf[2][gb + lane], v1 = g_buf[2][gb + 32 + lane];

        float term = r0 * __expf(u0 + k0) + r1 * __expf(u1 + k1);
        #pragma unroll
        for (int off = 16; off > 0; off >>= 1)
            term += __shfl_xor_sync(0xffffffffu, term, off);

        float o0 = op[t * 64 + lane]      + term * v0;
        float o1 = op[t * 64 + 32 + lane] + term * v1;

        float ssum = o0 + o1;
        float ssq  = o0 * o0 + o1 * o1;
        #pragma unroll
        for (int off = 16; off > 0; off >>= 1) {
            ssum += __shfl_xor_sync(0xffffffffu, ssum, off);
            ssq  += __shfl_xor_sync(0xffffffffu, ssq,  off);
        }
        float mean = ssum * (1.f / 64.f);
        float var  = ssq * (1.f / 64.f) - mean * mean;
        float rsd  = rsqrtf(var + 1e-5f);

        float n0 = ((o0 - mean) * rsd * lw0 + lb0) * r0;
        float n1 = ((o1 - mean) * rsd * lw1 + lb1) * r1;
        g_hO[base0 + t * Dz + pj0] = __float2half_rn(n0);
        g_hO[base0 + t * Dz + pj1] = __float2half_rn(n1);
    }
}

// ---------------------------------------------------------------------------
extern "C" void kernel_launch(void* const* d_in, const int* in_sizes, int n_in,
                              void* d_out, int out_size)
{
    const float* x    = (const float*)d_in[0];
    const float* W_r  = (const float*)d_in[1];
    const float* W_k  = (const float*)d_in[2];
    const float* W_v  = (const float*)d_in[3];
    const float* W_w  = (const float*)d_in[4];
    const float* W_o  = (const float*)d_in[5];
    const float* u    = (const float*)d_in[6];
    const float* tm_r = (const float*)d_in[7];
    const float* tm_k = (const float*)d_in[8];
    const float* tm_v = (const float*)d_in[9];
    const float* tm_w = (const float*)d_in[10];
    const float* ln_w = (const float*)d_in[11];
    const float* ln_b = (const float*)d_in[12];
    float* out = (float*)d_out;

    cudaFuncSetAttribute(scanA_kernel,
        cudaFuncAttributeMaxDynamicSharedMemorySize, SA_FLOATS * 4);
    cudaFuncSetAttribute(scanC_kernel,
        cudaFuncAttributeMaxDynamicSharedMemorySize, SCM_FLOATS * 4);
    cudaFuncSetAttribute(proj_gemm,
        cudaFuncAttributeMaxDynamicSharedMemorySize, GSMB);
    cudaFuncSetAttribute(out_gemm,
        cudaFuncAttributeMaxDynamicSharedMemorySize, GSMB);

    roundw_kernel<<<1280, 256>>>(
        (const float4*)W_r, (const float4*)W_k, (const float4*)W_v,
        (const float4*)W_w, (const float4*)W_o);

    mix_kernel<<<1024, 256>>>(
        (const float4*)x, (const float4*)tm_r, (const float4*)tm_k,
        (const float4*)tm_v, (const float4*)tm_w);

    proj_gemm<<<dim3(Nz / 128, Mz / 128, 4), 256, GSMB>>>();

    scanA_kernel<<<dim3(NC - 1, NBH), 256, SA_FLOATS * 4>>>();
    scanB_kernel<<<NBH, 256>>>();
    scanC_kernel<<<dim3(NC, NBH), 128, SCM_FLOATS * 4>>>(u, ln_w, ln_b);

    out_gemm<<<dim3(Nz / 128, Mz / 128), 256, GSMB>>>(out);
}